// round 2
// baseline (speedup 1.0000x reference)
#include <cuda_runtime.h>
#include <math.h>

// ---------------- problem constants ----------------
static constexpr int NB   = 8;          // batch
static constexpr int NC   = 96;         // channels
static constexpr int NH   = 128;
static constexpr int NWD  = 128;
static constexpr int HW   = NH * NWD;   // 16384
static constexpr int NCH  = NC * HW;    // per-batch elements 1572864
static constexpr int C2   = 2 * NC;     // 192

// ---------------- scratch (device globals; no allocation) ----------------
__device__ float g_qkv_u[(size_t)NB * C2 * HW];   // [b][192][HW]
__device__ float g_qkv_d[(size_t)NB * C2 * HW];
__device__ float g_d2u  [(size_t)NB * NC * HW];   // [b][96][HW]
__device__ float g_u2d  [(size_t)NB * NC * HW];
__device__ float g_part [2 * NB * 256 * 2];
__device__ float g_stats[2 * NB * 2];             // [z][b][{mean,std}]
__device__ float g_spart[(size_t)NB * 32 * 32 * 32];
__device__ float g_ac   [NB * 32 * 32];

// ---------------- K1: per-batch partial sums (mean/var) ----------------
__global__ void k_reduce1(const float* __restrict__ xu, const float* __restrict__ xd,
                          float* __restrict__ part)
{
    int chunk = blockIdx.x, b = blockIdx.y, z = blockIdx.z;
    const float* x = (z == 0 ? xu : xd) + (size_t)b * NCH + (size_t)chunk * 6144;
    float s = 0.f, ss = 0.f;
    for (int i = threadIdx.x; i < 6144; i += 256) {
        float v = x[i]; s += v; ss += v * v;
    }
    __shared__ float sh[256], sh2[256];
    sh[threadIdx.x] = s; sh2[threadIdx.x] = ss;
    __syncthreads();
    for (int o = 128; o > 0; o >>= 1) {
        if (threadIdx.x < o) { sh[threadIdx.x] += sh[threadIdx.x + o]; sh2[threadIdx.x] += sh2[threadIdx.x + o]; }
        __syncthreads();
    }
    if (threadIdx.x == 0) {
        int o = ((z * NB + b) * 256 + chunk) * 2;
        part[o] = sh[0]; part[o + 1] = sh2[0];
    }
}

// ---------------- K2: finalize mean/std (double accumulation) ----------------
__global__ void k_reduce2(const float* __restrict__ part, float* __restrict__ stats)
{
    int b = blockIdx.x, z = blockIdx.y, tid = threadIdx.x;
    __shared__ double sh[256], sh2[256];
    int o = ((z * NB + b) * 256 + tid) * 2;
    sh[tid] = (double)part[o]; sh2[tid] = (double)part[o + 1];
    __syncthreads();
    for (int s = 128; s > 0; s >>= 1) {
        if (tid < s) { sh[tid] += sh[tid + s]; sh2[tid] += sh2[tid + s]; }
        __syncthreads();
    }
    if (tid == 0) {
        double mean = sh[0] / (double)NCH;
        double var  = sh2[0] / (double)NCH - mean * mean;
        stats[(z * NB + b) * 2 + 0] = (float)mean;
        stats[(z * NB + b) * 2 + 1] = sqrtf((float)var + 1e-5f);
    }
}

// ---------------- K3: fused normalize + 1x1 conv GEMM ----------------
// out[b,o,n] = sum_k W[o,k] * ((x[b,k,n]-mean)/std*nw[k]+nb[k]) + bias[o]
// tiles: BM=64 (o), BN=128 (n), K=96 full; 256 thr, 4x8 per-thread tile.
__global__ void k_pconv(const float* __restrict__ x, const float* __restrict__ Wm,
                        const float* __restrict__ bias, const float* __restrict__ nw,
                        const float* __restrict__ nb, const float* __restrict__ stats,
                        float* __restrict__ out)
{
    extern __shared__ float sm[];
    float* sA = sm;              // [96][64]
    float* sB = sm + 96 * 64;    // [96][128]
    int b = blockIdx.z, mBase = blockIdx.y * 64, nBase = blockIdx.x * 128;
    int tid = threadIdx.x;
    float mean = stats[b * 2], inv = 1.0f / stats[b * 2 + 1];

    for (int idx = tid; idx < 96 * 64; idx += 256) {
        int k = idx >> 6, m = idx & 63;
        sA[idx] = Wm[(mBase + m) * 96 + k];
    }
    for (int idx = tid; idx < 96 * 128; idx += 256) {
        int k = idx >> 7, n = idx & 127;
        float v = x[((size_t)b * NC + k) * HW + nBase + n];
        sB[idx] = (v - mean) * inv * nw[k] + nb[k];
    }
    __syncthreads();

    int tm = (tid >> 4) << 2;   // 0..60
    int tn = (tid & 15) << 3;   // 0..120
    float acc[4][8];
#pragma unroll
    for (int i = 0; i < 4; i++)
#pragma unroll
        for (int j = 0; j < 8; j++) acc[i][j] = 0.f;

#pragma unroll 8
    for (int k = 0; k < 96; k++) {
        float4 a  = *(const float4*)&sA[k * 64 + tm];
        float4 b0 = *(const float4*)&sB[k * 128 + tn];
        float4 b1 = *(const float4*)&sB[k * 128 + tn + 4];
        float av[4] = {a.x, a.y, a.z, a.w};
        float bv[8] = {b0.x, b0.y, b0.z, b0.w, b1.x, b1.y, b1.z, b1.w};
#pragma unroll
        for (int i = 0; i < 4; i++)
#pragma unroll
            for (int j = 0; j < 8; j++) acc[i][j] = fmaf(av[i], bv[j], acc[i][j]);
    }

#pragma unroll
    for (int i = 0; i < 4; i++) {
        int o = mBase + tm + i;
        float bs = bias[o];
        float* dst = &out[((size_t)b * C2 + o) * HW + nBase + tn];
        float4 r0 = make_float4(acc[i][0] + bs, acc[i][1] + bs, acc[i][2] + bs, acc[i][3] + bs);
        float4 r1 = make_float4(acc[i][4] + bs, acc[i][5] + bs, acc[i][6] + bs, acc[i][7] + bs);
        *(float4*)dst = r0;
        *(float4*)(dst + 4) = r1;
    }
}

// ---------------- K4: height-axis attention, one CTA per (b,w) ----------------
// q=qkv_u ch[0..31], k=qkv_d ch[0..31], vd=qkv_d ch[96..127], vu=qkv_u ch[96..127]
__global__ void k_attn_h(const float* __restrict__ qu, const float* __restrict__ qd,
                         const float* __restrict__ sch,
                         float* __restrict__ d2u, float* __restrict__ u2d)
{
    extern __shared__ float sm[];
    float* S  = sm;                    // [128][129]
    float* T0 = sm + 128 * 129;        // [32][129]
    float* T1 = T0 + 32 * 129;
    int w = blockIdx.x, b = blockIdx.y, tid = threadIdx.x;
    const size_t bb = (size_t)b * C2 * HW;
    const size_t ob = (size_t)b * NC * HW;

    for (int idx = tid; idx < 32 * 128; idx += 256) {
        int c = idx >> 7, i = idx & 127;
        T0[c * 129 + i] = qu[bb + (size_t)c * HW + i * NWD + w];
        T1[c * 129 + i] = qd[bb + (size_t)c * HW + i * NWD + w];
    }
    __syncthreads();
    float sc = sch[0];

    // S[i][j] = sc * sum_c q[c,i] k[c,j]  (4x4 register tiles)
    for (int t = 0; t < 4; t++) {
        int jg = ((tid & 7) | (t << 3)) * 4;   // j base
        int ig = (tid >> 3) * 4;               // i base
        float acc[4][4];
#pragma unroll
        for (int a = 0; a < 4; a++)
#pragma unroll
            for (int c = 0; c < 4; c++) acc[a][c] = 0.f;
#pragma unroll
        for (int c = 0; c < 32; c++) {
            float qv[4], kv[4];
#pragma unroll
            for (int u = 0; u < 4; u++) { qv[u] = T0[c * 129 + ig + u]; kv[u] = T1[c * 129 + jg + u]; }
#pragma unroll
            for (int ii = 0; ii < 4; ii++)
#pragma unroll
                for (int jj = 0; jj < 4; jj++) acc[ii][jj] = fmaf(qv[ii], kv[jj], acc[ii][jj]);
        }
#pragma unroll
        for (int ii = 0; ii < 4; ii++)
#pragma unroll
            for (int jj = 0; jj < 4; jj++) S[(ig + ii) * 129 + jg + jj] = acc[ii][jj] * sc;
    }
    __syncthreads();

    // row softmax in place
    if (tid < 128) {
        float* row = S + tid * 129;
        float m = -1e30f;
        for (int j = 0; j < 128; j++) m = fmaxf(m, row[j]);
        float s = 0.f;
        for (int j = 0; j < 128; j++) { float e = __expf(row[j] - m); row[j] = e; s += e; }
        float invs = 1.0f / s;
        for (int j = 0; j < 128; j++) row[j] *= invs;
    }
    __syncthreads();

    // load vd -> T0, vu -> T1
    for (int idx = tid; idx < 32 * 128; idx += 256) {
        int c = idx >> 7, i = idx & 127;
        T0[c * 129 + i] = qd[bb + (size_t)(96 + c) * HW + i * NWD + w];
        T1[c * 129 + i] = qu[bb + (size_t)(96 + c) * HW + i * NWD + w];
    }
    __syncthreads();

    // d2u[c,i] = sum_j A[i,j] vd[c,j]
    {
        int cg = (tid & 7) * 4, ig = (tid >> 3) * 4;
        float acc[4][4];
#pragma unroll
        for (int a = 0; a < 4; a++)
#pragma unroll
            for (int c = 0; c < 4; c++) acc[a][c] = 0.f;
        for (int j = 0; j < 128; j++) {
            float av[4], vv[4];
#pragma unroll
            for (int u = 0; u < 4; u++) { av[u] = S[(ig + u) * 129 + j]; vv[u] = T0[(cg + u) * 129 + j]; }
#pragma unroll
            for (int ii = 0; ii < 4; ii++)
#pragma unroll
                for (int cc = 0; cc < 4; cc++) acc[ii][cc] = fmaf(av[ii], vv[cc], acc[ii][cc]);
        }
#pragma unroll
        for (int ii = 0; ii < 4; ii++)
#pragma unroll
            for (int cc = 0; cc < 4; cc++)
                d2u[ob + (size_t)(cg + cc) * HW + (ig + ii) * NWD + w] = acc[ii][cc];
    }
    // u2d[c,j] = sum_i A[i,j] vu[c,i]   (no shared writes since last sync)
    {
        int cg = (tid & 7) * 4, jg = (tid >> 3) * 4;
        float acc[4][4];
#pragma unroll
        for (int a = 0; a < 4; a++)
#pragma unroll
            for (int c = 0; c < 4; c++) acc[a][c] = 0.f;
        for (int i = 0; i < 128; i++) {
            float av[4], vv[4];
#pragma unroll
            for (int u = 0; u < 4; u++) { av[u] = S[i * 129 + jg + u]; vv[u] = T1[(cg + u) * 129 + i]; }
#pragma unroll
            for (int jj = 0; jj < 4; jj++)
#pragma unroll
                for (int cc = 0; cc < 4; cc++) acc[jj][cc] = fmaf(av[jj], vv[cc], acc[jj][cc]);
        }
#pragma unroll
        for (int jj = 0; jj < 4; jj++)
#pragma unroll
            for (int cc = 0; cc < 4; cc++)
                u2d[ob + (size_t)(cg + cc) * HW + (jg + jj) * NWD + w] = acc[jj][cc];
    }
}

// ---------------- K5: width-axis attention, one CTA per (b,h) ----------------
// q=qkv_u ch[32..63], k=qkv_d ch[32..63], vd=qkv_d ch[128..159], vu=qkv_u ch[128..159]
// Needs BOTH softmax(S,-1) (rows) and softmax(S,-2) (cols).
__global__ void k_attn_w(const float* __restrict__ qu, const float* __restrict__ qd,
                         const float* __restrict__ scw,
                         float* __restrict__ d2u, float* __restrict__ u2d)
{
    extern __shared__ float sm[];
    float* S  = sm;
    float* T0 = sm + 128 * 129;
    float* T1 = T0 + 32 * 129;
    __shared__ float rf[128], gc[128];
    int h = blockIdx.x, b = blockIdx.y, tid = threadIdx.x;
    const size_t bb = (size_t)b * C2 * HW;
    const size_t ob = (size_t)b * NC * HW;
    const size_t ro = (size_t)h * NWD;

    for (int idx = tid; idx < 32 * 128; idx += 256) {
        int c = idx >> 7, j = idx & 127;
        T0[c * 129 + j] = qu[bb + (size_t)(32 + c) * HW + ro + j];
        T1[c * 129 + j] = qd[bb + (size_t)(32 + c) * HW + ro + j];
    }
    __syncthreads();
    float sc = scw[0];

    for (int t = 0; t < 4; t++) {
        int jg = ((tid & 7) | (t << 3)) * 4;
        int ig = (tid >> 3) * 4;
        float acc[4][4];
#pragma unroll
        for (int a = 0; a < 4; a++)
#pragma unroll
            for (int c = 0; c < 4; c++) acc[a][c] = 0.f;
#pragma unroll
        for (int c = 0; c < 32; c++) {
            float qv[4], kv[4];
#pragma unroll
            for (int u = 0; u < 4; u++) { qv[u] = T0[c * 129 + ig + u]; kv[u] = T1[c * 129 + jg + u]; }
#pragma unroll
            for (int ii = 0; ii < 4; ii++)
#pragma unroll
                for (int jj = 0; jj < 4; jj++) acc[ii][jj] = fmaf(qv[ii], kv[jj], acc[ii][jj]);
        }
#pragma unroll
        for (int ii = 0; ii < 4; ii++)
#pragma unroll
            for (int jj = 0; jj < 4; jj++) S[(ig + ii) * 129 + jg + jj] = acc[ii][jj] * sc;
    }
    __syncthreads();

    // column stats from raw S: gc[j] = exp(-cmax[j]) / csum[j]
    if (tid < 128) {
        int j = tid;
        float m = -1e30f;
        for (int i = 0; i < 128; i++) m = fmaxf(m, S[i * 129 + j]);
        float s = 0.f;
        for (int i = 0; i < 128; i++) s += __expf(S[i * 129 + j] - m);
        gc[j] = __expf(-m) / s;
    }
    __syncthreads();

    // row softmax in place (A1); keep rf[i] = rsum*exp(rmax) for A2 recovery
    if (tid < 128) {
        float* row = S + tid * 129;
        float m = -1e30f;
        for (int j = 0; j < 128; j++) m = fmaxf(m, row[j]);
        float s = 0.f;
        for (int j = 0; j < 128; j++) { float e = __expf(row[j] - m); row[j] = e; s += e; }
        float invs = 1.0f / s;
        for (int j = 0; j < 128; j++) row[j] *= invs;
        rf[tid] = s * __expf(m);
    }
    __syncthreads();

    for (int idx = tid; idx < 32 * 128; idx += 256) {
        int c = idx >> 7, j = idx & 127;
        T0[c * 129 + j] = qd[bb + (size_t)(128 + c) * HW + ro + j];
        T1[c * 129 + j] = qu[bb + (size_t)(128 + c) * HW + ro + j];
    }
    __syncthreads();

    // d2u_w[c,i] = sum_j A1[i,j] vd[c,j]
    {
        int cg = (tid & 7) * 4, ig = (tid >> 3) * 4;
        float acc[4][4];
#pragma unroll
        for (int a = 0; a < 4; a++)
#pragma unroll
            for (int c = 0; c < 4; c++) acc[a][c] = 0.f;
        for (int j = 0; j < 128; j++) {
            float av[4], vv[4];
#pragma unroll
            for (int u = 0; u < 4; u++) { av[u] = S[(ig + u) * 129 + j]; vv[u] = T0[(cg + u) * 129 + j]; }
#pragma unroll
            for (int ii = 0; ii < 4; ii++)
#pragma unroll
                for (int cc = 0; cc < 4; cc++) acc[ii][cc] = fmaf(av[ii], vv[cc], acc[ii][cc]);
        }
#pragma unroll
        for (int ii = 0; ii < 4; ii++)
#pragma unroll
            for (int cc = 0; cc < 4; cc++)
                d2u[ob + (size_t)(32 + cg + cc) * HW + ro + (ig + ii)] = acc[ii][cc];
    }
    __syncthreads();

    // convert in place: A2[i,j] = A1[i,j] * rf[i] * gc[j]
    for (int idx = tid; idx < 128 * 128; idx += 256) {
        int i = idx >> 7, j = idx & 127;
        S[i * 129 + j] *= rf[i] * gc[j];
    }
    __syncthreads();

    // u2d_w[c,j] = sum_i A2[i,j] vu[c,i]
    {
        int cg = (tid & 7) * 4, jg = (tid >> 3) * 4;
        float acc[4][4];
#pragma unroll
        for (int a = 0; a < 4; a++)
#pragma unroll
            for (int c = 0; c < 4; c++) acc[a][c] = 0.f;
        for (int i = 0; i < 128; i++) {
            float av[4], vv[4];
#pragma unroll
            for (int u = 0; u < 4; u++) { av[u] = S[i * 129 + jg + u]; vv[u] = T1[(cg + u) * 129 + i]; }
#pragma unroll
            for (int jj = 0; jj < 4; jj++)
#pragma unroll
                for (int cc = 0; cc < 4; cc++) acc[jj][cc] = fmaf(av[jj], vv[cc], acc[jj][cc]);
        }
#pragma unroll
        for (int jj = 0; jj < 4; jj++)
#pragma unroll
            for (int cc = 0; cc < 4; cc++)
                u2d[ob + (size_t)(32 + cg + cc) * HW + ro + (jg + jj)] = acc[jj][cc];
    }
}

// ---------------- K6a: channel scores split-K partials ----------------
// S_c[c,d] partial over an n-chunk of 512; q=qkv_u ch[64..95], k=qkv_d ch[64..95]
__global__ void k_cpart(const float* __restrict__ qu, const float* __restrict__ qd,
                        float* __restrict__ spart)
{
    __shared__ float qs[32 * 129], ks[32 * 129];
    int chunk = blockIdx.x, b = blockIdx.y, tid = threadIdx.x;
    const size_t bb = (size_t)b * C2 * HW;
    int c0 = (tid >> 5) * 4, d = tid & 31;
    float acc[4] = {0.f, 0.f, 0.f, 0.f};
    for (int sub = 0; sub < 4; sub++) {
        int n0 = chunk * 512 + sub * 128;
        for (int idx = tid; idx < 32 * 128; idx += 256) {
            int c = idx >> 7, t = idx & 127;
            qs[c * 129 + t] = qu[bb + (size_t)(64 + c) * HW + n0 + t];
            ks[c * 129 + t] = qd[bb + (size_t)(64 + c) * HW + n0 + t];
        }
        __syncthreads();
        for (int t = 0; t < 128; t++) {
            float kv = ks[d * 129 + t];
#pragma unroll
            for (int cc = 0; cc < 4; cc++) acc[cc] = fmaf(qs[(c0 + cc) * 129 + t], kv, acc[cc]);
        }
        __syncthreads();
    }
#pragma unroll
    for (int cc = 0; cc < 4; cc++)
        spart[(((size_t)b * 32 + chunk) * 32 + c0 + cc) * 32 + d] = acc[cc];
}

// ---------------- K6b: reduce partials + row softmax -> A_c ----------------
__global__ void k_csoft(const float* __restrict__ spart, const float* __restrict__ scc,
                        float* __restrict__ ac)
{
    int b = blockIdx.x, d = threadIdx.x, c = threadIdx.y;
    float s = 0.f;
    for (int ch = 0; ch < 32; ch++)
        s += spart[(((size_t)b * 32 + ch) * 32 + c) * 32 + d];
    s *= scc[0];
    float m = s;
#pragma unroll
    for (int o = 16; o > 0; o >>= 1) m = fmaxf(m, __shfl_xor_sync(0xffffffffu, m, o));
    float e = __expf(s - m);
    float sum = e;
#pragma unroll
    for (int o = 16; o > 0; o >>= 1) sum += __shfl_xor_sync(0xffffffffu, sum, o);
    ac[((size_t)b * 32 + c) * 32 + d] = e / sum;
}

// ---------------- K6c: apply A_c to vd/vu ----------------
// vd = qkv_d ch[160..191], vu = qkv_u ch[160..191]; same A for both (ref quirk).
__global__ void k_capply(const float* __restrict__ qu, const float* __restrict__ qd,
                         const float* __restrict__ ac,
                         float* __restrict__ d2u, float* __restrict__ u2d)
{
    __shared__ float A[1024];
    int b = blockIdx.y, tid = threadIdx.x;
    int n = blockIdx.x * 256 + tid;
    for (int i = tid; i < 1024; i += 256) A[i] = ac[(size_t)b * 1024 + i];
    __syncthreads();
    const size_t bb = (size_t)b * C2 * HW;
    const size_t ob = (size_t)b * NC * HW;
    float vd[32], vu[32];
#pragma unroll
    for (int d = 0; d < 32; d++) {
        vd[d] = qd[bb + (size_t)(160 + d) * HW + n];
        vu[d] = qu[bb + (size_t)(160 + d) * HW + n];
    }
#pragma unroll
    for (int c = 0; c < 32; c++) {
        float ad = 0.f, au = 0.f;
#pragma unroll
        for (int d = 0; d < 32; d++) {
            float a = A[c * 32 + d];
            ad = fmaf(a, vd[d], ad);
            au = fmaf(a, vu[d], au);
        }
        d2u[ob + (size_t)(64 + c) * HW + n] = ad;
        u2d[ob + (size_t)(64 + c) * HW + n] = au;
    }
}

// ---------------- K7: epilogue ----------------
__global__ void k_epi(const float* __restrict__ d2u, const float* __restrict__ u2d,
                      const float* __restrict__ xu, const float* __restrict__ xd,
                      const float* __restrict__ stats,
                      const float* __restrict__ m1wu, const float* __restrict__ m1bu,
                      const float* __restrict__ m2wu, const float* __restrict__ m2bu,
                      const float* __restrict__ m1wd, const float* __restrict__ m1bd,
                      const float* __restrict__ m2wd, const float* __restrict__ m2bd,
                      float* __restrict__ out)
{
    size_t e = ((size_t)blockIdx.x * 256 + threadIdx.x) * 4;
    int b = (int)(e / (size_t)NCH);
    int c = (int)((e - (size_t)b * NCH) >> 14);
    float mu = stats[b * 2], su = stats[b * 2 + 1];
    float md = stats[2 * NB + b * 2], sd = stats[2 * NB + b * 2 + 1];
    float ru = su * m1wu[c] + m1bu[c];
    float bu = mu * m2wu[c] + m2bu[c];
    float rd = sd * m1wd[c] + m1bd[c];
    float bd = md * m2wd[c] + m2bd[c];
    float4 a = *(const float4*)&d2u[e];
    float4 u = *(const float4*)&u2d[e];
    float4 p = *(const float4*)&xu[e];
    float4 q = *(const float4*)&xd[e];
    float4 r;
    r.x = a.x * ru + bu + p.x + u.x * rd + bd + q.x;
    r.y = a.y * ru + bu + p.y + u.y * rd + bd + q.y;
    r.z = a.z * ru + bu + p.z + u.z * rd + bd + q.z;
    r.w = a.w * ru + bu + p.w + u.w * rd + bd + q.w;
    *(float4*)&out[e] = r;
}

// ---------------- launch ----------------
extern "C" void kernel_launch(void* const* d_in, const int* in_sizes, int n_in,
                              void* d_out, int out_size)
{
    const float* x_u  = (const float*)d_in[0];
    const float* x_d  = (const float*)d_in[1];
    const float* nw_u = (const float*)d_in[2];
    const float* nb_u = (const float*)d_in[3];
    const float* m1w_u = (const float*)d_in[4];
    const float* m1b_u = (const float*)d_in[5];
    const float* m2w_u = (const float*)d_in[6];
    const float* m2b_u = (const float*)d_in[7];
    const float* nw_d = (const float*)d_in[8];
    const float* nb_d = (const float*)d_in[9];
    const float* m1w_d = (const float*)d_in[10];
    const float* m1b_d = (const float*)d_in[11];
    const float* m2w_d = (const float*)d_in[12];
    const float* m2b_d = (const float*)d_in[13];
    const float* Wqkv_u = (const float*)d_in[14];
    const float* bqkv_u = (const float*)d_in[15];
    const float* Wqkv_d = (const float*)d_in[16];
    const float* bqkv_d = (const float*)d_in[17];
    const float* scale_h = (const float*)d_in[18];
    const float* scale_w = (const float*)d_in[19];
    const float* scale_c = (const float*)d_in[20];
    float* out = (float*)d_out;

    static bool s_init = false;
    static float *p_qu, *p_qd, *p_du, *p_ud, *p_part, *p_stats, *p_sp, *p_ac;
    if (!s_init) {
        cudaGetSymbolAddress((void**)&p_qu, g_qkv_u);
        cudaGetSymbolAddress((void**)&p_qd, g_qkv_d);
        cudaGetSymbolAddress((void**)&p_du, g_d2u);
        cudaGetSymbolAddress((void**)&p_ud, g_u2d);
        cudaGetSymbolAddress((void**)&p_part, g_part);
        cudaGetSymbolAddress((void**)&p_stats, g_stats);
        cudaGetSymbolAddress((void**)&p_sp, g_spart);
        cudaGetSymbolAddress((void**)&p_ac, g_ac);
        cudaFuncSetAttribute(k_pconv,  cudaFuncAttributeMaxDynamicSharedMemorySize, (96 * 64 + 96 * 128) * 4);
        cudaFuncSetAttribute(k_attn_h, cudaFuncAttributeMaxDynamicSharedMemorySize, (128 * 129 + 2 * 32 * 129) * 4);
        cudaFuncSetAttribute(k_attn_w, cudaFuncAttributeMaxDynamicSharedMemorySize, (128 * 129 + 2 * 32 * 129) * 4);
        s_init = true;
    }

    // stats
    k_reduce1<<<dim3(256, NB, 2), 256>>>(x_u, x_d, p_part);
    k_reduce2<<<dim3(NB, 2), 256>>>(p_part, p_stats);

    // fused normalize + qkv 1x1 conv
    size_t smemG = (size_t)(96 * 64 + 96 * 128) * 4;
    k_pconv<<<dim3(128, 3, NB), 256, smemG>>>(x_u, Wqkv_u, bqkv_u, nw_u, nb_u, p_stats,          p_qu);
    k_pconv<<<dim3(128, 3, NB), 256, smemG>>>(x_d, Wqkv_d, bqkv_d, nw_d, nb_d, p_stats + 2 * NB, p_qd);

    // attentions
    size_t smemA = (size_t)(128 * 129 + 2 * 32 * 129) * 4;
    k_attn_h<<<dim3(NWD, NB), 256, smemA>>>(p_qu, p_qd, scale_h, p_du, p_ud);
    k_attn_w<<<dim3(NH,  NB), 256, smemA>>>(p_qu, p_qd, scale_w, p_du, p_ud);
    k_cpart<<<dim3(32, NB), 256>>>(p_qu, p_qd, p_sp);
    k_csoft<<<NB, dim3(32, 32)>>>(p_sp, scale_c, p_ac);
    k_capply<<<dim3(HW / 256, NB), 256>>>(p_qu, p_qd, p_ac, p_du, p_ud);

    // epilogue
    k_epi<<<(NB * NCH) / (256 * 4), 256>>>(p_du, p_ud, x_u, x_d, p_stats,
                                           m1w_u, m1b_u, m2w_u, m2b_u,
                                           m1w_d, m1b_d, m2w_d, m2b_d, out);
}

// round 3
// speedup vs baseline: 1.4191x; 1.4191x over previous
#include <cuda_runtime.h>
#include <math.h>
#include <stdint.h>

// ---------------- problem constants ----------------
static constexpr int NB   = 8;          // batch
static constexpr int NC   = 96;         // channels
static constexpr int NH   = 128;
static constexpr int NWD  = 128;
static constexpr int HW   = NH * NWD;   // 16384
static constexpr int NCH  = NC * HW;    // per-batch elements 1572864
static constexpr int C2   = 2 * NC;     // 192

// ---------------- scratch (device globals; no allocation) ----------------
__device__ float g_qkv_u[(size_t)NB * C2 * HW];   // [b][192][HW]
__device__ float g_qkv_d[(size_t)NB * C2 * HW];
__device__ float g_d2u  [(size_t)NB * NC * HW];   // [b][96][HW]
__device__ float g_u2d  [(size_t)NB * NC * HW];
__device__ float g_part [2 * NB * 256 * 2];
__device__ float g_stats[2 * NB * 2];             // [z][b][{mean,std}]
__device__ float g_spart[(size_t)NB * 32 * 32 * 32];
__device__ float g_ac   [NB * 32 * 32];

// ---------------- K1: per-batch partial sums (mean/var) ----------------
__global__ void k_reduce1(const float* __restrict__ xu, const float* __restrict__ xd,
                          float* __restrict__ part)
{
    int chunk = blockIdx.x, b = blockIdx.y, z = blockIdx.z;
    const float* x = (z == 0 ? xu : xd) + (size_t)b * NCH + (size_t)chunk * 6144;
    float s = 0.f, ss = 0.f;
    for (int i = threadIdx.x; i < 6144; i += 256) {
        float v = x[i]; s += v; ss += v * v;
    }
    __shared__ float sh[256], sh2[256];
    sh[threadIdx.x] = s; sh2[threadIdx.x] = ss;
    __syncthreads();
    for (int o = 128; o > 0; o >>= 1) {
        if (threadIdx.x < o) { sh[threadIdx.x] += sh[threadIdx.x + o]; sh2[threadIdx.x] += sh2[threadIdx.x + o]; }
        __syncthreads();
    }
    if (threadIdx.x == 0) {
        int o = ((z * NB + b) * 256 + chunk) * 2;
        part[o] = sh[0]; part[o + 1] = sh2[0];
    }
}

// ---------------- K2: finalize mean/std (double accumulation) ----------------
__global__ void k_reduce2(const float* __restrict__ part, float* __restrict__ stats)
{
    int b = blockIdx.x, z = blockIdx.y, tid = threadIdx.x;
    __shared__ double sh[256], sh2[256];
    int o = ((z * NB + b) * 256 + tid) * 2;
    sh[tid] = (double)part[o]; sh2[tid] = (double)part[o + 1];
    __syncthreads();
    for (int s = 128; s > 0; s >>= 1) {
        if (tid < s) { sh[tid] += sh[tid + s]; sh2[tid] += sh2[tid + s]; }
        __syncthreads();
    }
    if (tid == 0) {
        double mean = sh[0] / (double)NCH;
        double var  = sh2[0] / (double)NCH - mean * mean;
        stats[(z * NB + b) * 2 + 0] = (float)mean;
        stats[(z * NB + b) * 2 + 1] = sqrtf((float)var + 1e-5f);
    }
}

// ---------------- tf32 helpers ----------------
__device__ __forceinline__ float to_tf32(float v) {
    uint32_t u;
    asm("cvt.rna.tf32.f32 %0, %1;" : "=r"(u) : "f"(v));
    return __uint_as_float(u);
}

__device__ __forceinline__ void mma_tf32(float& c0, float& c1, float& c2, float& c3,
                                         uint32_t a0, uint32_t a1, uint32_t a2, uint32_t a3,
                                         uint32_t b0, uint32_t b1)
{
    asm volatile("mma.sync.aligned.m16n8k8.row.col.f32.tf32.tf32.f32 "
                 "{%0,%1,%2,%3}, {%4,%5,%6,%7}, {%8,%9}, {%0,%1,%2,%3};"
                 : "+f"(c0), "+f"(c1), "+f"(c2), "+f"(c3)
                 : "r"(a0), "r"(a1), "r"(a2), "r"(a3), "r"(b0), "r"(b1));
}

// ---------------- K3: fused normalize + 1x1 conv GEMM (tf32 tensor core) ----------------
// out[b,o,n] = sum_k W[o,k] * ((x[b,k,n]-mean)/std*nw[k]+nb[k]) + bias[o]
// CTA tile: BM=64 (o), BN=128 (n), K=96 full. 8 warps in 2(M)x4(N); each warp 32x32.
// Shared layouts are row-major over the fragment row index with pitch 100
// (pitch % 32 == 4 makes the m16n8k8 fragment gathers conflict-free).
static constexpr int PIT = 100;

__global__ void k_pconv_tc(const float* __restrict__ x, const float* __restrict__ Wm,
                           const float* __restrict__ bias, const float* __restrict__ nw,
                           const float* __restrict__ nb, const float* __restrict__ stats,
                           float* __restrict__ out)
{
    extern __shared__ float sm[];
    float* sA = sm;               // [64][PIT]  (m, k)
    float* sB = sm + 64 * PIT;    // [128][PIT] (n, k)
    int b = blockIdx.z, mBase = blockIdx.y * 64, nBase = blockIdx.x * 128;
    int tid = threadIdx.x;
    float mean = stats[b * 2], inv = 1.0f / stats[b * 2 + 1];

    // A: W[mBase+m][k] -> sA[m][k]
    for (int idx = tid; idx < 64 * 96; idx += 256) {
        int m = idx / 96, k = idx - m * 96;
        sA[m * PIT + k] = to_tf32(Wm[(mBase + m) * 96 + k]);
    }
    // B: normalized x -> sB[n][k] (transpose in shared)
    for (int idx = tid; idx < 96 * 128; idx += 256) {
        int k = idx >> 7, n = idx & 127;
        float v = x[((size_t)b * NC + k) * HW + nBase + n];
        sB[n * PIT + k] = to_tf32((v - mean) * inv * nw[k] + nb[k]);
    }
    __syncthreads();

    int warp = tid >> 5, lane = tid & 31;
    int warpM = warp & 1, warpN = warp >> 1;      // 2 x 4
    int g = lane >> 2, tg = lane & 3;             // group row / thread-in-group

    float acc[2][4][4];
#pragma unroll
    for (int mt = 0; mt < 2; mt++)
#pragma unroll
        for (int nt = 0; nt < 4; nt++)
#pragma unroll
            for (int r = 0; r < 4; r++) acc[mt][nt][r] = 0.f;

    const float* pa = sA + (warpM * 32 + g) * PIT + tg;     // a0 base
    const float* pb = sB + (warpN * 32 + g) * PIT + tg;     // b0 base

#pragma unroll
    for (int ks = 0; ks < 12; ks++) {
        int k0 = ks * 8;
        uint32_t a[2][4], bf[4][2];
#pragma unroll
        for (int mt = 0; mt < 2; mt++) {
            const float* p = pa + mt * 16 * PIT + k0;
            a[mt][0] = __float_as_uint(p[0]);
            a[mt][1] = __float_as_uint(p[8 * PIT]);
            a[mt][2] = __float_as_uint(p[4]);
            a[mt][3] = __float_as_uint(p[8 * PIT + 4]);
        }
#pragma unroll
        for (int nt = 0; nt < 4; nt++) {
            const float* p = pb + nt * 8 * PIT + k0;
            bf[nt][0] = __float_as_uint(p[0]);
            bf[nt][1] = __float_as_uint(p[4]);
        }
#pragma unroll
        for (int mt = 0; mt < 2; mt++)
#pragma unroll
            for (int nt = 0; nt < 4; nt++)
                mma_tf32(acc[mt][nt][0], acc[mt][nt][1], acc[mt][nt][2], acc[mt][nt][3],
                         a[mt][0], a[mt][1], a[mt][2], a[mt][3], bf[nt][0], bf[nt][1]);
    }

    // epilogue: c0 -> (row g, col tg*2), c1 -> +1 col, c2/c3 -> row+8
#pragma unroll
    for (int mt = 0; mt < 2; mt++) {
        int o0 = mBase + warpM * 32 + mt * 16 + g;
        float bs0 = bias[o0], bs1 = bias[o0 + 8];
        size_t base0 = ((size_t)b * C2 + o0) * HW + nBase + warpN * 32;
        size_t base1 = base0 + (size_t)8 * HW;
#pragma unroll
        for (int nt = 0; nt < 4; nt++) {
            int nc0 = nt * 8 + tg * 2;
            float2 r0 = make_float2(acc[mt][nt][0] + bs0, acc[mt][nt][1] + bs0);
            float2 r1 = make_float2(acc[mt][nt][2] + bs1, acc[mt][nt][3] + bs1);
            *(float2*)&out[base0 + nc0] = r0;
            *(float2*)&out[base1 + nc0] = r1;
        }
    }
}

// ---------------- K4: height-axis attention, one CTA per (b,w) ----------------
__global__ void k_attn_h(const float* __restrict__ qu, const float* __restrict__ qd,
                         const float* __restrict__ sch,
                         float* __restrict__ d2u, float* __restrict__ u2d)
{
    extern __shared__ float sm[];
    float* S  = sm;                    // [128][129]
    float* T0 = sm + 128 * 129;        // [32][129]
    float* T1 = T0 + 32 * 129;
    int w = blockIdx.x, b = blockIdx.y, tid = threadIdx.x;
    const size_t bb = (size_t)b * C2 * HW;
    const size_t ob = (size_t)b * NC * HW;

    for (int idx = tid; idx < 32 * 128; idx += 256) {
        int c = idx >> 7, i = idx & 127;
        T0[c * 129 + i] = qu[bb + (size_t)c * HW + i * NWD + w];
        T1[c * 129 + i] = qd[bb + (size_t)c * HW + i * NWD + w];
    }
    __syncthreads();
    float sc = sch[0];

    for (int t = 0; t < 4; t++) {
        int jg = ((tid & 7) | (t << 3)) * 4;
        int ig = (tid >> 3) * 4;
        float acc[4][4];
#pragma unroll
        for (int a = 0; a < 4; a++)
#pragma unroll
            for (int c = 0; c < 4; c++) acc[a][c] = 0.f;
#pragma unroll
        for (int c = 0; c < 32; c++) {
            float qv[4], kv[4];
#pragma unroll
            for (int u = 0; u < 4; u++) { qv[u] = T0[c * 129 + ig + u]; kv[u] = T1[c * 129 + jg + u]; }
#pragma unroll
            for (int ii = 0; ii < 4; ii++)
#pragma unroll
                for (int jj = 0; jj < 4; jj++) acc[ii][jj] = fmaf(qv[ii], kv[jj], acc[ii][jj]);
        }
#pragma unroll
        for (int ii = 0; ii < 4; ii++)
#pragma unroll
            for (int jj = 0; jj < 4; jj++) S[(ig + ii) * 129 + jg + jj] = acc[ii][jj] * sc;
    }
    __syncthreads();

    if (tid < 128) {
        float* row = S + tid * 129;
        float m = -1e30f;
        for (int j = 0; j < 128; j++) m = fmaxf(m, row[j]);
        float s = 0.f;
        for (int j = 0; j < 128; j++) { float e = __expf(row[j] - m); row[j] = e; s += e; }
        float invs = 1.0f / s;
        for (int j = 0; j < 128; j++) row[j] *= invs;
    }
    __syncthreads();

    for (int idx = tid; idx < 32 * 128; idx += 256) {
        int c = idx >> 7, i = idx & 127;
        T0[c * 129 + i] = qd[bb + (size_t)(96 + c) * HW + i * NWD + w];
        T1[c * 129 + i] = qu[bb + (size_t)(96 + c) * HW + i * NWD + w];
    }
    __syncthreads();

    {
        int cg = (tid & 7) * 4, ig = (tid >> 3) * 4;
        float acc[4][4];
#pragma unroll
        for (int a = 0; a < 4; a++)
#pragma unroll
            for (int c = 0; c < 4; c++) acc[a][c] = 0.f;
        for (int j = 0; j < 128; j++) {
            float av[4], vv[4];
#pragma unroll
            for (int u = 0; u < 4; u++) { av[u] = S[(ig + u) * 129 + j]; vv[u] = T0[(cg + u) * 129 + j]; }
#pragma unroll
            for (int ii = 0; ii < 4; ii++)
#pragma unroll
                for (int cc = 0; cc < 4; cc++) acc[ii][cc] = fmaf(av[ii], vv[cc], acc[ii][cc]);
        }
#pragma unroll
        for (int ii = 0; ii < 4; ii++)
#pragma unroll
            for (int cc = 0; cc < 4; cc++)
                d2u[ob + (size_t)(cg + cc) * HW + (ig + ii) * NWD + w] = acc[ii][cc];
    }
    {
        int cg = (tid & 7) * 4, jg = (tid >> 3) * 4;
        float acc[4][4];
#pragma unroll
        for (int a = 0; a < 4; a++)
#pragma unroll
            for (int c = 0; c < 4; c++) acc[a][c] = 0.f;
        for (int i = 0; i < 128; i++) {
            float av[4], vv[4];
#pragma unroll
            for (int u = 0; u < 4; u++) { av[u] = S[i * 129 + jg + u]; vv[u] = T1[(cg + u) * 129 + i]; }
#pragma unroll
            for (int jj = 0; jj < 4; jj++)
#pragma unroll
                for (int cc = 0; cc < 4; cc++) acc[jj][cc] = fmaf(av[jj], vv[cc], acc[jj][cc]);
        }
#pragma unroll
        for (int jj = 0; jj < 4; jj++)
#pragma unroll
            for (int cc = 0; cc < 4; cc++)
                u2d[ob + (size_t)(cg + cc) * HW + (jg + jj) * NWD + w] = acc[jj][cc];
    }
}

// ---------------- K5: width-axis attention, one CTA per (b,h) ----------------
__global__ void k_attn_w(const float* __restrict__ qu, const float* __restrict__ qd,
                         const float* __restrict__ scw,
                         float* __restrict__ d2u, float* __restrict__ u2d)
{
    extern __shared__ float sm[];
    float* S  = sm;
    float* T0 = sm + 128 * 129;
    float* T1 = T0 + 32 * 129;
    __shared__ float rf[128], gc[128];
    int h = blockIdx.x, b = blockIdx.y, tid = threadIdx.x;
    const size_t bb = (size_t)b * C2 * HW;
    const size_t ob = (size_t)b * NC * HW;
    const size_t ro = (size_t)h * NWD;

    for (int idx = tid; idx < 32 * 128; idx += 256) {
        int c = idx >> 7, j = idx & 127;
        T0[c * 129 + j] = qu[bb + (size_t)(32 + c) * HW + ro + j];
        T1[c * 129 + j] = qd[bb + (size_t)(32 + c) * HW + ro + j];
    }
    __syncthreads();
    float sc = scw[0];

    for (int t = 0; t < 4; t++) {
        int jg = ((tid & 7) | (t << 3)) * 4;
        int ig = (tid >> 3) * 4;
        float acc[4][4];
#pragma unroll
        for (int a = 0; a < 4; a++)
#pragma unroll
            for (int c = 0; c < 4; c++) acc[a][c] = 0.f;
#pragma unroll
        for (int c = 0; c < 32; c++) {
            float qv[4], kv[4];
#pragma unroll
            for (int u = 0; u < 4; u++) { qv[u] = T0[c * 129 + ig + u]; kv[u] = T1[c * 129 + jg + u]; }
#pragma unroll
            for (int ii = 0; ii < 4; ii++)
#pragma unroll
                for (int jj = 0; jj < 4; jj++) acc[ii][jj] = fmaf(qv[ii], kv[jj], acc[ii][jj]);
        }
#pragma unroll
        for (int ii = 0; ii < 4; ii++)
#pragma unroll
            for (int jj = 0; jj < 4; jj++) S[(ig + ii) * 129 + jg + jj] = acc[ii][jj] * sc;
    }
    __syncthreads();

    if (tid < 128) {
        int j = tid;
        float m = -1e30f;
        for (int i = 0; i < 128; i++) m = fmaxf(m, S[i * 129 + j]);
        float s = 0.f;
        for (int i = 0; i < 128; i++) s += __expf(S[i * 129 + j] - m);
        gc[j] = __expf(-m) / s;
    }
    __syncthreads();

    if (tid < 128) {
        float* row = S + tid * 129;
        float m = -1e30f;
        for (int j = 0; j < 128; j++) m = fmaxf(m, row[j]);
        float s = 0.f;
        for (int j = 0; j < 128; j++) { float e = __expf(row[j] - m); row[j] = e; s += e; }
        float invs = 1.0f / s;
        for (int j = 0; j < 128; j++) row[j] *= invs;
        rf[tid] = s * __expf(m);
    }
    __syncthreads();

    for (int idx = tid; idx < 32 * 128; idx += 256) {
        int c = idx >> 7, j = idx & 127;
        T0[c * 129 + j] = qd[bb + (size_t)(128 + c) * HW + ro + j];
        T1[c * 129 + j] = qu[bb + (size_t)(128 + c) * HW + ro + j];
    }
    __syncthreads();

    {
        int cg = (tid & 7) * 4, ig = (tid >> 3) * 4;
        float acc[4][4];
#pragma unroll
        for (int a = 0; a < 4; a++)
#pragma unroll
            for (int c = 0; c < 4; c++) acc[a][c] = 0.f;
        for (int j = 0; j < 128; j++) {
            float av[4], vv[4];
#pragma unroll
            for (int u = 0; u < 4; u++) { av[u] = S[(ig + u) * 129 + j]; vv[u] = T0[(cg + u) * 129 + j]; }
#pragma unroll
            for (int ii = 0; ii < 4; ii++)
#pragma unroll
                for (int cc = 0; cc < 4; cc++) acc[ii][cc] = fmaf(av[ii], vv[cc], acc[ii][cc]);
        }
#pragma unroll
        for (int ii = 0; ii < 4; ii++)
#pragma unroll
            for (int cc = 0; cc < 4; cc++)
                d2u[ob + (size_t)(32 + cg + cc) * HW + ro + (ig + ii)] = acc[ii][cc];
    }
    __syncthreads();

    for (int idx = tid; idx < 128 * 128; idx += 256) {
        int i = idx >> 7, j = idx & 127;
        S[i * 129 + j] *= rf[i] * gc[j];
    }
    __syncthreads();

    {
        int cg = (tid & 7) * 4, jg = (tid >> 3) * 4;
        float acc[4][4];
#pragma unroll
        for (int a = 0; a < 4; a++)
#pragma unroll
            for (int c = 0; c < 4; c++) acc[a][c] = 0.f;
        for (int i = 0; i < 128; i++) {
            float av[4], vv[4];
#pragma unroll
            for (int u = 0; u < 4; u++) { av[u] = S[i * 129 + jg + u]; vv[u] = T1[(cg + u) * 129 + i]; }
#pragma unroll
            for (int jj = 0; jj < 4; jj++)
#pragma unroll
                for (int cc = 0; cc < 4; cc++) acc[jj][cc] = fmaf(av[jj], vv[cc], acc[jj][cc]);
        }
#pragma unroll
        for (int jj = 0; jj < 4; jj++)
#pragma unroll
            for (int cc = 0; cc < 4; cc++)
                u2d[ob + (size_t)(32 + cg + cc) * HW + ro + (jg + jj)] = acc[jj][cc];
    }
}

// ---------------- K6a: channel scores split-K partials ----------------
__global__ void k_cpart(const float* __restrict__ qu, const float* __restrict__ qd,
                        float* __restrict__ spart)
{
    __shared__ float qs[32 * 129], ks[32 * 129];
    int chunk = blockIdx.x, b = blockIdx.y, tid = threadIdx.x;
    const size_t bb = (size_t)b * C2 * HW;
    int c0 = (tid >> 5) * 4, d = tid & 31;
    float acc[4] = {0.f, 0.f, 0.f, 0.f};
    for (int sub = 0; sub < 4; sub++) {
        int n0 = chunk * 512 + sub * 128;
        for (int idx = tid; idx < 32 * 128; idx += 256) {
            int c = idx >> 7, t = idx & 127;
            qs[c * 129 + t] = qu[bb + (size_t)(64 + c) * HW + n0 + t];
            ks[c * 129 + t] = qd[bb + (size_t)(64 + c) * HW + n0 + t];
        }
        __syncthreads();
        for (int t = 0; t < 128; t++) {
            float kv = ks[d * 129 + t];
#pragma unroll
            for (int cc = 0; cc < 4; cc++) acc[cc] = fmaf(qs[(c0 + cc) * 129 + t], kv, acc[cc]);
        }
        __syncthreads();
    }
#pragma unroll
    for (int cc = 0; cc < 4; cc++)
        spart[(((size_t)b * 32 + chunk) * 32 + c0 + cc) * 32 + d] = acc[cc];
}

// ---------------- K6b: reduce partials + row softmax -> A_c ----------------
__global__ void k_csoft(const float* __restrict__ spart, const float* __restrict__ scc,
                        float* __restrict__ ac)
{
    int b = blockIdx.x, d = threadIdx.x, c = threadIdx.y;
    float s = 0.f;
    for (int ch = 0; ch < 32; ch++)
        s += spart[(((size_t)b * 32 + ch) * 32 + c) * 32 + d];
    s *= scc[0];
    float m = s;
#pragma unroll
    for (int o = 16; o > 0; o >>= 1) m = fmaxf(m, __shfl_xor_sync(0xffffffffu, m, o));
    float e = __expf(s - m);
    float sum = e;
#pragma unroll
    for (int o = 16; o > 0; o >>= 1) sum += __shfl_xor_sync(0xffffffffu, sum, o);
    ac[((size_t)b * 32 + c) * 32 + d] = e / sum;
}

// ---------------- K6c: apply A_c to vd/vu ----------------
__global__ void k_capply(const float* __restrict__ qu, const float* __restrict__ qd,
                         const float* __restrict__ ac,
                         float* __restrict__ d2u, float* __restrict__ u2d)
{
    __shared__ float A[1024];
    int b = blockIdx.y, tid = threadIdx.x;
    int n = blockIdx.x * 256 + tid;
    for (int i = tid; i < 1024; i += 256) A[i] = ac[(size_t)b * 1024 + i];
    __syncthreads();
    const size_t bb = (size_t)b * C2 * HW;
    const size_t ob = (size_t)b * NC * HW;
    float vd[32], vu[32];
#pragma unroll
    for (int d = 0; d < 32; d++) {
        vd[d] = qd[bb + (size_t)(160 + d) * HW + n];
        vu[d] = qu[bb + (size_t)(160 + d) * HW + n];
    }
#pragma unroll
    for (int c = 0; c < 32; c++) {
        float ad = 0.f, au = 0.f;
#pragma unroll
        for (int d = 0; d < 32; d++) {
            float a = A[c * 32 + d];
            ad = fmaf(a, vd[d], ad);
            au = fmaf(a, vu[d], au);
        }
        d2u[ob + (size_t)(64 + c) * HW + n] = ad;
        u2d[ob + (size_t)(64 + c) * HW + n] = au;
    }
}

// ---------------- K7: epilogue ----------------
__global__ void k_epi(const float* __restrict__ d2u, const float* __restrict__ u2d,
                      const float* __restrict__ xu, const float* __restrict__ xd,
                      const float* __restrict__ stats,
                      const float* __restrict__ m1wu, const float* __restrict__ m1bu,
                      const float* __restrict__ m2wu, const float* __restrict__ m2bu,
                      const float* __restrict__ m1wd, const float* __restrict__ m1bd,
                      const float* __restrict__ m2wd, const float* __restrict__ m2bd,
                      float* __restrict__ out)
{
    size_t e = ((size_t)blockIdx.x * 256 + threadIdx.x) * 4;
    int b = (int)(e / (size_t)NCH);
    int c = (int)((e - (size_t)b * NCH) >> 14);
    float mu = stats[b * 2], su = stats[b * 2 + 1];
    float md = stats[2 * NB + b * 2], sd = stats[2 * NB + b * 2 + 1];
    float ru = su * m1wu[c] + m1bu[c];
    float bu = mu * m2wu[c] + m2bu[c];
    float rd = sd * m1wd[c] + m1bd[c];
    float bd = md * m2wd[c] + m2bd[c];
    float4 a = *(const float4*)&d2u[e];
    float4 u = *(const float4*)&u2d[e];
    float4 p = *(const float4*)&xu[e];
    float4 q = *(const float4*)&xd[e];
    float4 r;
    r.x = a.x * ru + bu + p.x + u.x * rd + bd + q.x;
    r.y = a.y * ru + bu + p.y + u.y * rd + bd + q.y;
    r.z = a.z * ru + bu + p.z + u.z * rd + bd + q.z;
    r.w = a.w * ru + bu + p.w + u.w * rd + bd + q.w;
    *(float4*)&out[e] = r;
}

// ---------------- launch ----------------
extern "C" void kernel_launch(void* const* d_in, const int* in_sizes, int n_in,
                              void* d_out, int out_size)
{
    const float* x_u  = (const float*)d_in[0];
    const float* x_d  = (const float*)d_in[1];
    const float* nw_u = (const float*)d_in[2];
    const float* nb_u = (const float*)d_in[3];
    const float* m1w_u = (const float*)d_in[4];
    const float* m1b_u = (const float*)d_in[5];
    const float* m2w_u = (const float*)d_in[6];
    const float* m2b_u = (const float*)d_in[7];
    const float* nw_d = (const float*)d_in[8];
    const float* nb_d = (const float*)d_in[9];
    const float* m1w_d = (const float*)d_in[10];
    const float* m1b_d = (const float*)d_in[11];
    const float* m2w_d = (const float*)d_in[12];
    const float* m2b_d = (const float*)d_in[13];
    const float* Wqkv_u = (const float*)d_in[14];
    const float* bqkv_u = (const float*)d_in[15];
    const float* Wqkv_d = (const float*)d_in[16];
    const float* bqkv_d = (const float*)d_in[17];
    const float* scale_h = (const float*)d_in[18];
    const float* scale_w = (const float*)d_in[19];
    const float* scale_c = (const float*)d_in[20];
    float* out = (float*)d_out;

    static bool s_init = false;
    static float *p_qu, *p_qd, *p_du, *p_ud, *p_part, *p_stats, *p_sp, *p_ac;
    if (!s_init) {
        cudaGetSymbolAddress((void**)&p_qu, g_qkv_u);
        cudaGetSymbolAddress((void**)&p_qd, g_qkv_d);
        cudaGetSymbolAddress((void**)&p_du, g_d2u);
        cudaGetSymbolAddress((void**)&p_ud, g_u2d);
        cudaGetSymbolAddress((void**)&p_part, g_part);
        cudaGetSymbolAddress((void**)&p_stats, g_stats);
        cudaGetSymbolAddress((void**)&p_sp, g_spart);
        cudaGetSymbolAddress((void**)&p_ac, g_ac);
        cudaFuncSetAttribute(k_pconv_tc, cudaFuncAttributeMaxDynamicSharedMemorySize, (64 * PIT + 128 * PIT) * 4);
        cudaFuncSetAttribute(k_attn_h, cudaFuncAttributeMaxDynamicSharedMemorySize, (128 * 129 + 2 * 32 * 129) * 4);
        cudaFuncSetAttribute(k_attn_w, cudaFuncAttributeMaxDynamicSharedMemorySize, (128 * 129 + 2 * 32 * 129) * 4);
        s_init = true;
    }

    // stats
    k_reduce1<<<dim3(256, NB, 2), 256>>>(x_u, x_d, p_part);
    k_reduce2<<<dim3(NB, 2), 256>>>(p_part, p_stats);

    // fused normalize + qkv 1x1 conv (tf32 tensor core)
    size_t smemG = (size_t)(64 * PIT + 128 * PIT) * 4;
    k_pconv_tc<<<dim3(128, 3, NB), 256, smemG>>>(x_u, Wqkv_u, bqkv_u, nw_u, nb_u, p_stats,          p_qu);
    k_pconv_tc<<<dim3(128, 3, NB), 256, smemG>>>(x_d, Wqkv_d, bqkv_d, nw_d, nb_d, p_stats + 2 * NB, p_qd);

    // attentions
    size_t smemA = (size_t)(128 * 129 + 2 * 32 * 129) * 4;
    k_attn_h<<<dim3(NWD, NB), 256, smemA>>>(p_qu, p_qd, scale_h, p_du, p_ud);
    k_attn_w<<<dim3(NH,  NB), 256, smemA>>>(p_qu, p_qd, scale_w, p_du, p_ud);
    k_cpart<<<dim3(32, NB), 256>>>(p_qu, p_qd, p_sp);
    k_csoft<<<NB, dim3(32, 32)>>>(p_sp, scale_c, p_ac);
    k_capply<<<dim3(HW / 256, NB), 256>>>(p_qu, p_qd, p_ac, p_du, p_ud);

    // epilogue
    k_epi<<<(NB * NCH) / (256 * 4), 256>>>(p_du, p_ud, x_u, x_d, p_stats,
                                           m1w_u, m1b_u, m2w_u, m2b_u,
                                           m1w_d, m1b_d, m2w_d, m2b_d, out);
}

// round 4
// speedup vs baseline: 1.7663x; 1.2446x over previous
#include <cuda_runtime.h>
#include <math.h>
#include <stdint.h>

// ---------------- problem constants ----------------
static constexpr int NB   = 8;
static constexpr int NC   = 96;
static constexpr int NH   = 128;
static constexpr int NWD  = 128;
static constexpr int HW   = NH * NWD;   // 16384
static constexpr int NCH  = NC * HW;
static constexpr int C2   = 2 * NC;     // 192

// ---------------- scratch ----------------
__device__ float g_qkv_u[(size_t)NB * C2 * HW];
__device__ float g_qkv_d[(size_t)NB * C2 * HW];
__device__ float g_d2u  [(size_t)NB * NC * HW];
__device__ float g_u2d  [(size_t)NB * NC * HW];
__device__ float g_part [2 * NB * 256 * 2];
__device__ float g_stats[2 * NB * 2];
__device__ float g_spart[(size_t)NB * 32 * 32 * 32];
__device__ float g_ac   [NB * 32 * 32];
__device__ float g_tin  [(size_t)4 * NB * 32 * HW];  // transposed h-attn inputs [t][b][c][w][h]
__device__ float g_tout [(size_t)2 * NB * 32 * HW];  // transposed h-attn outputs

// ---------------- K1/K2: mean/var ----------------
__global__ void k_reduce1(const float* __restrict__ xu, const float* __restrict__ xd,
                          float* __restrict__ part)
{
    int chunk = blockIdx.x, b = blockIdx.y, z = blockIdx.z;
    const float* x = (z == 0 ? xu : xd) + (size_t)b * NCH + (size_t)chunk * 6144;
    float s = 0.f, ss = 0.f;
    for (int i = threadIdx.x; i < 6144; i += 256) { float v = x[i]; s += v; ss += v * v; }
    __shared__ float sh[256], sh2[256];
    sh[threadIdx.x] = s; sh2[threadIdx.x] = ss;
    __syncthreads();
    for (int o = 128; o > 0; o >>= 1) {
        if (threadIdx.x < o) { sh[threadIdx.x] += sh[threadIdx.x + o]; sh2[threadIdx.x] += sh2[threadIdx.x + o]; }
        __syncthreads();
    }
    if (threadIdx.x == 0) {
        int o = ((z * NB + b) * 256 + chunk) * 2;
        part[o] = sh[0]; part[o + 1] = sh2[0];
    }
}

__global__ void k_reduce2(const float* __restrict__ part, float* __restrict__ stats)
{
    int b = blockIdx.x, z = blockIdx.y, tid = threadIdx.x;
    __shared__ double sh[256], sh2[256];
    int o = ((z * NB + b) * 256 + tid) * 2;
    sh[tid] = (double)part[o]; sh2[tid] = (double)part[o + 1];
    __syncthreads();
    for (int s = 128; s > 0; s >>= 1) {
        if (tid < s) { sh[tid] += sh[tid + s]; sh2[tid] += sh2[tid + s]; }
        __syncthreads();
    }
    if (tid == 0) {
        double mean = sh[0] / (double)NCH;
        double var  = sh2[0] / (double)NCH - mean * mean;
        stats[(z * NB + b) * 2 + 0] = (float)mean;
        stats[(z * NB + b) * 2 + 1] = sqrtf((float)var + 1e-5f);
    }
}

// ---------------- tf32 helpers ----------------
__device__ __forceinline__ float to_tf32(float v) {
    uint32_t u;
    asm("cvt.rna.tf32.f32 %0, %1;" : "=r"(u) : "f"(v));
    return __uint_as_float(u);
}
__device__ __forceinline__ uint32_t ldu(const float* p) { return __float_as_uint(*p); }

__device__ __forceinline__ void mma_tf32(float* c,
                                         uint32_t a0, uint32_t a1, uint32_t a2, uint32_t a3,
                                         uint32_t b0, uint32_t b1)
{
    asm volatile("mma.sync.aligned.m16n8k8.row.col.f32.tf32.tf32.f32 "
                 "{%0,%1,%2,%3}, {%4,%5,%6,%7}, {%8,%9}, {%0,%1,%2,%3};"
                 : "+f"(c[0]), "+f"(c[1]), "+f"(c[2]), "+f"(c[3])
                 : "r"(a0), "r"(a1), "r"(a2), "r"(a3), "r"(b0), "r"(b1));
}

// ---------------- K3: fused normalize + 1x1 conv GEMM (tf32) ----------------
static constexpr int PIT = 100;

__global__ void k_pconv_tc(const float* __restrict__ x, const float* __restrict__ Wm,
                           const float* __restrict__ bias, const float* __restrict__ nw,
                           const float* __restrict__ nb, const float* __restrict__ stats,
                           float* __restrict__ out)
{
    extern __shared__ float sm[];
    float* sA = sm;
    float* sB = sm + 64 * PIT;
    int b = blockIdx.z, mBase = blockIdx.y * 64, nBase = blockIdx.x * 128;
    int tid = threadIdx.x;
    float mean = stats[b * 2], inv = 1.0f / stats[b * 2 + 1];

    for (int idx = tid; idx < 64 * 96; idx += 256) {
        int m = idx / 96, k = idx - m * 96;
        sA[m * PIT + k] = to_tf32(Wm[(mBase + m) * 96 + k]);
    }
    for (int idx = tid; idx < 96 * 128; idx += 256) {
        int k = idx >> 7, n = idx & 127;
        float v = x[((size_t)b * NC + k) * HW + nBase + n];
        sB[n * PIT + k] = to_tf32((v - mean) * inv * nw[k] + nb[k]);
    }
    __syncthreads();

    int warp = tid >> 5, lane = tid & 31;
    int warpM = warp & 1, warpN = warp >> 1;
    int g = lane >> 2, tg = lane & 3;

    float acc[2][4][4];
#pragma unroll
    for (int mt = 0; mt < 2; mt++)
#pragma unroll
        for (int nt = 0; nt < 4; nt++)
#pragma unroll
            for (int r = 0; r < 4; r++) acc[mt][nt][r] = 0.f;

    const float* pa = sA + (warpM * 32 + g) * PIT + tg;
    const float* pb = sB + (warpN * 32 + g) * PIT + tg;

#pragma unroll
    for (int ks = 0; ks < 12; ks++) {
        int k0 = ks * 8;
        uint32_t a[2][4], bf[4][2];
#pragma unroll
        for (int mt = 0; mt < 2; mt++) {
            const float* p = pa + mt * 16 * PIT + k0;
            a[mt][0] = ldu(p); a[mt][1] = ldu(p + 8 * PIT);
            a[mt][2] = ldu(p + 4); a[mt][3] = ldu(p + 8 * PIT + 4);
        }
#pragma unroll
        for (int nt = 0; nt < 4; nt++) {
            const float* p = pb + nt * 8 * PIT + k0;
            bf[nt][0] = ldu(p); bf[nt][1] = ldu(p + 4);
        }
#pragma unroll
        for (int mt = 0; mt < 2; mt++)
#pragma unroll
            for (int nt = 0; nt < 4; nt++)
                mma_tf32(acc[mt][nt], a[mt][0], a[mt][1], a[mt][2], a[mt][3], bf[nt][0], bf[nt][1]);
    }

#pragma unroll
    for (int mt = 0; mt < 2; mt++) {
        int o0 = mBase + warpM * 32 + mt * 16 + g;
        float bs0 = bias[o0], bs1 = bias[o0 + 8];
        size_t base0 = ((size_t)b * C2 + o0) * HW + nBase + warpN * 32;
        size_t base1 = base0 + (size_t)8 * HW;
#pragma unroll
        for (int nt = 0; nt < 4; nt++) {
            int nc0 = nt * 8 + tg * 2;
            *(float2*)&out[base0 + nc0] = make_float2(acc[mt][nt][0] + bs0, acc[mt][nt][1] + bs0);
            *(float2*)&out[base1 + nc0] = make_float2(acc[mt][nt][2] + bs1, acc[mt][nt][3] + bs1);
        }
    }
}

// ---------------- transpose helpers (32x32 tiles) ----------------
// in: for h-attn. t=0: qu ch c; t=1: qd ch c; t=2: qd ch 96+c; t=3: qu ch 96+c.
__global__ void k_tin(const float* __restrict__ qu, const float* __restrict__ qd,
                      float* __restrict__ tin)
{
    __shared__ float sh[32][33];
    int tile = blockIdx.x;
    int wb = (tile & 3) * 32, hb = (tile >> 2) * 32;
    int c = blockIdx.y;
    int z = blockIdx.z, t = z & 3, b = z >> 2;
    int tx = threadIdx.x, ty = threadIdx.y;
    const float* base = (t == 0 || t == 3) ? qu : qd;
    int coff = (t >= 2) ? 96 + c : c;
    const float* src = base + ((size_t)b * C2 + coff) * HW;
#pragma unroll
    for (int r = 0; r < 4; r++)
        sh[ty + 8 * r][tx] = src[(hb + ty + 8 * r) * 128 + wb + tx];
    __syncthreads();
    float* dst = tin + ((size_t)(t * NB + b) * 32 + c) * HW;
#pragma unroll
    for (int r = 0; r < 4; r++)
        dst[(wb + ty + 8 * r) * 128 + hb + tx] = sh[tx][ty + 8 * r];
}

// out: tout [t][b][c][w][h] -> (t=0: d2u ch c, t=1: u2d ch c) [h][w]
__global__ void k_tout(const float* __restrict__ tout,
                       float* __restrict__ d2u, float* __restrict__ u2d)
{
    __shared__ float sh[32][33];
    int tile = blockIdx.x;
    int hb = (tile & 3) * 32, wb = (tile >> 2) * 32;
    int c = blockIdx.y;
    int z = blockIdx.z, t = z & 1, b = z >> 1;
    int tx = threadIdx.x, ty = threadIdx.y;
    const float* src = tout + ((size_t)(t * NB + b) * 32 + c) * HW;   // [w][h]
#pragma unroll
    for (int r = 0; r < 4; r++)
        sh[ty + 8 * r][tx] = src[(wb + ty + 8 * r) * 128 + hb + tx];
    __syncthreads();
    float* dst = (t == 0 ? d2u : u2d) + ((size_t)b * NC + c) * HW;    // [h][w]
#pragma unroll
    for (int r = 0; r < 4; r++)
        dst[(hb + ty + 8 * r) * 128 + wb + tx] = sh[tx][ty + 8 * r];
}

// ---------------- tensor-core attention ----------------
static constexpr int PS = 132;   // S pitch
static constexpr int PT = 132;   // tile pitch
static constexpr int ASMEM = (128 * PS + 2 * 32 * PT);   // floats

// height-axis attention on transposed data. CTA = (w, b).
__global__ __launch_bounds__(256, 2)
void k_attn_h_tc(const float* __restrict__ tin, const float* __restrict__ sch,
                 float* __restrict__ tout)
{
    extern __shared__ float sm[];
    float* S  = sm;
    float* T0 = sm + 128 * PS;
    float* T1 = T0 + 32 * PT;
    int w = blockIdx.x, b = blockIdx.y, tid = threadIdx.x;
    int warp = tid >> 5, lane = tid & 31, g = lane >> 2, tg = lane & 3;
    const size_t GRP = (size_t)NB * 32 * HW;
    const float* qp  = tin + (size_t)b * 32 * HW + (size_t)w * 128;
    const float* kp  = qp + GRP;
    const float* vdp = qp + 2 * GRP;
    const float* vup = qp + 3 * GRP;

    for (int idx = tid; idx < 32 * 128; idx += 256) {
        int c = idx >> 7, i = idx & 127;
        T0[c * PT + i] = to_tf32(qp[(size_t)c * HW + i]);
        T1[c * PT + i] = to_tf32(kp[(size_t)c * HW + i]);
    }
    __syncthreads();
    float sc = sch[0];

    // S[i][j] = sc * sum_c Q[c][i] K[c][j]
    int ib = warp * 16;
    {
        float acc[16][4];
#pragma unroll
        for (int jt = 0; jt < 16; jt++)
#pragma unroll
            for (int r = 0; r < 4; r++) acc[jt][r] = 0.f;
#pragma unroll
        for (int ks = 0; ks < 4; ks++) {
            int k0 = ks * 8;
            uint32_t a0 = ldu(&T0[(k0 + tg) * PT + ib + g]);
            uint32_t a1 = ldu(&T0[(k0 + tg) * PT + ib + g + 8]);
            uint32_t a2 = ldu(&T0[(k0 + tg + 4) * PT + ib + g]);
            uint32_t a3 = ldu(&T0[(k0 + tg + 4) * PT + ib + g + 8]);
#pragma unroll
            for (int jt = 0; jt < 16; jt++) {
                int jb = jt * 8;
                uint32_t b0 = ldu(&T1[(k0 + tg) * PT + jb + g]);
                uint32_t b1 = ldu(&T1[(k0 + tg + 4) * PT + jb + g]);
                mma_tf32(acc[jt], a0, a1, a2, a3, b0, b1);
            }
        }
#pragma unroll
        for (int jt = 0; jt < 16; jt++) {
            int jb = jt * 8;
            S[(ib + g) * PS + jb + 2 * tg]         = acc[jt][0] * sc;
            S[(ib + g) * PS + jb + 2 * tg + 1]     = acc[jt][1] * sc;
            S[(ib + g + 8) * PS + jb + 2 * tg]     = acc[jt][2] * sc;
            S[(ib + g + 8) * PS + jb + 2 * tg + 1] = acc[jt][3] * sc;
        }
    }
    __syncthreads();

    // row softmax, warp-parallel
#pragma unroll 1
    for (int t = 0; t < 16; t++) {
        int r = warp * 16 + t;
        float* row = S + r * PS;
        float v0 = row[lane], v1 = row[lane + 32], v2 = row[lane + 64], v3 = row[lane + 96];
        float m = fmaxf(fmaxf(v0, v1), fmaxf(v2, v3));
#pragma unroll
        for (int o = 16; o > 0; o >>= 1) m = fmaxf(m, __shfl_xor_sync(0xffffffffu, m, o));
        float e0 = __expf(v0 - m), e1 = __expf(v1 - m), e2 = __expf(v2 - m), e3 = __expf(v3 - m);
        float s = e0 + e1 + e2 + e3;
#pragma unroll
        for (int o = 16; o > 0; o >>= 1) s += __shfl_xor_sync(0xffffffffu, s, o);
        float inv = 1.0f / s;
        row[lane] = e0 * inv; row[lane + 32] = e1 * inv; row[lane + 64] = e2 * inv; row[lane + 96] = e3 * inv;
    }
    __syncthreads();

    for (int idx = tid; idx < 32 * 128; idx += 256) {
        int c = idx >> 7, i = idx & 127;
        T0[c * PT + i] = to_tf32(vdp[(size_t)c * HW + i]);
        T1[c * PT + i] = to_tf32(vup[(size_t)c * HW + i]);
    }
    __syncthreads();

    // E[i][c] = sum_j S[i][j] Vd[c][j]
    float accD[4][4], accU[4][4];
#pragma unroll
    for (int ct = 0; ct < 4; ct++)
#pragma unroll
        for (int r = 0; r < 4; r++) { accD[ct][r] = 0.f; accU[ct][r] = 0.f; }

#pragma unroll 4
    for (int ks = 0; ks < 16; ks++) {
        int k0 = ks * 8;
        uint32_t a0 = ldu(&S[(ib + g) * PS + k0 + tg]);
        uint32_t a1 = ldu(&S[(ib + g + 8) * PS + k0 + tg]);
        uint32_t a2 = ldu(&S[(ib + g) * PS + k0 + tg + 4]);
        uint32_t a3 = ldu(&S[(ib + g + 8) * PS + k0 + tg + 4]);
#pragma unroll
        for (int ct = 0; ct < 4; ct++) {
            int cb = ct * 8;
            uint32_t b0 = ldu(&T0[(cb + g) * PT + k0 + tg]);
            uint32_t b1 = ldu(&T0[(cb + g) * PT + k0 + tg + 4]);
            mma_tf32(accD[ct], a0, a1, a2, a3, b0, b1);
        }
    }
    // F[j][c] = sum_i S[i][j] Vu[c][i]   (A = S^T)
#pragma unroll 4
    for (int ks = 0; ks < 16; ks++) {
        int k0 = ks * 8;
        uint32_t a0 = ldu(&S[(k0 + tg) * PS + ib + g]);
        uint32_t a1 = ldu(&S[(k0 + tg) * PS + ib + g + 8]);
        uint32_t a2 = ldu(&S[(k0 + tg + 4) * PS + ib + g]);
        uint32_t a3 = ldu(&S[(k0 + tg + 4) * PS + ib + g + 8]);
#pragma unroll
        for (int ct = 0; ct < 4; ct++) {
            int cb = ct * 8;
            uint32_t b0 = ldu(&T1[(cb + g) * PT + k0 + tg]);
            uint32_t b1 = ldu(&T1[(cb + g) * PT + k0 + tg + 4]);
            mma_tf32(accU[ct], a0, a1, a2, a3, b0, b1);
        }
    }
    __syncthreads();   // everyone done reading T0/T1

    // stage results [c][i] for coalesced write
#pragma unroll
    for (int ct = 0; ct < 4; ct++) {
        int cb = ct * 8;
        T0[(cb + 2 * tg) * PT + ib + g]         = accD[ct][0];
        T0[(cb + 2 * tg + 1) * PT + ib + g]     = accD[ct][1];
        T0[(cb + 2 * tg) * PT + ib + g + 8]     = accD[ct][2];
        T0[(cb + 2 * tg + 1) * PT + ib + g + 8] = accD[ct][3];
        T1[(cb + 2 * tg) * PT + ib + g]         = accU[ct][0];
        T1[(cb + 2 * tg + 1) * PT + ib + g]     = accU[ct][1];
        T1[(cb + 2 * tg) * PT + ib + g + 8]     = accU[ct][2];
        T1[(cb + 2 * tg + 1) * PT + ib + g + 8] = accU[ct][3];
    }
    __syncthreads();

    const size_t GRPO = (size_t)NB * 32 * HW;
    float* du = tout + (size_t)b * 32 * HW + (size_t)w * 128;
    float* ud = tout + GRPO + (size_t)b * 32 * HW + (size_t)w * 128;
    for (int idx = tid; idx < 32 * 128; idx += 256) {
        int c = idx >> 7, i = idx & 127;
        du[(size_t)c * HW + i] = T0[c * PT + i];
        ud[(size_t)c * HW + i] = T1[c * PT + i];
    }
}

// width-axis attention, natural layout. CTA = (h, b). Needs row AND col softmax.
__global__ __launch_bounds__(256, 2)
void k_attn_w_tc(const float* __restrict__ qu, const float* __restrict__ qd,
                 const float* __restrict__ scw,
                 float* __restrict__ d2u, float* __restrict__ u2d)
{
    extern __shared__ float sm[];
    float* S  = sm;
    float* T0 = sm + 128 * PS;
    float* T1 = T0 + 32 * PT;
    __shared__ float aux[4][128];
    __shared__ float rf[128], gc[128];
    int h = blockIdx.x, b = blockIdx.y, tid = threadIdx.x;
    int warp = tid >> 5, lane = tid & 31, g = lane >> 2, tg = lane & 3;
    const size_t bb = (size_t)b * C2 * HW;
    const size_t ro = (size_t)h * 128;
    const float* qp  = qu + bb + (size_t)32 * HW + ro;
    const float* kp  = qd + bb + (size_t)32 * HW + ro;
    const float* vdp = qd + bb + (size_t)128 * HW + ro;
    const float* vup = qu + bb + (size_t)128 * HW + ro;

    for (int idx = tid; idx < 32 * 128; idx += 256) {
        int c = idx >> 7, j = idx & 127;
        T0[c * PT + j] = to_tf32(qp[(size_t)c * HW + j]);
        T1[c * PT + j] = to_tf32(kp[(size_t)c * HW + j]);
    }
    __syncthreads();
    float sc = scw[0];

    int ib = warp * 16;
    {
        float acc[16][4];
#pragma unroll
        for (int jt = 0; jt < 16; jt++)
#pragma unroll
            for (int r = 0; r < 4; r++) acc[jt][r] = 0.f;
#pragma unroll
        for (int ks = 0; ks < 4; ks++) {
            int k0 = ks * 8;
            uint32_t a0 = ldu(&T0[(k0 + tg) * PT + ib + g]);
            uint32_t a1 = ldu(&T0[(k0 + tg) * PT + ib + g + 8]);
            uint32_t a2 = ldu(&T0[(k0 + tg + 4) * PT + ib + g]);
            uint32_t a3 = ldu(&T0[(k0 + tg + 4) * PT + ib + g + 8]);
#pragma unroll
            for (int jt = 0; jt < 16; jt++) {
                int jb = jt * 8;
                uint32_t b0 = ldu(&T1[(k0 + tg) * PT + jb + g]);
                uint32_t b1 = ldu(&T1[(k0 + tg + 4) * PT + jb + g]);
                mma_tf32(acc[jt], a0, a1, a2, a3, b0, b1);
            }
        }
#pragma unroll
        for (int jt = 0; jt < 16; jt++) {
            int jb = jt * 8;
            S[(ib + g) * PS + jb + 2 * tg]         = acc[jt][0] * sc;
            S[(ib + g) * PS + jb + 2 * tg + 1]     = acc[jt][1] * sc;
            S[(ib + g + 8) * PS + jb + 2 * tg]     = acc[jt][2] * sc;
            S[(ib + g + 8) * PS + jb + 2 * tg + 1] = acc[jt][3] * sc;
        }
    }
    __syncthreads();

    // column stats: gc[j] = exp(-cmax_j)/csum_j
    {
        int c = tid & 127, half = tid >> 7;
        float m = -1e30f;
        for (int i = half * 64; i < half * 64 + 64; i++) m = fmaxf(m, S[i * PS + c]);
        aux[half][c] = m;
        __syncthreads();
        float M = fmaxf(aux[0][c], aux[1][c]);
        float s = 0.f;
        for (int i = half * 64; i < half * 64 + 64; i++) s += __expf(S[i * PS + c] - M);
        aux[2 + half][c] = s;
        __syncthreads();
        if (tid < 128) gc[tid] = __expf(-M) / (aux[2][tid] + aux[3][tid]);
    }
    __syncthreads();

    // row softmax (A1) + rf
#pragma unroll 1
    for (int t = 0; t < 16; t++) {
        int r = warp * 16 + t;
        float* row = S + r * PS;
        float v0 = row[lane], v1 = row[lane + 32], v2 = row[lane + 64], v3 = row[lane + 96];
        float m = fmaxf(fmaxf(v0, v1), fmaxf(v2, v3));
#pragma unroll
        for (int o = 16; o > 0; o >>= 1) m = fmaxf(m, __shfl_xor_sync(0xffffffffu, m, o));
        float e0 = __expf(v0 - m), e1 = __expf(v1 - m), e2 = __expf(v2 - m), e3 = __expf(v3 - m);
        float s = e0 + e1 + e2 + e3;
#pragma unroll
        for (int o = 16; o > 0; o >>= 1) s += __shfl_xor_sync(0xffffffffu, s, o);
        float inv = 1.0f / s;
        row[lane] = e0 * inv; row[lane + 32] = e1 * inv; row[lane + 64] = e2 * inv; row[lane + 96] = e3 * inv;
        if (lane == 0) rf[r] = s * __expf(m);
    }
    __syncthreads();

    for (int idx = tid; idx < 32 * 128; idx += 256) {
        int c = idx >> 7, j = idx & 127;
        T0[c * PT + j] = to_tf32(vdp[(size_t)c * HW + j]);
        T1[c * PT + j] = to_tf32(vup[(size_t)c * HW + j]);
    }
    __syncthreads();

    // d2u[c][i] = sum_j A1[i][j] Vd[c][j]
    float accD[4][4];
#pragma unroll
    for (int ct = 0; ct < 4; ct++)
#pragma unroll
        for (int r = 0; r < 4; r++) accD[ct][r] = 0.f;
#pragma unroll 4
    for (int ks = 0; ks < 16; ks++) {
        int k0 = ks * 8;
        uint32_t a0 = ldu(&S[(ib + g) * PS + k0 + tg]);
        uint32_t a1 = ldu(&S[(ib + g + 8) * PS + k0 + tg]);
        uint32_t a2 = ldu(&S[(ib + g) * PS + k0 + tg + 4]);
        uint32_t a3 = ldu(&S[(ib + g + 8) * PS + k0 + tg + 4]);
#pragma unroll
        for (int ct = 0; ct < 4; ct++) {
            int cb = ct * 8;
            uint32_t b0 = ldu(&T0[(cb + g) * PT + k0 + tg]);
            uint32_t b1 = ldu(&T0[(cb + g) * PT + k0 + tg + 4]);
            mma_tf32(accD[ct], a0, a1, a2, a3, b0, b1);
        }
    }
    __syncthreads();   // all warps done reading A1

    // A2[i][j] = A1[i][j] * rf[i] * gc[j]
    for (int idx = tid; idx < 128 * 128; idx += 256) {
        int i = idx >> 7, j = idx & 127;
        S[i * PS + j] *= rf[i] * gc[j];
    }
    __syncthreads();

    // u2d[c][j] = sum_i A2[i][j] Vu[c][i]
    float accU[4][4];
#pragma unroll
    for (int ct = 0; ct < 4; ct++)
#pragma unroll
        for (int r = 0; r < 4; r++) accU[ct][r] = 0.f;
#pragma unroll 4
    for (int ks = 0; ks < 16; ks++) {
        int k0 = ks * 8;
        uint32_t a0 = ldu(&S[(k0 + tg) * PS + ib + g]);
        uint32_t a1 = ldu(&S[(k0 + tg) * PS + ib + g + 8]);
        uint32_t a2 = ldu(&S[(k0 + tg + 4) * PS + ib + g]);
        uint32_t a3 = ldu(&S[(k0 + tg + 4) * PS + ib + g + 8]);
#pragma unroll
        for (int ct = 0; ct < 4; ct++) {
            int cb = ct * 8;
            uint32_t b0 = ldu(&T1[(cb + g) * PT + k0 + tg]);
            uint32_t b1 = ldu(&T1[(cb + g) * PT + k0 + tg + 4]);
            mma_tf32(accU[ct], a0, a1, a2, a3, b0, b1);
        }
    }
    __syncthreads();

#pragma unroll
    for (int ct = 0; ct < 4; ct++) {
        int cb = ct * 8;
        T0[(cb + 2 * tg) * PT + ib + g]         = accD[ct][0];
        T0[(cb + 2 * tg + 1) * PT + ib + g]     = accD[ct][1];
        T0[(cb + 2 * tg) * PT + ib + g + 8]     = accD[ct][2];
        T0[(cb + 2 * tg + 1) * PT + ib + g + 8] = accD[ct][3];
        T1[(cb + 2 * tg) * PT + ib + g]         = accU[ct][0];
        T1[(cb + 2 * tg + 1) * PT + ib + g]     = accU[ct][1];
        T1[(cb + 2 * tg) * PT + ib + g + 8]     = accU[ct][2];
        T1[(cb + 2 * tg + 1) * PT + ib + g + 8] = accU[ct][3];
    }
    __syncthreads();

    float* du = d2u + ((size_t)b * NC + 32) * HW + ro;
    float* ud = u2d + ((size_t)b * NC + 32) * HW + ro;
    for (int idx = tid; idx < 32 * 128; idx += 256) {
        int c = idx >> 7, j = idx & 127;
        du[(size_t)c * HW + j] = T0[c * PT + j];
        ud[(size_t)c * HW + j] = T1[c * PT + j];
    }
}

// ---------------- channel attention ----------------
__global__ void k_cpart(const float* __restrict__ qu, const float* __restrict__ qd,
                        float* __restrict__ spart)
{
    __shared__ float qs[32 * 129], ks[32 * 129];
    int chunk = blockIdx.x, b = blockIdx.y, tid = threadIdx.x;
    const size_t bb = (size_t)b * C2 * HW;
    int c0 = (tid >> 5) * 4, d = tid & 31;
    float acc[4] = {0.f, 0.f, 0.f, 0.f};
    for (int sub = 0; sub < 4; sub++) {
        int n0 = chunk * 512 + sub * 128;
        for (int idx = tid; idx < 32 * 128; idx += 256) {
            int c = idx >> 7, t = idx & 127;
            qs[c * 129 + t] = qu[bb + (size_t)(64 + c) * HW + n0 + t];
            ks[c * 129 + t] = qd[bb + (size_t)(64 + c) * HW + n0 + t];
        }
        __syncthreads();
        for (int t = 0; t < 128; t++) {
            float kv = ks[d * 129 + t];
#pragma unroll
            for (int cc = 0; cc < 4; cc++) acc[cc] = fmaf(qs[(c0 + cc) * 129 + t], kv, acc[cc]);
        }
        __syncthreads();
    }
#pragma unroll
    for (int cc = 0; cc < 4; cc++)
        spart[(((size_t)b * 32 + chunk) * 32 + c0 + cc) * 32 + d] = acc[cc];
}

__global__ void k_csoft(const float* __restrict__ spart, const float* __restrict__ scc,
                        float* __restrict__ ac)
{
    int b = blockIdx.x, d = threadIdx.x, c = threadIdx.y;
    float s = 0.f;
    for (int ch = 0; ch < 32; ch++)
        s += spart[(((size_t)b * 32 + ch) * 32 + c) * 32 + d];
    s *= scc[0];
    float m = s;
#pragma unroll
    for (int o = 16; o > 0; o >>= 1) m = fmaxf(m, __shfl_xor_sync(0xffffffffu, m, o));
    float e = __expf(s - m);
    float sum = e;
#pragma unroll
    for (int o = 16; o > 0; o >>= 1) sum += __shfl_xor_sync(0xffffffffu, sum, o);
    ac[((size_t)b * 32 + c) * 32 + d] = e / sum;
}

__global__ void k_capply(const float* __restrict__ qu, const float* __restrict__ qd,
                         const float* __restrict__ ac,
                         float* __restrict__ d2u, float* __restrict__ u2d)
{
    __shared__ float A[1024];
    int b = blockIdx.y, tid = threadIdx.x;
    int n = blockIdx.x * 256 + tid;
    for (int i = tid; i < 1024; i += 256) A[i] = ac[(size_t)b * 1024 + i];
    __syncthreads();
    const size_t bb = (size_t)b * C2 * HW;
    const size_t ob = (size_t)b * NC * HW;
    float vd[32], vu[32];
#pragma unroll
    for (int d = 0; d < 32; d++) {
        vd[d] = qd[bb + (size_t)(160 + d) * HW + n];
        vu[d] = qu[bb + (size_t)(160 + d) * HW + n];
    }
#pragma unroll
    for (int c = 0; c < 32; c++) {
        float ad = 0.f, au = 0.f;
#pragma unroll
        for (int d = 0; d < 32; d++) {
            float a = A[c * 32 + d];
            ad = fmaf(a, vd[d], ad);
            au = fmaf(a, vu[d], au);
        }
        d2u[ob + (size_t)(64 + c) * HW + n] = ad;
        u2d[ob + (size_t)(64 + c) * HW + n] = au;
    }
}

// ---------------- epilogue ----------------
__global__ void k_epi(const float* __restrict__ d2u, const float* __restrict__ u2d,
                      const float* __restrict__ xu, const float* __restrict__ xd,
                      const float* __restrict__ stats,
                      const float* __restrict__ m1wu, const float* __restrict__ m1bu,
                      const float* __restrict__ m2wu, const float* __restrict__ m2bu,
                      const float* __restrict__ m1wd, const float* __restrict__ m1bd,
                      const float* __restrict__ m2wd, const float* __restrict__ m2bd,
                      float* __restrict__ out)
{
    size_t e = ((size_t)blockIdx.x * 256 + threadIdx.x) * 4;
    int b = (int)(e / (size_t)NCH);
    int c = (int)((e - (size_t)b * NCH) >> 14);
    float mu = stats[b * 2], su = stats[b * 2 + 1];
    float md = stats[2 * NB + b * 2], sd = stats[2 * NB + b * 2 + 1];
    float ru = su * m1wu[c] + m1bu[c];
    float bu = mu * m2wu[c] + m2bu[c];
    float rd = sd * m1wd[c] + m1bd[c];
    float bd = md * m2wd[c] + m2bd[c];
    float4 a = *(const float4*)&d2u[e];
    float4 u = *(const float4*)&u2d[e];
    float4 p = *(const float4*)&xu[e];
    float4 q = *(const float4*)&xd[e];
    float4 r;
    r.x = a.x * ru + bu + p.x + u.x * rd + bd + q.x;
    r.y = a.y * ru + bu + p.y + u.y * rd + bd + q.y;
    r.z = a.z * ru + bu + p.z + u.z * rd + bd + q.z;
    r.w = a.w * ru + bu + p.w + u.w * rd + bd + q.w;
    *(float4*)&out[e] = r;
}

// ---------------- launch ----------------
extern "C" void kernel_launch(void* const* d_in, const int* in_sizes, int n_in,
                              void* d_out, int out_size)
{
    const float* x_u  = (const float*)d_in[0];
    const float* x_d  = (const float*)d_in[1];
    const float* nw_u = (const float*)d_in[2];
    const float* nb_u = (const float*)d_in[3];
    const float* m1w_u = (const float*)d_in[4];
    const float* m1b_u = (const float*)d_in[5];
    const float* m2w_u = (const float*)d_in[6];
    const float* m2b_u = (const float*)d_in[7];
    const float* nw_d = (const float*)d_in[8];
    const float* nb_d = (const float*)d_in[9];
    const float* m1w_d = (const float*)d_in[10];
    const float* m1b_d = (const float*)d_in[11];
    const float* m2w_d = (const float*)d_in[12];
    const float* m2b_d = (const float*)d_in[13];
    const float* Wqkv_u = (const float*)d_in[14];
    const float* bqkv_u = (const float*)d_in[15];
    const float* Wqkv_d = (const float*)d_in[16];
    const float* bqkv_d = (const float*)d_in[17];
    const float* scale_h = (const float*)d_in[18];
    const float* scale_w = (const float*)d_in[19];
    const float* scale_c = (const float*)d_in[20];
    float* out = (float*)d_out;

    static bool s_init = false;
    static float *p_qu, *p_qd, *p_du, *p_ud, *p_part, *p_stats, *p_sp, *p_ac, *p_tin, *p_tout;
    if (!s_init) {
        cudaGetSymbolAddress((void**)&p_qu, g_qkv_u);
        cudaGetSymbolAddress((void**)&p_qd, g_qkv_d);
        cudaGetSymbolAddress((void**)&p_du, g_d2u);
        cudaGetSymbolAddress((void**)&p_ud, g_u2d);
        cudaGetSymbolAddress((void**)&p_part, g_part);
        cudaGetSymbolAddress((void**)&p_stats, g_stats);
        cudaGetSymbolAddress((void**)&p_sp, g_spart);
        cudaGetSymbolAddress((void**)&p_ac, g_ac);
        cudaGetSymbolAddress((void**)&p_tin, g_tin);
        cudaGetSymbolAddress((void**)&p_tout, g_tout);
        cudaFuncSetAttribute(k_pconv_tc,  cudaFuncAttributeMaxDynamicSharedMemorySize, (64 * PIT + 128 * PIT) * 4);
        cudaFuncSetAttribute(k_attn_h_tc, cudaFuncAttributeMaxDynamicSharedMemorySize, ASMEM * 4);
        cudaFuncSetAttribute(k_attn_w_tc, cudaFuncAttributeMaxDynamicSharedMemorySize, ASMEM * 4);
        s_init = true;
    }

    k_reduce1<<<dim3(256, NB, 2), 256>>>(x_u, x_d, p_part);
    k_reduce2<<<dim3(NB, 2), 256>>>(p_part, p_stats);

    size_t smemG = (size_t)(64 * PIT + 128 * PIT) * 4;
    k_pconv_tc<<<dim3(128, 3, NB), 256, smemG>>>(x_u, Wqkv_u, bqkv_u, nw_u, nb_u, p_stats,          p_qu);
    k_pconv_tc<<<dim3(128, 3, NB), 256, smemG>>>(x_d, Wqkv_d, bqkv_d, nw_d, nb_d, p_stats + 2 * NB, p_qd);

    // transpose h-attn inputs
    k_tin<<<dim3(16, 32, NB * 4), dim3(32, 8)>>>(p_qu, p_qd, p_tin);

    size_t smemA = (size_t)ASMEM * 4;
    k_attn_h_tc<<<dim3(NWD, NB), 256, smemA>>>(p_tin, scale_h, p_tout);
    k_tout<<<dim3(16, 32, NB * 2), dim3(32, 8)>>>(p_tout, p_du, p_ud);

    k_attn_w_tc<<<dim3(NH, NB), 256, smemA>>>(p_qu, p_qd, scale_w, p_du, p_ud);

    k_cpart<<<dim3(32, NB), 256>>>(p_qu, p_qd, p_sp);
    k_csoft<<<NB, dim3(32, 32)>>>(p_sp, scale_c, p_ac);
    k_capply<<<dim3(HW / 256, NB), 256>>>(p_qu, p_qd, p_ac, p_du, p_ud);

    k_epi<<<(NB * NCH) / (256 * 4), 256>>>(p_du, p_ud, x_u, x_d, p_stats,
                                           m1w_u, m1b_u, m2w_u, m2b_u,
                                           m1w_d, m1b_d, m2w_d, m2b_d, out);
}

// round 5
// speedup vs baseline: 2.0058x; 1.1356x over previous
#include <cuda_runtime.h>
#include <math.h>
#include <stdint.h>

// ---------------- problem constants ----------------
static constexpr int NB   = 8;
static constexpr int NC   = 96;
static constexpr int NH   = 128;
static constexpr int NWD  = 128;
static constexpr int HW   = NH * NWD;   // 16384
static constexpr int NCH  = NC * HW;
static constexpr int C2   = 2 * NC;     // 192

// ---------------- scratch ----------------
__device__ float g_qkv_u[(size_t)NB * C2 * HW];
__device__ float g_qkv_d[(size_t)NB * C2 * HW];
__device__ float g_part [2 * NB * 256 * 2];
__device__ float g_stats[2 * NB * 2];
__device__ float g_spart[(size_t)NB * 32 * 32 * 32];
__device__ float g_ac   [NB * 32 * 32];
__device__ float g_tin  [(size_t)4 * NB * 32 * HW];  // h-attn inputs [t][b][c][w][h]
__device__ float g_tout [(size_t)2 * NB * 32 * HW];  // h-attn outputs [t][b][c][w][h]

// ---------------- K1/K2: mean/var ----------------
__global__ void k_reduce1(const float* __restrict__ xu, const float* __restrict__ xd,
                          float* __restrict__ part)
{
    int chunk = blockIdx.x, b = blockIdx.y, z = blockIdx.z;
    const float* x = (z == 0 ? xu : xd) + (size_t)b * NCH + (size_t)chunk * 6144;
    float s = 0.f, ss = 0.f;
    for (int i = threadIdx.x; i < 6144; i += 256) { float v = x[i]; s += v; ss += v * v; }
    __shared__ float sh[256], sh2[256];
    sh[threadIdx.x] = s; sh2[threadIdx.x] = ss;
    __syncthreads();
    for (int o = 128; o > 0; o >>= 1) {
        if (threadIdx.x < o) { sh[threadIdx.x] += sh[threadIdx.x + o]; sh2[threadIdx.x] += sh2[threadIdx.x + o]; }
        __syncthreads();
    }
    if (threadIdx.x == 0) {
        int o = ((z * NB + b) * 256 + chunk) * 2;
        part[o] = sh[0]; part[o + 1] = sh2[0];
    }
}

__global__ void k_reduce2(const float* __restrict__ part, float* __restrict__ stats)
{
    int b = blockIdx.x, z = blockIdx.y, tid = threadIdx.x;
    __shared__ double sh[256], sh2[256];
    int o = ((z * NB + b) * 256 + tid) * 2;
    sh[tid] = (double)part[o]; sh2[tid] = (double)part[o + 1];
    __syncthreads();
    for (int s = 128; s > 0; s >>= 1) {
        if (tid < s) { sh[tid] += sh[tid + s]; sh2[tid] += sh2[tid + s]; }
        __syncthreads();
    }
    if (tid == 0) {
        double mean = sh[0] / (double)NCH;
        double var  = sh2[0] / (double)NCH - mean * mean;
        stats[(z * NB + b) * 2 + 0] = (float)mean;
        stats[(z * NB + b) * 2 + 1] = sqrtf((float)var + 1e-5f);
    }
}

// ---------------- tf32 helpers ----------------
__device__ __forceinline__ float to_tf32(float v) {
    uint32_t u;
    asm("cvt.rna.tf32.f32 %0, %1;" : "=r"(u) : "f"(v));
    return __uint_as_float(u);
}
__device__ __forceinline__ uint32_t ldu(const float* p) { return __float_as_uint(*p); }

__device__ __forceinline__ void mma_tf32(float* c,
                                         uint32_t a0, uint32_t a1, uint32_t a2, uint32_t a3,
                                         uint32_t b0, uint32_t b1)
{
    asm volatile("mma.sync.aligned.m16n8k8.row.col.f32.tf32.tf32.f32 "
                 "{%0,%1,%2,%3}, {%4,%5,%6,%7}, {%8,%9}, {%0,%1,%2,%3};"
                 : "+f"(c[0]), "+f"(c[1]), "+f"(c[2]), "+f"(c[3])
                 : "r"(a0), "r"(a1), "r"(a2), "r"(a3), "r"(b0), "r"(b1));
}

// ---------------- K3: fused normalize + 1x1 conv GEMM (tf32) ----------------
static constexpr int PIT = 100;

__global__ void k_pconv_tc(const float* __restrict__ x, const float* __restrict__ Wm,
                           const float* __restrict__ bias, const float* __restrict__ nw,
                           const float* __restrict__ nb, const float* __restrict__ stats,
                           float* __restrict__ out)
{
    extern __shared__ float sm[];
    float* sA = sm;
    float* sB = sm + 64 * PIT;
    int b = blockIdx.z, mBase = blockIdx.y * 64, nBase = blockIdx.x * 128;
    int tid = threadIdx.x;
    float mean = stats[b * 2], inv = 1.0f / stats[b * 2 + 1];

    for (int idx = tid; idx < 64 * 96; idx += 256) {
        int m = idx / 96, k = idx - m * 96;
        sA[m * PIT + k] = to_tf32(Wm[(mBase + m) * 96 + k]);
    }
    for (int idx = tid; idx < 96 * 128; idx += 256) {
        int k = idx >> 7, n = idx & 127;
        float v = x[((size_t)b * NC + k) * HW + nBase + n];
        sB[n * PIT + k] = to_tf32((v - mean) * inv * nw[k] + nb[k]);
    }
    __syncthreads();

    int warp = tid >> 5, lane = tid & 31;
    int warpM = warp & 1, warpN = warp >> 1;
    int g = lane >> 2, tg = lane & 3;

    float acc[2][4][4];
#pragma unroll
    for (int mt = 0; mt < 2; mt++)
#pragma unroll
        for (int nt = 0; nt < 4; nt++)
#pragma unroll
            for (int r = 0; r < 4; r++) acc[mt][nt][r] = 0.f;

    const float* pa = sA + (warpM * 32 + g) * PIT + tg;
    const float* pb = sB + (warpN * 32 + g) * PIT + tg;

#pragma unroll
    for (int ks = 0; ks < 12; ks++) {
        int k0 = ks * 8;
        uint32_t a[2][4], bf[4][2];
#pragma unroll
        for (int mt = 0; mt < 2; mt++) {
            const float* p = pa + mt * 16 * PIT + k0;
            a[mt][0] = ldu(p); a[mt][1] = ldu(p + 8 * PIT);
            a[mt][2] = ldu(p + 4); a[mt][3] = ldu(p + 8 * PIT + 4);
        }
#pragma unroll
        for (int nt = 0; nt < 4; nt++) {
            const float* p = pb + nt * 8 * PIT + k0;
            bf[nt][0] = ldu(p); bf[nt][1] = ldu(p + 4);
        }
#pragma unroll
        for (int mt = 0; mt < 2; mt++)
#pragma unroll
            for (int nt = 0; nt < 4; nt++)
                mma_tf32(acc[mt][nt], a[mt][0], a[mt][1], a[mt][2], a[mt][3], bf[nt][0], bf[nt][1]);
    }

#pragma unroll
    for (int mt = 0; mt < 2; mt++) {
        int o0 = mBase + warpM * 32 + mt * 16 + g;
        float bs0 = bias[o0], bs1 = bias[o0 + 8];
        size_t base0 = ((size_t)b * C2 + o0) * HW + nBase + warpN * 32;
        size_t base1 = base0 + (size_t)8 * HW;
#pragma unroll
        for (int nt = 0; nt < 4; nt++) {
            int nc0 = nt * 8 + tg * 2;
            *(float2*)&out[base0 + nc0] = make_float2(acc[mt][nt][0] + bs0, acc[mt][nt][1] + bs0);
            *(float2*)&out[base1 + nc0] = make_float2(acc[mt][nt][2] + bs1, acc[mt][nt][3] + bs1);
        }
    }
}

// ---------------- transpose in (32x32 tiles) ----------------
__global__ void k_tin(const float* __restrict__ qu, const float* __restrict__ qd,
                      float* __restrict__ tin)
{
    __shared__ float sh[32][33];
    int tile = blockIdx.x;
    int wb = (tile & 3) * 32, hb = (tile >> 2) * 32;
    int c = blockIdx.y;
    int z = blockIdx.z, t = z & 3, b = z >> 2;
    int tx = threadIdx.x, ty = threadIdx.y;
    const float* base = (t == 0 || t == 3) ? qu : qd;
    int coff = (t >= 2) ? 96 + c : c;
    const float* src = base + ((size_t)b * C2 + coff) * HW;
#pragma unroll
    for (int r = 0; r < 4; r++)
        sh[ty + 8 * r][tx] = src[(hb + ty + 8 * r) * 128 + wb + tx];
    __syncthreads();
    float* dst = tin + ((size_t)(t * NB + b) * 32 + c) * HW;
#pragma unroll
    for (int r = 0; r < 4; r++)
        dst[(wb + ty + 8 * r) * 128 + hb + tx] = sh[tx][ty + 8 * r];
}

// ---------------- transpose out + fused epilogue (ch 0-31) ----------------
__global__ void k_tout_epi(const float* __restrict__ tout,
                           const float* __restrict__ xu, const float* __restrict__ xd,
                           const float* __restrict__ stats,
                           const float* __restrict__ m1wu, const float* __restrict__ m1bu,
                           const float* __restrict__ m2wu, const float* __restrict__ m2bu,
                           const float* __restrict__ m1wd, const float* __restrict__ m1bd,
                           const float* __restrict__ m2wd, const float* __restrict__ m2bd,
                           float* __restrict__ out)
{
    __shared__ float sh0[32][33], sh1[32][33];
    int tile = blockIdx.x;
    int hb = (tile & 3) * 32, wb = (tile >> 2) * 32;
    int c = blockIdx.y, b = blockIdx.z;
    int tx = threadIdx.x, ty = threadIdx.y;
    const size_t GRPO = (size_t)NB * 32 * HW;
    const float* src0 = tout + ((size_t)b * 32 + c) * HW;          // d2u [w][h]
    const float* src1 = tout + GRPO + ((size_t)b * 32 + c) * HW;   // u2d [w][h]
#pragma unroll
    for (int r = 0; r < 4; r++) {
        sh0[ty + 8 * r][tx] = src0[(wb + ty + 8 * r) * 128 + hb + tx];
        sh1[ty + 8 * r][tx] = src1[(wb + ty + 8 * r) * 128 + hb + tx];
    }
    __syncthreads();
    float mu = stats[b * 2], su = stats[b * 2 + 1];
    float md = stats[2 * NB + b * 2], sd = stats[2 * NB + b * 2 + 1];
    float ru = su * m1wu[c] + m1bu[c], bu = mu * m2wu[c] + m2bu[c];
    float rd = sd * m1wd[c] + m1bd[c], bd = md * m2wd[c] + m2bd[c];
    size_t cb = ((size_t)b * NC + c) * HW;
#pragma unroll
    for (int r = 0; r < 4; r++) {
        size_t e = cb + (size_t)(hb + ty + 8 * r) * 128 + wb + tx;
        out[e] = sh0[tx][ty + 8 * r] * ru + bu + xu[e] + sh1[tx][ty + 8 * r] * rd + bd + xd[e];
    }
}

// ---------------- tensor-core attention (512 threads) ----------------
static constexpr int PS = 132;
static constexpr int PT = 132;
static constexpr int ASMEM = (128 * PS + 2 * 32 * PT);

// height-axis attention on transposed data. CTA = (w, b).
__global__ __launch_bounds__(512, 2)
void k_attn_h_tc(const float* __restrict__ tin, const float* __restrict__ sch,
                 float* __restrict__ tout)
{
    extern __shared__ float sm[];
    float* S  = sm;
    float* T0 = sm + 128 * PS;
    float* T1 = T0 + 32 * PT;
    int w = blockIdx.x, b = blockIdx.y, tid = threadIdx.x;
    int wid = tid >> 5, lane = tid & 31, g = lane >> 2, tg = lane & 3;
    const size_t GRP = (size_t)NB * 32 * HW;
    const float* qp  = tin + (size_t)b * 32 * HW + (size_t)w * 128;
    const float* kp  = qp + GRP;
    const float* vdp = qp + 2 * GRP;
    const float* vup = qp + 3 * GRP;

    for (int idx = tid; idx < 32 * 128; idx += 512) {
        int c = idx >> 7, i = idx & 127;
        T0[c * PT + i] = to_tf32(qp[(size_t)c * HW + i]);
        T1[c * PT + i] = to_tf32(kp[(size_t)c * HW + i]);
    }
    __syncthreads();
    float sc = sch[0];

    int ib = (wid >> 1) * 16;
    int jh = (wid & 1) * 64;
    {
        float acc[8][4];
#pragma unroll
        for (int jt = 0; jt < 8; jt++)
#pragma unroll
            for (int r = 0; r < 4; r++) acc[jt][r] = 0.f;
#pragma unroll
        for (int ks = 0; ks < 4; ks++) {
            int k0 = ks * 8;
            uint32_t a0 = ldu(&T0[(k0 + tg) * PT + ib + g]);
            uint32_t a1 = ldu(&T0[(k0 + tg) * PT + ib + g + 8]);
            uint32_t a2 = ldu(&T0[(k0 + tg + 4) * PT + ib + g]);
            uint32_t a3 = ldu(&T0[(k0 + tg + 4) * PT + ib + g + 8]);
#pragma unroll
            for (int jt = 0; jt < 8; jt++) {
                int jb = jh + jt * 8;
                uint32_t b0 = ldu(&T1[(k0 + tg) * PT + jb + g]);
                uint32_t b1 = ldu(&T1[(k0 + tg + 4) * PT + jb + g]);
                mma_tf32(acc[jt], a0, a1, a2, a3, b0, b1);
            }
        }
#pragma unroll
        for (int jt = 0; jt < 8; jt++) {
            int jb = jh + jt * 8;
            S[(ib + g) * PS + jb + 2 * tg]         = acc[jt][0] * sc;
            S[(ib + g) * PS + jb + 2 * tg + 1]     = acc[jt][1] * sc;
            S[(ib + g + 8) * PS + jb + 2 * tg]     = acc[jt][2] * sc;
            S[(ib + g + 8) * PS + jb + 2 * tg + 1] = acc[jt][3] * sc;
        }
    }
    __syncthreads();

    // row softmax: 8 rows per warp
#pragma unroll 1
    for (int t = 0; t < 8; t++) {
        int r = wid * 8 + t;
        float* row = S + r * PS;
        float v0 = row[lane], v1 = row[lane + 32], v2 = row[lane + 64], v3 = row[lane + 96];
        float m = fmaxf(fmaxf(v0, v1), fmaxf(v2, v3));
#pragma unroll
        for (int o = 16; o > 0; o >>= 1) m = fmaxf(m, __shfl_xor_sync(0xffffffffu, m, o));
        float e0 = __expf(v0 - m), e1 = __expf(v1 - m), e2 = __expf(v2 - m), e3 = __expf(v3 - m);
        float s = e0 + e1 + e2 + e3;
#pragma unroll
        for (int o = 16; o > 0; o >>= 1) s += __shfl_xor_sync(0xffffffffu, s, o);
        float inv = 1.0f / s;
        row[lane] = e0 * inv; row[lane + 32] = e1 * inv; row[lane + 64] = e2 * inv; row[lane + 96] = e3 * inv;
    }
    __syncthreads();

    for (int idx = tid; idx < 32 * 128; idx += 512) {
        int c = idx >> 7, i = idx & 127;
        T0[c * PT + i] = to_tf32(vdp[(size_t)c * HW + i]);
        T1[c * PT + i] = to_tf32(vup[(size_t)c * HW + i]);
    }
    __syncthreads();

    int ch = (wid & 1) * 16;
    float accD[2][4], accU[2][4];
#pragma unroll
    for (int ct = 0; ct < 2; ct++)
#pragma unroll
        for (int r = 0; r < 4; r++) { accD[ct][r] = 0.f; accU[ct][r] = 0.f; }

#pragma unroll 4
    for (int ks = 0; ks < 16; ks++) {
        int k0 = ks * 8;
        uint32_t a0 = ldu(&S[(ib + g) * PS + k0 + tg]);
        uint32_t a1 = ldu(&S[(ib + g + 8) * PS + k0 + tg]);
        uint32_t a2 = ldu(&S[(ib + g) * PS + k0 + tg + 4]);
        uint32_t a3 = ldu(&S[(ib + g + 8) * PS + k0 + tg + 4]);
#pragma unroll
        for (int ct = 0; ct < 2; ct++) {
            int cb = ch + ct * 8;
            uint32_t b0 = ldu(&T0[(cb + g) * PT + k0 + tg]);
            uint32_t b1 = ldu(&T0[(cb + g) * PT + k0 + tg + 4]);
            mma_tf32(accD[ct], a0, a1, a2, a3, b0, b1);
        }
    }
#pragma unroll 4
    for (int ks = 0; ks < 16; ks++) {
        int k0 = ks * 8;
        uint32_t a0 = ldu(&S[(k0 + tg) * PS + ib + g]);
        uint32_t a1 = ldu(&S[(k0 + tg) * PS + ib + g + 8]);
        uint32_t a2 = ldu(&S[(k0 + tg + 4) * PS + ib + g]);
        uint32_t a3 = ldu(&S[(k0 + tg + 4) * PS + ib + g + 8]);
#pragma unroll
        for (int ct = 0; ct < 2; ct++) {
            int cb = ch + ct * 8;
            uint32_t b0 = ldu(&T1[(cb + g) * PT + k0 + tg]);
            uint32_t b1 = ldu(&T1[(cb + g) * PT + k0 + tg + 4]);
            mma_tf32(accU[ct], a0, a1, a2, a3, b0, b1);
        }
    }
    __syncthreads();

#pragma unroll
    for (int ct = 0; ct < 2; ct++) {
        int cb = ch + ct * 8;
        T0[(cb + 2 * tg) * PT + ib + g]         = accD[ct][0];
        T0[(cb + 2 * tg + 1) * PT + ib + g]     = accD[ct][1];
        T0[(cb + 2 * tg) * PT + ib + g + 8]     = accD[ct][2];
        T0[(cb + 2 * tg + 1) * PT + ib + g + 8] = accD[ct][3];
        T1[(cb + 2 * tg) * PT + ib + g]         = accU[ct][0];
        T1[(cb + 2 * tg + 1) * PT + ib + g]     = accU[ct][1];
        T1[(cb + 2 * tg) * PT + ib + g + 8]     = accU[ct][2];
        T1[(cb + 2 * tg + 1) * PT + ib + g + 8] = accU[ct][3];
    }
    __syncthreads();

    const size_t GRPO = (size_t)NB * 32 * HW;
    float* du = tout + (size_t)b * 32 * HW + (size_t)w * 128;
    float* ud = tout + GRPO + (size_t)b * 32 * HW + (size_t)w * 128;
    for (int idx = tid; idx < 32 * 128; idx += 512) {
        int c = idx >> 7, i = idx & 127;
        du[(size_t)c * HW + i] = T0[c * PT + i];
        ud[(size_t)c * HW + i] = T1[c * PT + i];
    }
}

// width-axis attention + fused epilogue (ch 32-63). CTA = (h, b).
__global__ __launch_bounds__(512, 2)
void k_attn_w_tc(const float* __restrict__ qu, const float* __restrict__ qd,
                 const float* __restrict__ scw,
                 const float* __restrict__ xu, const float* __restrict__ xd,
                 const float* __restrict__ stats,
                 const float* __restrict__ m1wu, const float* __restrict__ m1bu,
                 const float* __restrict__ m2wu, const float* __restrict__ m2bu,
                 const float* __restrict__ m1wd, const float* __restrict__ m1bd,
                 const float* __restrict__ m2wd, const float* __restrict__ m2bd,
                 float* __restrict__ out)
{
    extern __shared__ float sm[];
    float* S  = sm;
    float* T0 = sm + 128 * PS;
    float* T1 = T0 + 32 * PT;
    __shared__ float auxm[4][128], auxs[4][128];
    __shared__ float rf[128], gc[128];
    __shared__ float sru[32], sbu[32], srd[32], sbd[32];
    int h = blockIdx.x, b = blockIdx.y, tid = threadIdx.x;
    int wid = tid >> 5, lane = tid & 31, g = lane >> 2, tg = lane & 3;
    const size_t bb = (size_t)b * C2 * HW;
    const size_t ro = (size_t)h * 128;
    const float* qp  = qu + bb + (size_t)32 * HW + ro;
    const float* kp  = qd + bb + (size_t)32 * HW + ro;
    const float* vdp = qd + bb + (size_t)128 * HW + ro;
    const float* vup = qu + bb + (size_t)128 * HW + ro;

    if (tid < 32) {
        int c = 32 + tid;
        float mu = stats[b * 2], su = stats[b * 2 + 1];
        float md = stats[2 * NB + b * 2], sd = stats[2 * NB + b * 2 + 1];
        sru[tid] = su * m1wu[c] + m1bu[c];
        sbu[tid] = mu * m2wu[c] + m2bu[c];
        srd[tid] = sd * m1wd[c] + m1bd[c];
        sbd[tid] = md * m2wd[c] + m2bd[c];
    }

    for (int idx = tid; idx < 32 * 128; idx += 512) {
        int c = idx >> 7, j = idx & 127;
        T0[c * PT + j] = to_tf32(qp[(size_t)c * HW + j]);
        T1[c * PT + j] = to_tf32(kp[(size_t)c * HW + j]);
    }
    __syncthreads();
    float sc = scw[0];

    int ib = (wid >> 1) * 16;
    int jh = (wid & 1) * 64;
    {
        float acc[8][4];
#pragma unroll
        for (int jt = 0; jt < 8; jt++)
#pragma unroll
            for (int r = 0; r < 4; r++) acc[jt][r] = 0.f;
#pragma unroll
        for (int ks = 0; ks < 4; ks++) {
            int k0 = ks * 8;
            uint32_t a0 = ldu(&T0[(k0 + tg) * PT + ib + g]);
            uint32_t a1 = ldu(&T0[(k0 + tg) * PT + ib + g + 8]);
            uint32_t a2 = ldu(&T0[(k0 + tg + 4) * PT + ib + g]);
            uint32_t a3 = ldu(&T0[(k0 + tg + 4) * PT + ib + g + 8]);
#pragma unroll
            for (int jt = 0; jt < 8; jt++) {
                int jb = jh + jt * 8;
                uint32_t b0 = ldu(&T1[(k0 + tg) * PT + jb + g]);
                uint32_t b1 = ldu(&T1[(k0 + tg + 4) * PT + jb + g]);
                mma_tf32(acc[jt], a0, a1, a2, a3, b0, b1);
            }
        }
#pragma unroll
        for (int jt = 0; jt < 8; jt++) {
            int jb = jh + jt * 8;
            S[(ib + g) * PS + jb + 2 * tg]         = acc[jt][0] * sc;
            S[(ib + g) * PS + jb + 2 * tg + 1]     = acc[jt][1] * sc;
            S[(ib + g + 8) * PS + jb + 2 * tg]     = acc[jt][2] * sc;
            S[(ib + g + 8) * PS + jb + 2 * tg + 1] = acc[jt][3] * sc;
        }
    }
    __syncthreads();

    // column stats: gc[j] = exp(-cmax_j)/csum_j  (4 row-groups of 32)
    {
        int cc = tid & 127, q = tid >> 7;
        float m = -1e30f;
        for (int i = q * 32; i < q * 32 + 32; i++) m = fmaxf(m, S[i * PS + cc]);
        auxm[q][cc] = m;
        __syncthreads();
        float M = fmaxf(fmaxf(auxm[0][cc], auxm[1][cc]), fmaxf(auxm[2][cc], auxm[3][cc]));
        float s = 0.f;
        for (int i = q * 32; i < q * 32 + 32; i++) s += __expf(S[i * PS + cc] - M);
        auxs[q][cc] = s;
        __syncthreads();
        if (tid < 128)
            gc[tid] = __expf(-M) / (auxs[0][tid] + auxs[1][tid] + auxs[2][tid] + auxs[3][tid]);
    }
    __syncthreads();

    // row softmax (A1) + rf
#pragma unroll 1
    for (int t = 0; t < 8; t++) {
        int r = wid * 8 + t;
        float* row = S + r * PS;
        float v0 = row[lane], v1 = row[lane + 32], v2 = row[lane + 64], v3 = row[lane + 96];
        float m = fmaxf(fmaxf(v0, v1), fmaxf(v2, v3));
#pragma unroll
        for (int o = 16; o > 0; o >>= 1) m = fmaxf(m, __shfl_xor_sync(0xffffffffu, m, o));
        float e0 = __expf(v0 - m), e1 = __expf(v1 - m), e2 = __expf(v2 - m), e3 = __expf(v3 - m);
        float s = e0 + e1 + e2 + e3;
#pragma unroll
        for (int o = 16; o > 0; o >>= 1) s += __shfl_xor_sync(0xffffffffu, s, o);
        float inv = 1.0f / s;
        row[lane] = e0 * inv; row[lane + 32] = e1 * inv; row[lane + 64] = e2 * inv; row[lane + 96] = e3 * inv;
        if (lane == 0) rf[r] = s * __expf(m);
    }
    __syncthreads();

    for (int idx = tid; idx < 32 * 128; idx += 512) {
        int c = idx >> 7, j = idx & 127;
        T0[c * PT + j] = to_tf32(vdp[(size_t)c * HW + j]);
        T1[c * PT + j] = to_tf32(vup[(size_t)c * HW + j]);
    }
    __syncthreads();

    int ch = (wid & 1) * 16;
    // d2u[c][i] = sum_j A1[i][j] Vd[c][j]
    float accD[2][4];
#pragma unroll
    for (int ct = 0; ct < 2; ct++)
#pragma unroll
        for (int r = 0; r < 4; r++) accD[ct][r] = 0.f;
#pragma unroll 4
    for (int ks = 0; ks < 16; ks++) {
        int k0 = ks * 8;
        uint32_t a0 = ldu(&S[(ib + g) * PS + k0 + tg]);
        uint32_t a1 = ldu(&S[(ib + g + 8) * PS + k0 + tg]);
        uint32_t a2 = ldu(&S[(ib + g) * PS + k0 + tg + 4]);
        uint32_t a3 = ldu(&S[(ib + g + 8) * PS + k0 + tg + 4]);
#pragma unroll
        for (int ct = 0; ct < 2; ct++) {
            int cb = ch + ct * 8;
            uint32_t b0 = ldu(&T0[(cb + g) * PT + k0 + tg]);
            uint32_t b1 = ldu(&T0[(cb + g) * PT + k0 + tg + 4]);
            mma_tf32(accD[ct], a0, a1, a2, a3, b0, b1);
        }
    }
    __syncthreads();

    // A2[i][j] = A1[i][j] * rf[i] * gc[j]
    for (int idx = tid; idx < 128 * 128; idx += 512) {
        int i = idx >> 7, j = idx & 127;
        S[i * PS + j] *= rf[i] * gc[j];
    }
    __syncthreads();

    // u2d[c][j] = sum_i A2[i][j] Vu[c][i]
    float accU[2][4];
#pragma unroll
    for (int ct = 0; ct < 2; ct++)
#pragma unroll
        for (int r = 0; r < 4; r++) accU[ct][r] = 0.f;
#pragma unroll 4
    for (int ks = 0; ks < 16; ks++) {
        int k0 = ks * 8;
        uint32_t a0 = ldu(&S[(k0 + tg) * PS + ib + g]);
        uint32_t a1 = ldu(&S[(k0 + tg) * PS + ib + g + 8]);
        uint32_t a2 = ldu(&S[(k0 + tg + 4) * PS + ib + g]);
        uint32_t a3 = ldu(&S[(k0 + tg + 4) * PS + ib + g + 8]);
#pragma unroll
        for (int ct = 0; ct < 2; ct++) {
            int cb = ch + ct * 8;
            uint32_t b0 = ldu(&T1[(cb + g) * PT + k0 + tg]);
            uint32_t b1 = ldu(&T1[(cb + g) * PT + k0 + tg + 4]);
            mma_tf32(accU[ct], a0, a1, a2, a3, b0, b1);
        }
    }
    __syncthreads();

#pragma unroll
    for (int ct = 0; ct < 2; ct++) {
        int cb = ch + ct * 8;
        T0[(cb + 2 * tg) * PT + ib + g]         = accD[ct][0];
        T0[(cb + 2 * tg + 1) * PT + ib + g]     = accD[ct][1];
        T0[(cb + 2 * tg) * PT + ib + g + 8]     = accD[ct][2];
        T0[(cb + 2 * tg + 1) * PT + ib + g + 8] = accD[ct][3];
        T1[(cb + 2 * tg) * PT + ib + g]         = accU[ct][0];
        T1[(cb + 2 * tg + 1) * PT + ib + g]     = accU[ct][1];
        T1[(cb + 2 * tg) * PT + ib + g + 8]     = accU[ct][2];
        T1[(cb + 2 * tg + 1) * PT + ib + g + 8] = accU[ct][3];
    }
    __syncthreads();

    // fused epilogue write for ch 32..63
    const size_t xb = (size_t)b * NCH + (size_t)32 * HW + ro;
    for (int idx = tid; idx < 32 * 128; idx += 512) {
        int c = idx >> 7, j = idx & 127;
        size_t e = xb + (size_t)c * HW + j;
        out[e] = T0[c * PT + j] * sru[c] + sbu[c] + xu[e]
               + T1[c * PT + j] * srd[c] + sbd[c] + xd[e];
    }
}

// ---------------- channel attention ----------------
__global__ void k_cpart(const float* __restrict__ qu, const float* __restrict__ qd,
                        float* __restrict__ spart)
{
    __shared__ float qs[32 * 129], ks[32 * 129];
    int chunk = blockIdx.x, b = blockIdx.y, tid = threadIdx.x;
    const size_t bb = (size_t)b * C2 * HW;
    int c0 = (tid >> 5) * 4, d = tid & 31;
    float acc[4] = {0.f, 0.f, 0.f, 0.f};
    for (int sub = 0; sub < 4; sub++) {
        int n0 = chunk * 512 + sub * 128;
        for (int idx = tid; idx < 32 * 128; idx += 256) {
            int c = idx >> 7, t = idx & 127;
            qs[c * 129 + t] = qu[bb + (size_t)(64 + c) * HW + n0 + t];
            ks[c * 129 + t] = qd[bb + (size_t)(64 + c) * HW + n0 + t];
        }
        __syncthreads();
        for (int t = 0; t < 128; t++) {
            float kv = ks[d * 129 + t];
#pragma unroll
            for (int cc = 0; cc < 4; cc++) acc[cc] = fmaf(qs[(c0 + cc) * 129 + t], kv, acc[cc]);
        }
        __syncthreads();
    }
#pragma unroll
    for (int cc = 0; cc < 4; cc++)
        spart[(((size_t)b * 32 + chunk) * 32 + c0 + cc) * 32 + d] = acc[cc];
}

__global__ void k_csoft(const float* __restrict__ spart, const float* __restrict__ scc,
                        float* __restrict__ ac)
{
    int b = blockIdx.x, d = threadIdx.x, c = threadIdx.y;
    float s = 0.f;
    for (int ch = 0; ch < 32; ch++)
        s += spart[(((size_t)b * 32 + ch) * 32 + c) * 32 + d];
    s *= scc[0];
    float m = s;
#pragma unroll
    for (int o = 16; o > 0; o >>= 1) m = fmaxf(m, __shfl_xor_sync(0xffffffffu, m, o));
    float e = __expf(s - m);
    float sum = e;
#pragma unroll
    for (int o = 16; o > 0; o >>= 1) sum += __shfl_xor_sync(0xffffffffu, sum, o);
    ac[((size_t)b * 32 + c) * 32 + d] = e / sum;
}

// channel apply + fused epilogue (ch 64-95)
__global__ void k_capply_epi(const float* __restrict__ qu, const float* __restrict__ qd,
                             const float* __restrict__ ac,
                             const float* __restrict__ xu, const float* __restrict__ xd,
                             const float* __restrict__ stats,
                             const float* __restrict__ m1wu, const float* __restrict__ m1bu,
                             const float* __restrict__ m2wu, const float* __restrict__ m2bu,
                             const float* __restrict__ m1wd, const float* __restrict__ m1bd,
                             const float* __restrict__ m2wd, const float* __restrict__ m2bd,
                             float* __restrict__ out)
{
    __shared__ float A[1024];
    __shared__ float sru[32], sbu[32], srd[32], sbd[32];
    int b = blockIdx.y, tid = threadIdx.x;
    int n = blockIdx.x * 256 + tid;
    for (int i = tid; i < 1024; i += 256) A[i] = ac[(size_t)b * 1024 + i];
    if (tid < 32) {
        int c = 64 + tid;
        float mu = stats[b * 2], su = stats[b * 2 + 1];
        float md = stats[2 * NB + b * 2], sd = stats[2 * NB + b * 2 + 1];
        sru[tid] = su * m1wu[c] + m1bu[c];
        sbu[tid] = mu * m2wu[c] + m2bu[c];
        srd[tid] = sd * m1wd[c] + m1bd[c];
        sbd[tid] = md * m2wd[c] + m2bd[c];
    }
    __syncthreads();
    const size_t bb = (size_t)b * C2 * HW;
    const size_t xb = (size_t)b * NCH;
    float vd[32], vu[32];
#pragma unroll
    for (int d = 0; d < 32; d++) {
        vd[d] = qd[bb + (size_t)(160 + d) * HW + n];
        vu[d] = qu[bb + (size_t)(160 + d) * HW + n];
    }
#pragma unroll
    for (int c = 0; c < 32; c++) {
        float ad = 0.f, au = 0.f;
#pragma unroll
        for (int d = 0; d < 32; d++) {
            float a = A[c * 32 + d];
            ad = fmaf(a, vd[d], ad);
            au = fmaf(a, vu[d], au);
        }
        size_t e = xb + (size_t)(64 + c) * HW + n;
        out[e] = ad * sru[c] + sbu[c] + xu[e] + au * srd[c] + sbd[c] + xd[e];
    }
}

// ---------------- launch ----------------
extern "C" void kernel_launch(void* const* d_in, const int* in_sizes, int n_in,
                              void* d_out, int out_size)
{
    const float* x_u  = (const float*)d_in[0];
    const float* x_d  = (const float*)d_in[1];
    const float* nw_u = (const float*)d_in[2];
    const float* nb_u = (const float*)d_in[3];
    const float* m1w_u = (const float*)d_in[4];
    const float* m1b_u = (const float*)d_in[5];
    const float* m2w_u = (const float*)d_in[6];
    const float* m2b_u = (const float*)d_in[7];
    const float* nw_d = (const float*)d_in[8];
    const float* nb_d = (const float*)d_in[9];
    const float* m1w_d = (const float*)d_in[10];
    const float* m1b_d = (const float*)d_in[11];
    const float* m2w_d = (const float*)d_in[12];
    const float* m2b_d = (const float*)d_in[13];
    const float* Wqkv_u = (const float*)d_in[14];
    const float* bqkv_u = (const float*)d_in[15];
    const float* Wqkv_d = (const float*)d_in[16];
    const float* bqkv_d = (const float*)d_in[17];
    const float* scale_h = (const float*)d_in[18];
    const float* scale_w = (const float*)d_in[19];
    const float* scale_c = (const float*)d_in[20];
    float* out = (float*)d_out;

    static bool s_init = false;
    static float *p_qu, *p_qd, *p_part, *p_stats, *p_sp, *p_ac, *p_tin, *p_tout;
    if (!s_init) {
        cudaGetSymbolAddress((void**)&p_qu, g_qkv_u);
        cudaGetSymbolAddress((void**)&p_qd, g_qkv_d);
        cudaGetSymbolAddress((void**)&p_part, g_part);
        cudaGetSymbolAddress((void**)&p_stats, g_stats);
        cudaGetSymbolAddress((void**)&p_sp, g_spart);
        cudaGetSymbolAddress((void**)&p_ac, g_ac);
        cudaGetSymbolAddress((void**)&p_tin, g_tin);
        cudaGetSymbolAddress((void**)&p_tout, g_tout);
        cudaFuncSetAttribute(k_pconv_tc,  cudaFuncAttributeMaxDynamicSharedMemorySize, (64 * PIT + 128 * PIT) * 4);
        cudaFuncSetAttribute(k_attn_h_tc, cudaFuncAttributeMaxDynamicSharedMemorySize, ASMEM * 4);
        cudaFuncSetAttribute(k_attn_w_tc, cudaFuncAttributeMaxDynamicSharedMemorySize, ASMEM * 4);
        s_init = true;
    }

    k_reduce1<<<dim3(256, NB, 2), 256>>>(x_u, x_d, p_part);
    k_reduce2<<<dim3(NB, 2), 256>>>(p_part, p_stats);

    size_t smemG = (size_t)(64 * PIT + 128 * PIT) * 4;
    k_pconv_tc<<<dim3(128, 3, NB), 256, smemG>>>(x_u, Wqkv_u, bqkv_u, nw_u, nb_u, p_stats,          p_qu);
    k_pconv_tc<<<dim3(128, 3, NB), 256, smemG>>>(x_d, Wqkv_d, bqkv_d, nw_d, nb_d, p_stats + 2 * NB, p_qd);

    k_tin<<<dim3(16, 32, NB * 4), dim3(32, 8)>>>(p_qu, p_qd, p_tin);

    size_t smemA = (size_t)ASMEM * 4;
    k_attn_h_tc<<<dim3(NWD, NB), 512, smemA>>>(p_tin, scale_h, p_tout);
    k_tout_epi<<<dim3(16, 32, NB), dim3(32, 8)>>>(p_tout, x_u, x_d, p_stats,
                                                  m1w_u, m1b_u, m2w_u, m2b_u,
                                                  m1w_d, m1b_d, m2w_d, m2b_d, out);

    k_attn_w_tc<<<dim3(NH, NB), 512, smemA>>>(p_qu, p_qd, scale_w, x_u, x_d, p_stats,
                                              m1w_u, m1b_u, m2w_u, m2b_u,
                                              m1w_d, m1b_d, m2w_d, m2b_d, out);

    k_cpart<<<dim3(32, NB), 256>>>(p_qu, p_qd, p_sp);
    k_csoft<<<NB, dim3(32, 32)>>>(p_sp, scale_c, p_ac);
    k_capply_epi<<<dim3(HW / 256, NB), 256>>>(p_qu, p_qd, p_ac, x_u, x_d, p_stats,
                                              m1w_u, m1b_u, m2w_u, m2b_u,
                                              m1w_d, m1b_d, m2w_d, m2b_d, out);
}

// round 6
// speedup vs baseline: 2.1074x; 1.0507x over previous
#include <cuda_runtime.h>
#include <math.h>
#include <stdint.h>

// ---------------- problem constants ----------------
static constexpr int NB   = 8;
static constexpr int NC   = 96;
static constexpr int NH   = 128;
static constexpr int NWD  = 128;
static constexpr int HW   = NH * NWD;   // 16384
static constexpr int NCH  = NC * HW;
static constexpr int C2   = 2 * NC;     // 192

// ---------------- scratch ----------------
__device__ float g_qkv_u[(size_t)NB * C2 * HW];
__device__ float g_qkv_d[(size_t)NB * C2 * HW];
__device__ float g_part [2 * NB * 256 * 2];
__device__ float g_stats[2 * NB * 2];
__device__ float g_spart[(size_t)NB * 32 * 32 * 32];
__device__ float g_ac   [NB * 32 * 32];
__device__ float g_tin  [(size_t)4 * NB * 32 * HW];  // h-attn inputs [t][b][c][w][h]
__device__ float g_tout [(size_t)2 * NB * 32 * HW];  // h-attn outputs [t][b][c][w][h]

// ---------------- K1/K2: mean/var ----------------
__global__ void k_reduce1(const float* __restrict__ xu, const float* __restrict__ xd,
                          float* __restrict__ part)
{
    int chunk = blockIdx.x, b = blockIdx.y, z = blockIdx.z;
    const float4* x = (const float4*)((z == 0 ? xu : xd) + (size_t)b * NCH + (size_t)chunk * 6144);
    float s = 0.f, ss = 0.f;
    for (int i = threadIdx.x; i < 1536; i += 256) {
        float4 v = x[i];
        s += v.x + v.y + v.z + v.w;
        ss += v.x * v.x + v.y * v.y + v.z * v.z + v.w * v.w;
    }
    __shared__ float sh[256], sh2[256];
    sh[threadIdx.x] = s; sh2[threadIdx.x] = ss;
    __syncthreads();
    for (int o = 128; o > 0; o >>= 1) {
        if (threadIdx.x < o) { sh[threadIdx.x] += sh[threadIdx.x + o]; sh2[threadIdx.x] += sh2[threadIdx.x + o]; }
        __syncthreads();
    }
    if (threadIdx.x == 0) {
        int o = ((z * NB + b) * 256 + chunk) * 2;
        part[o] = sh[0]; part[o + 1] = sh2[0];
    }
}

__global__ void k_reduce2(const float* __restrict__ part, float* __restrict__ stats)
{
    int b = blockIdx.x, z = blockIdx.y, tid = threadIdx.x;
    __shared__ double sh[256], sh2[256];
    int o = ((z * NB + b) * 256 + tid) * 2;
    sh[tid] = (double)part[o]; sh2[tid] = (double)part[o + 1];
    __syncthreads();
    for (int s = 128; s > 0; s >>= 1) {
        if (tid < s) { sh[tid] += sh[tid + s]; sh2[tid] += sh2[tid + s]; }
        __syncthreads();
    }
    if (tid == 0) {
        double mean = sh[0] / (double)NCH;
        double var  = sh2[0] / (double)NCH - mean * mean;
        stats[(z * NB + b) * 2 + 0] = (float)mean;
        stats[(z * NB + b) * 2 + 1] = sqrtf((float)var + 1e-5f);
    }
}

// ---------------- tf32 helpers ----------------
__device__ __forceinline__ float to_tf32(float v) {
    uint32_t u;
    asm("cvt.rna.tf32.f32 %0, %1;" : "=r"(u) : "f"(v));
    return __uint_as_float(u);
}
__device__ __forceinline__ uint32_t ldu(const float* p) { return __float_as_uint(*p); }
__device__ __forceinline__ uint32_t ntf(float v, float s, float o) {
    uint32_t u;
    float t = fmaf(v, s, o);
    asm("cvt.rna.tf32.f32 %0, %1;" : "=r"(u) : "f"(t));
    return u;
}

__device__ __forceinline__ void mma_tf32(float* c,
                                         uint32_t a0, uint32_t a1, uint32_t a2, uint32_t a3,
                                         uint32_t b0, uint32_t b1)
{
    asm volatile("mma.sync.aligned.m16n8k8.row.col.f32.tf32.tf32.f32 "
                 "{%0,%1,%2,%3}, {%4,%5,%6,%7}, {%8,%9}, {%0,%1,%2,%3};"
                 : "+f"(c[0]), "+f"(c[1]), "+f"(c[2]), "+f"(c[3])
                 : "r"(a0), "r"(a1), "r"(a2), "r"(a3), "r"(b0), "r"(b1));
}

// ---------------- K3: fused normalize + 1x1 conv GEMM (tf32, no B staging) ----------------
static constexpr int PIT = 100;

__global__ __launch_bounds__(256)
void k_pconv_tc(const float* __restrict__ x, const float* __restrict__ Wm,
                const float* __restrict__ bias, const float* __restrict__ nw,
                const float* __restrict__ nb, const float* __restrict__ stats,
                float* __restrict__ out)
{
    __shared__ float sA[64 * PIT];
    __shared__ float sSc[96], sOf[96];
    int b = blockIdx.z, mBase = blockIdx.y * 64, nBase = blockIdx.x * 128;
    int tid = threadIdx.x;
    float mean = stats[b * 2], inv = 1.0f / stats[b * 2 + 1];

    for (int idx = tid; idx < 64 * 96; idx += 256) {
        int m = idx / 96, k = idx - m * 96;
        sA[m * PIT + k] = to_tf32(Wm[(mBase + m) * 96 + k]);
    }
    if (tid < 96) {
        float s = inv * nw[tid];
        sSc[tid] = s;
        sOf[tid] = fmaf(-mean, s, nb[tid]);
    }
    __syncthreads();

    int warp = tid >> 5, lane = tid & 31;
    int warpM = warp & 1, warpN = warp >> 1;
    int g = lane >> 2, tg = lane & 3;

    float acc[2][4][4];
#pragma unroll
    for (int mt = 0; mt < 2; mt++)
#pragma unroll
        for (int nt = 0; nt < 4; nt++)
#pragma unroll
            for (int r = 0; r < 4; r++) acc[mt][nt][r] = 0.f;

    const float* pa = sA + (warpM * 32 + g) * PIT + tg;
    const float* px = x + (size_t)b * NC * HW + nBase + warpN * 32 + g;

#pragma unroll
    for (int ks = 0; ks < 12; ks++) {
        int k0 = ks * 8;
        // A fragments from shared (conflict-free: pitch%32==4)
        uint32_t a[2][4];
#pragma unroll
        for (int mt = 0; mt < 2; mt++) {
            const float* p = pa + mt * 16 * PIT + k0;
            a[mt][0] = ldu(p); a[mt][1] = ldu(p + 8 * PIT);
            a[mt][2] = ldu(p + 4); a[mt][3] = ldu(p + 8 * PIT + 4);
        }
        // B fragments straight from gmem with fused normalization
        float s0 = sSc[k0 + tg], o0 = sOf[k0 + tg];
        float s1 = sSc[k0 + tg + 4], o1 = sOf[k0 + tg + 4];
        const float* q0 = px + (size_t)(k0 + tg) * HW;
        const float* q1 = px + (size_t)(k0 + tg + 4) * HW;
        uint32_t bf[4][2];
#pragma unroll
        for (int nt = 0; nt < 4; nt++) {
            bf[nt][0] = ntf(q0[nt * 8], s0, o0);
            bf[nt][1] = ntf(q1[nt * 8], s1, o1);
        }
#pragma unroll
        for (int mt = 0; mt < 2; mt++)
#pragma unroll
            for (int nt = 0; nt < 4; nt++)
                mma_tf32(acc[mt][nt], a[mt][0], a[mt][1], a[mt][2], a[mt][3], bf[nt][0], bf[nt][1]);
    }

#pragma unroll
    for (int mt = 0; mt < 2; mt++) {
        int o0 = mBase + warpM * 32 + mt * 16 + g;
        float bs0 = bias[o0], bs1 = bias[o0 + 8];
        size_t base0 = ((size_t)b * C2 + o0) * HW + nBase + warpN * 32;
        size_t base1 = base0 + (size_t)8 * HW;
#pragma unroll
        for (int nt = 0; nt < 4; nt++) {
            int nc0 = nt * 8 + tg * 2;
            *(float2*)&out[base0 + nc0] = make_float2(acc[mt][nt][0] + bs0, acc[mt][nt][1] + bs0);
            *(float2*)&out[base1 + nc0] = make_float2(acc[mt][nt][2] + bs1, acc[mt][nt][3] + bs1);
        }
    }
}

// ---------------- transpose in (32x32 tiles) ----------------
__global__ void k_tin(const float* __restrict__ qu, const float* __restrict__ qd,
                      float* __restrict__ tin)
{
    __shared__ float sh[32][33];
    int tile = blockIdx.x;
    int wb = (tile & 3) * 32, hb = (tile >> 2) * 32;
    int c = blockIdx.y;
    int z = blockIdx.z, t = z & 3, b = z >> 2;
    int tx = threadIdx.x, ty = threadIdx.y;
    const float* base = (t == 0 || t == 3) ? qu : qd;
    int coff = (t >= 2) ? 96 + c : c;
    const float* src = base + ((size_t)b * C2 + coff) * HW;
#pragma unroll
    for (int r = 0; r < 4; r++)
        sh[ty + 8 * r][tx] = src[(hb + ty + 8 * r) * 128 + wb + tx];
    __syncthreads();
    float* dst = tin + ((size_t)(t * NB + b) * 32 + c) * HW;
#pragma unroll
    for (int r = 0; r < 4; r++)
        dst[(wb + ty + 8 * r) * 128 + hb + tx] = sh[tx][ty + 8 * r];
}

// ---------------- transpose out + fused epilogue (ch 0-31) ----------------
__global__ void k_tout_epi(const float* __restrict__ tout,
                           const float* __restrict__ xu, const float* __restrict__ xd,
                           const float* __restrict__ stats,
                           const float* __restrict__ m1wu, const float* __restrict__ m1bu,
                           const float* __restrict__ m2wu, const float* __restrict__ m2bu,
                           const float* __restrict__ m1wd, const float* __restrict__ m1bd,
                           const float* __restrict__ m2wd, const float* __restrict__ m2bd,
                           float* __restrict__ out)
{
    __shared__ float sh0[32][33], sh1[32][33];
    int tile = blockIdx.x;
    int hb = (tile & 3) * 32, wb = (tile >> 2) * 32;
    int c = blockIdx.y, b = blockIdx.z;
    int tx = threadIdx.x, ty = threadIdx.y;
    const size_t GRPO = (size_t)NB * 32 * HW;
    const float* src0 = tout + ((size_t)b * 32 + c) * HW;
    const float* src1 = tout + GRPO + ((size_t)b * 32 + c) * HW;
#pragma unroll
    for (int r = 0; r < 4; r++) {
        sh0[ty + 8 * r][tx] = src0[(wb + ty + 8 * r) * 128 + hb + tx];
        sh1[ty + 8 * r][tx] = src1[(wb + ty + 8 * r) * 128 + hb + tx];
    }
    __syncthreads();
    float mu = stats[b * 2], su = stats[b * 2 + 1];
    float md = stats[2 * NB + b * 2], sd = stats[2 * NB + b * 2 + 1];
    float ru = su * m1wu[c] + m1bu[c], bu = mu * m2wu[c] + m2bu[c];
    float rd = sd * m1wd[c] + m1bd[c], bd = md * m2wd[c] + m2bd[c];
    size_t cb = ((size_t)b * NC + c) * HW;
#pragma unroll
    for (int r = 0; r < 4; r++) {
        size_t e = cb + (size_t)(hb + ty + 8 * r) * 128 + wb + tx;
        out[e] = sh0[tx][ty + 8 * r] * ru + bu + xu[e] + sh1[tx][ty + 8 * r] * rd + bd + xd[e];
    }
}

// ---------------- tensor-core attention (512 threads) ----------------
static constexpr int PS = 132;
static constexpr int PT = 132;
static constexpr int ASMEM = (128 * PS + 2 * 32 * PT);

// height-axis attention on transposed data. CTA = (w, b).
__global__ __launch_bounds__(512, 2)
void k_attn_h_tc(const float* __restrict__ tin, const float* __restrict__ sch,
                 float* __restrict__ tout)
{
    extern __shared__ float sm[];
    float* S  = sm;
    float* T0 = sm + 128 * PS;
    float* T1 = T0 + 32 * PT;
    int w = blockIdx.x, b = blockIdx.y, tid = threadIdx.x;
    int wid = tid >> 5, lane = tid & 31, g = lane >> 2, tg = lane & 3;
    const size_t GRP = (size_t)NB * 32 * HW;
    const float* qp  = tin + (size_t)b * 32 * HW + (size_t)w * 128;
    const float* kp  = qp + GRP;
    const float* vdp = qp + 2 * GRP;
    const float* vup = qp + 3 * GRP;

    for (int idx = tid; idx < 32 * 128; idx += 512) {
        int c = idx >> 7, i = idx & 127;
        T0[c * PT + i] = to_tf32(qp[(size_t)c * HW + i]);
        T1[c * PT + i] = to_tf32(kp[(size_t)c * HW + i]);
    }
    __syncthreads();
    float sc = sch[0];

    int ib = (wid >> 1) * 16;
    int jh = (wid & 1) * 64;
    {
        float acc[8][4];
#pragma unroll
        for (int jt = 0; jt < 8; jt++)
#pragma unroll
            for (int r = 0; r < 4; r++) acc[jt][r] = 0.f;
#pragma unroll
        for (int ks = 0; ks < 4; ks++) {
            int k0 = ks * 8;
            uint32_t a0 = ldu(&T0[(k0 + tg) * PT + ib + g]);
            uint32_t a1 = ldu(&T0[(k0 + tg) * PT + ib + g + 8]);
            uint32_t a2 = ldu(&T0[(k0 + tg + 4) * PT + ib + g]);
            uint32_t a3 = ldu(&T0[(k0 + tg + 4) * PT + ib + g + 8]);
#pragma unroll
            for (int jt = 0; jt < 8; jt++) {
                int jb = jh + jt * 8;
                uint32_t b0 = ldu(&T1[(k0 + tg) * PT + jb + g]);
                uint32_t b1 = ldu(&T1[(k0 + tg + 4) * PT + jb + g]);
                mma_tf32(acc[jt], a0, a1, a2, a3, b0, b1);
            }
        }
#pragma unroll
        for (int jt = 0; jt < 8; jt++) {
            int jb = jh + jt * 8;
            S[(ib + g) * PS + jb + 2 * tg]         = acc[jt][0] * sc;
            S[(ib + g) * PS + jb + 2 * tg + 1]     = acc[jt][1] * sc;
            S[(ib + g + 8) * PS + jb + 2 * tg]     = acc[jt][2] * sc;
            S[(ib + g + 8) * PS + jb + 2 * tg + 1] = acc[jt][3] * sc;
        }
    }
    __syncthreads();

#pragma unroll 1
    for (int t = 0; t < 8; t++) {
        int r = wid * 8 + t;
        float* row = S + r * PS;
        float v0 = row[lane], v1 = row[lane + 32], v2 = row[lane + 64], v3 = row[lane + 96];
        float m = fmaxf(fmaxf(v0, v1), fmaxf(v2, v3));
#pragma unroll
        for (int o = 16; o > 0; o >>= 1) m = fmaxf(m, __shfl_xor_sync(0xffffffffu, m, o));
        float e0 = __expf(v0 - m), e1 = __expf(v1 - m), e2 = __expf(v2 - m), e3 = __expf(v3 - m);
        float s = e0 + e1 + e2 + e3;
#pragma unroll
        for (int o = 16; o > 0; o >>= 1) s += __shfl_xor_sync(0xffffffffu, s, o);
        float inv = 1.0f / s;
        row[lane] = e0 * inv; row[lane + 32] = e1 * inv; row[lane + 64] = e2 * inv; row[lane + 96] = e3 * inv;
    }
    __syncthreads();

    for (int idx = tid; idx < 32 * 128; idx += 512) {
        int c = idx >> 7, i = idx & 127;
        T0[c * PT + i] = to_tf32(vdp[(size_t)c * HW + i]);
        T1[c * PT + i] = to_tf32(vup[(size_t)c * HW + i]);
    }
    __syncthreads();

    int ch = (wid & 1) * 16;
    float accD[2][4], accU[2][4];
#pragma unroll
    for (int ct = 0; ct < 2; ct++)
#pragma unroll
        for (int r = 0; r < 4; r++) { accD[ct][r] = 0.f; accU[ct][r] = 0.f; }

#pragma unroll 4
    for (int ks = 0; ks < 16; ks++) {
        int k0 = ks * 8;
        uint32_t a0 = ldu(&S[(ib + g) * PS + k0 + tg]);
        uint32_t a1 = ldu(&S[(ib + g + 8) * PS + k0 + tg]);
        uint32_t a2 = ldu(&S[(ib + g) * PS + k0 + tg + 4]);
        uint32_t a3 = ldu(&S[(ib + g + 8) * PS + k0 + tg + 4]);
#pragma unroll
        for (int ct = 0; ct < 2; ct++) {
            int cb = ch + ct * 8;
            uint32_t b0 = ldu(&T0[(cb + g) * PT + k0 + tg]);
            uint32_t b1 = ldu(&T0[(cb + g) * PT + k0 + tg + 4]);
            mma_tf32(accD[ct], a0, a1, a2, a3, b0, b1);
        }
    }
#pragma unroll 4
    for (int ks = 0; ks < 16; ks++) {
        int k0 = ks * 8;
        uint32_t a0 = ldu(&S[(k0 + tg) * PS + ib + g]);
        uint32_t a1 = ldu(&S[(k0 + tg) * PS + ib + g + 8]);
        uint32_t a2 = ldu(&S[(k0 + tg + 4) * PS + ib + g]);
        uint32_t a3 = ldu(&S[(k0 + tg + 4) * PS + ib + g + 8]);
#pragma unroll
        for (int ct = 0; ct < 2; ct++) {
            int cb = ch + ct * 8;
            uint32_t b0 = ldu(&T1[(cb + g) * PT + k0 + tg]);
            uint32_t b1 = ldu(&T1[(cb + g) * PT + k0 + tg + 4]);
            mma_tf32(accU[ct], a0, a1, a2, a3, b0, b1);
        }
    }
    __syncthreads();

#pragma unroll
    for (int ct = 0; ct < 2; ct++) {
        int cb = ch + ct * 8;
        T0[(cb + 2 * tg) * PT + ib + g]         = accD[ct][0];
        T0[(cb + 2 * tg + 1) * PT + ib + g]     = accD[ct][1];
        T0[(cb + 2 * tg) * PT + ib + g + 8]     = accD[ct][2];
        T0[(cb + 2 * tg + 1) * PT + ib + g + 8] = accD[ct][3];
        T1[(cb + 2 * tg) * PT + ib + g]         = accU[ct][0];
        T1[(cb + 2 * tg + 1) * PT + ib + g]     = accU[ct][1];
        T1[(cb + 2 * tg) * PT + ib + g + 8]     = accU[ct][2];
        T1[(cb + 2 * tg + 1) * PT + ib + g + 8] = accU[ct][3];
    }
    __syncthreads();

    const size_t GRPO = (size_t)NB * 32 * HW;
    float* du = tout + (size_t)b * 32 * HW + (size_t)w * 128;
    float* ud = tout + GRPO + (size_t)b * 32 * HW + (size_t)w * 128;
    for (int idx = tid; idx < 32 * 128; idx += 512) {
        int c = idx >> 7, i = idx & 127;
        du[(size_t)c * HW + i] = T0[c * PT + i];
        ud[(size_t)c * HW + i] = T1[c * PT + i];
    }
}

// width-axis attention + fused epilogue (ch 32-63). CTA = (h, b).
__global__ __launch_bounds__(512, 2)
void k_attn_w_tc(const float* __restrict__ qu, const float* __restrict__ qd,
                 const float* __restrict__ scw,
                 const float* __restrict__ xu, const float* __restrict__ xd,
                 const float* __restrict__ stats,
                 const float* __restrict__ m1wu, const float* __restrict__ m1bu,
                 const float* __restrict__ m2wu, const float* __restrict__ m2bu,
                 const float* __restrict__ m1wd, const float* __restrict__ m1bd,
                 const float* __restrict__ m2wd, const float* __restrict__ m2bd,
                 float* __restrict__ out)
{
    extern __shared__ float sm[];
    float* S  = sm;
    float* T0 = sm + 128 * PS;
    float* T1 = T0 + 32 * PT;
    __shared__ float auxm[4][128], auxs[4][128];
    __shared__ float rf[128], gc[128];
    __shared__ float sru[32], sbu[32], srd[32], sbd[32];
    int h = blockIdx.x, b = blockIdx.y, tid = threadIdx.x;
    int wid = tid >> 5, lane = tid & 31, g = lane >> 2, tg = lane & 3;
    const size_t bb = (size_t)b * C2 * HW;
    const size_t ro = (size_t)h * 128;
    const float* qp  = qu + bb + (size_t)32 * HW + ro;
    const float* kp  = qd + bb + (size_t)32 * HW + ro;
    const float* vdp = qd + bb + (size_t)128 * HW + ro;
    const float* vup = qu + bb + (size_t)128 * HW + ro;

    if (tid < 32) {
        int c = 32 + tid;
        float mu = stats[b * 2], su = stats[b * 2 + 1];
        float md = stats[2 * NB + b * 2], sd = stats[2 * NB + b * 2 + 1];
        sru[tid] = su * m1wu[c] + m1bu[c];
        sbu[tid] = mu * m2wu[c] + m2bu[c];
        srd[tid] = sd * m1wd[c] + m1bd[c];
        sbd[tid] = md * m2wd[c] + m2bd[c];
    }

    for (int idx = tid; idx < 32 * 128; idx += 512) {
        int c = idx >> 7, j = idx & 127;
        T0[c * PT + j] = to_tf32(qp[(size_t)c * HW + j]);
        T1[c * PT + j] = to_tf32(kp[(size_t)c * HW + j]);
    }
    __syncthreads();
    float sc = scw[0];

    int ib = (wid >> 1) * 16;
    int jh = (wid & 1) * 64;
    {
        float acc[8][4];
#pragma unroll
        for (int jt = 0; jt < 8; jt++)
#pragma unroll
            for (int r = 0; r < 4; r++) acc[jt][r] = 0.f;
#pragma unroll
        for (int ks = 0; ks < 4; ks++) {
            int k0 = ks * 8;
            uint32_t a0 = ldu(&T0[(k0 + tg) * PT + ib + g]);
            uint32_t a1 = ldu(&T0[(k0 + tg) * PT + ib + g + 8]);
            uint32_t a2 = ldu(&T0[(k0 + tg + 4) * PT + ib + g]);
            uint32_t a3 = ldu(&T0[(k0 + tg + 4) * PT + ib + g + 8]);
#pragma unroll
            for (int jt = 0; jt < 8; jt++) {
                int jb = jh + jt * 8;
                uint32_t b0 = ldu(&T1[(k0 + tg) * PT + jb + g]);
                uint32_t b1 = ldu(&T1[(k0 + tg + 4) * PT + jb + g]);
                mma_tf32(acc[jt], a0, a1, a2, a3, b0, b1);
            }
        }
#pragma unroll
        for (int jt = 0; jt < 8; jt++) {
            int jb = jh + jt * 8;
            S[(ib + g) * PS + jb + 2 * tg]         = acc[jt][0] * sc;
            S[(ib + g) * PS + jb + 2 * tg + 1]     = acc[jt][1] * sc;
            S[(ib + g + 8) * PS + jb + 2 * tg]     = acc[jt][2] * sc;
            S[(ib + g + 8) * PS + jb + 2 * tg + 1] = acc[jt][3] * sc;
        }
    }
    __syncthreads();

    {
        int cc = tid & 127, q = tid >> 7;
        float m = -1e30f;
        for (int i = q * 32; i < q * 32 + 32; i++) m = fmaxf(m, S[i * PS + cc]);
        auxm[q][cc] = m;
        __syncthreads();
        float M = fmaxf(fmaxf(auxm[0][cc], auxm[1][cc]), fmaxf(auxm[2][cc], auxm[3][cc]));
        float s = 0.f;
        for (int i = q * 32; i < q * 32 + 32; i++) s += __expf(S[i * PS + cc] - M);
        auxs[q][cc] = s;
        __syncthreads();
        if (tid < 128)
            gc[tid] = __expf(-M) / (auxs[0][tid] + auxs[1][tid] + auxs[2][tid] + auxs[3][tid]);
    }
    __syncthreads();

#pragma unroll 1
    for (int t = 0; t < 8; t++) {
        int r = wid * 8 + t;
        float* row = S + r * PS;
        float v0 = row[lane], v1 = row[lane + 32], v2 = row[lane + 64], v3 = row[lane + 96];
        float m = fmaxf(fmaxf(v0, v1), fmaxf(v2, v3));
#pragma unroll
        for (int o = 16; o > 0; o >>= 1) m = fmaxf(m, __shfl_xor_sync(0xffffffffu, m, o));
        float e0 = __expf(v0 - m), e1 = __expf(v1 - m), e2 = __expf(v2 - m), e3 = __expf(v3 - m);
        float s = e0 + e1 + e2 + e3;
#pragma unroll
        for (int o = 16; o > 0; o >>= 1) s += __shfl_xor_sync(0xffffffffu, s, o);
        float inv = 1.0f / s;
        row[lane] = e0 * inv; row[lane + 32] = e1 * inv; row[lane + 64] = e2 * inv; row[lane + 96] = e3 * inv;
        if (lane == 0) rf[r] = s * __expf(m);
    }
    __syncthreads();

    for (int idx = tid; idx < 32 * 128; idx += 512) {
        int c = idx >> 7, j = idx & 127;
        T0[c * PT + j] = to_tf32(vdp[(size_t)c * HW + j]);
        T1[c * PT + j] = to_tf32(vup[(size_t)c * HW + j]);
    }
    __syncthreads();

    int ch = (wid & 1) * 16;
    float accD[2][4];
#pragma unroll
    for (int ct = 0; ct < 2; ct++)
#pragma unroll
        for (int r = 0; r < 4; r++) accD[ct][r] = 0.f;
#pragma unroll 4
    for (int ks = 0; ks < 16; ks++) {
        int k0 = ks * 8;
        uint32_t a0 = ldu(&S[(ib + g) * PS + k0 + tg]);
        uint32_t a1 = ldu(&S[(ib + g + 8) * PS + k0 + tg]);
        uint32_t a2 = ldu(&S[(ib + g) * PS + k0 + tg + 4]);
        uint32_t a3 = ldu(&S[(ib + g + 8) * PS + k0 + tg + 4]);
#pragma unroll
        for (int ct = 0; ct < 2; ct++) {
            int cb = ch + ct * 8;
            uint32_t b0 = ldu(&T0[(cb + g) * PT + k0 + tg]);
            uint32_t b1 = ldu(&T0[(cb + g) * PT + k0 + tg + 4]);
            mma_tf32(accD[ct], a0, a1, a2, a3, b0, b1);
        }
    }
    __syncthreads();

    for (int idx = tid; idx < 128 * 128; idx += 512) {
        int i = idx >> 7, j = idx & 127;
        S[i * PS + j] *= rf[i] * gc[j];
    }
    __syncthreads();

    float accU[2][4];
#pragma unroll
    for (int ct = 0; ct < 2; ct++)
#pragma unroll
        for (int r = 0; r < 4; r++) accU[ct][r] = 0.f;
#pragma unroll 4
    for (int ks = 0; ks < 16; ks++) {
        int k0 = ks * 8;
        uint32_t a0 = ldu(&S[(k0 + tg) * PS + ib + g]);
        uint32_t a1 = ldu(&S[(k0 + tg) * PS + ib + g + 8]);
        uint32_t a2 = ldu(&S[(k0 + tg + 4) * PS + ib + g]);
        uint32_t a3 = ldu(&S[(k0 + tg + 4) * PS + ib + g + 8]);
#pragma unroll
        for (int ct = 0; ct < 2; ct++) {
            int cb = ch + ct * 8;
            uint32_t b0 = ldu(&T1[(cb + g) * PT + k0 + tg]);
            uint32_t b1 = ldu(&T1[(cb + g) * PT + k0 + tg + 4]);
            mma_tf32(accU[ct], a0, a1, a2, a3, b0, b1);
        }
    }
    __syncthreads();

#pragma unroll
    for (int ct = 0; ct < 2; ct++) {
        int cb = ch + ct * 8;
        T0[(cb + 2 * tg) * PT + ib + g]         = accD[ct][0];
        T0[(cb + 2 * tg + 1) * PT + ib + g]     = accD[ct][1];
        T0[(cb + 2 * tg) * PT + ib + g + 8]     = accD[ct][2];
        T0[(cb + 2 * tg + 1) * PT + ib + g + 8] = accD[ct][3];
        T1[(cb + 2 * tg) * PT + ib + g]         = accU[ct][0];
        T1[(cb + 2 * tg + 1) * PT + ib + g]     = accU[ct][1];
        T1[(cb + 2 * tg) * PT + ib + g + 8]     = accU[ct][2];
        T1[(cb + 2 * tg + 1) * PT + ib + g + 8] = accU[ct][3];
    }
    __syncthreads();

    const size_t xb = (size_t)b * NCH + (size_t)32 * HW + ro;
    for (int idx = tid; idx < 32 * 128; idx += 512) {
        int c = idx >> 7, j = idx & 127;
        size_t e = xb + (size_t)c * HW + j;
        out[e] = T0[c * PT + j] * sru[c] + sbu[c] + xu[e]
               + T1[c * PT + j] * srd[c] + sbd[c] + xd[e];
    }
}

// ---------------- channel attention ----------------
__global__ void k_cpart(const float* __restrict__ qu, const float* __restrict__ qd,
                        float* __restrict__ spart)
{
    __shared__ float qs[32 * 129], ks[32 * 129];
    int chunk = blockIdx.x, b = blockIdx.y, tid = threadIdx.x;
    const size_t bb = (size_t)b * C2 * HW;
    int c0 = (tid >> 5) * 4, d = tid & 31;
    float acc[4] = {0.f, 0.f, 0.f, 0.f};
    for (int sub = 0; sub < 4; sub++) {
        int n0 = chunk * 512 + sub * 128;
        for (int idx = tid; idx < 32 * 128; idx += 256) {
            int c = idx >> 7, t = idx & 127;
            qs[c * 129 + t] = qu[bb + (size_t)(64 + c) * HW + n0 + t];
            ks[c * 129 + t] = qd[bb + (size_t)(64 + c) * HW + n0 + t];
        }
        __syncthreads();
        for (int t = 0; t < 128; t++) {
            float kv = ks[d * 129 + t];
#pragma unroll
            for (int cc = 0; cc < 4; cc++) acc[cc] = fmaf(qs[(c0 + cc) * 129 + t], kv, acc[cc]);
        }
        __syncthreads();
    }
#pragma unroll
    for (int cc = 0; cc < 4; cc++)
        spart[(((size_t)b * 32 + chunk) * 32 + c0 + cc) * 32 + d] = acc[cc];
}

__global__ void k_csoft(const float* __restrict__ spart, const float* __restrict__ scc,
                        float* __restrict__ ac)
{
    int b = blockIdx.x, d = threadIdx.x, c = threadIdx.y;
    float s = 0.f;
    for (int ch = 0; ch < 32; ch++)
        s += spart[(((size_t)b * 32 + ch) * 32 + c) * 32 + d];
    s *= scc[0];
    float m = s;
#pragma unroll
    for (int o = 16; o > 0; o >>= 1) m = fmaxf(m, __shfl_xor_sync(0xffffffffu, m, o));
    float e = __expf(s - m);
    float sum = e;
#pragma unroll
    for (int o = 16; o > 0; o >>= 1) sum += __shfl_xor_sync(0xffffffffu, sum, o);
    ac[((size_t)b * 32 + c) * 32 + d] = e / sum;
}

__global__ void k_capply_epi(const float* __restrict__ qu, const float* __restrict__ qd,
                             const float* __restrict__ ac,
                             const float* __restrict__ xu, const float* __restrict__ xd,
                             const float* __restrict__ stats,
                             const float* __restrict__ m1wu, const float* __restrict__ m1bu,
                             const float* __restrict__ m2wu, const float* __restrict__ m2bu,
                             const float* __restrict__ m1wd, const float* __restrict__ m1bd,
                             const float* __restrict__ m2wd, const float* __restrict__ m2bd,
                             float* __restrict__ out)
{
    __shared__ float A[1024];
    __shared__ float sru[32], sbu[32], srd[32], sbd[32];
    int b = blockIdx.y, tid = threadIdx.x;
    int n = blockIdx.x * 256 + tid;
    for (int i = tid; i < 1024; i += 256) A[i] = ac[(size_t)b * 1024 + i];
    if (tid < 32) {
        int c = 64 + tid;
        float mu = stats[b * 2], su = stats[b * 2 + 1];
        float md = stats[2 * NB + b * 2], sd = stats[2 * NB + b * 2 + 1];
        sru[tid] = su * m1wu[c] + m1bu[c];
        sbu[tid] = mu * m2wu[c] + m2bu[c];
        srd[tid] = sd * m1wd[c] + m1bd[c];
        sbd[tid] = md * m2wd[c] + m2bd[c];
    }
    __syncthreads();
    const size_t bb = (size_t)b * C2 * HW;
    const size_t xb = (size_t)b * NCH;
    float vd[32], vu[32];
#pragma unroll
    for (int d = 0; d < 32; d++) {
        vd[d] = qd[bb + (size_t)(160 + d) * HW + n];
        vu[d] = qu[bb + (size_t)(160 + d) * HW + n];
    }
#pragma unroll
    for (int c = 0; c < 32; c++) {
        float ad = 0.f, au = 0.f;
#pragma unroll
        for (int d = 0; d < 32; d++) {
            float a = A[c * 32 + d];
            ad = fmaf(a, vd[d], ad);
            au = fmaf(a, vu[d], au);
        }
        size_t e = xb + (size_t)(64 + c) * HW + n;
        out[e] = ad * sru[c] + sbu[c] + xu[e] + au * srd[c] + sbd[c] + xd[e];
    }
}

// ---------------- launch ----------------
extern "C" void kernel_launch(void* const* d_in, const int* in_sizes, int n_in,
                              void* d_out, int out_size)
{
    const float* x_u  = (const float*)d_in[0];
    const float* x_d  = (const float*)d_in[1];
    const float* nw_u = (const float*)d_in[2];
    const float* nb_u = (const float*)d_in[3];
    const float* m1w_u = (const float*)d_in[4];
    const float* m1b_u = (const float*)d_in[5];
    const float* m2w_u = (const float*)d_in[6];
    const float* m2b_u = (const float*)d_in[7];
    const float* nw_d = (const float*)d_in[8];
    const float* nb_d = (const float*)d_in[9];
    const float* m1w_d = (const float*)d_in[10];
    const float* m1b_d = (const float*)d_in[11];
    const float* m2w_d = (const float*)d_in[12];
    const float* m2b_d = (const float*)d_in[13];
    const float* Wqkv_u = (const float*)d_in[14];
    const float* bqkv_u = (const float*)d_in[15];
    const float* Wqkv_d = (const float*)d_in[16];
    const float* bqkv_d = (const float*)d_in[17];
    const float* scale_h = (const float*)d_in[18];
    const float* scale_w = (const float*)d_in[19];
    const float* scale_c = (const float*)d_in[20];
    float* out = (float*)d_out;

    static bool s_init = false;
    static float *p_qu, *p_qd, *p_part, *p_stats, *p_sp, *p_ac, *p_tin, *p_tout;
    if (!s_init) {
        cudaGetSymbolAddress((void**)&p_qu, g_qkv_u);
        cudaGetSymbolAddress((void**)&p_qd, g_qkv_d);
        cudaGetSymbolAddress((void**)&p_part, g_part);
        cudaGetSymbolAddress((void**)&p_stats, g_stats);
        cudaGetSymbolAddress((void**)&p_sp, g_spart);
        cudaGetSymbolAddress((void**)&p_ac, g_ac);
        cudaGetSymbolAddress((void**)&p_tin, g_tin);
        cudaGetSymbolAddress((void**)&p_tout, g_tout);
        cudaFuncSetAttribute(k_attn_h_tc, cudaFuncAttributeMaxDynamicSharedMemorySize, ASMEM * 4);
        cudaFuncSetAttribute(k_attn_w_tc, cudaFuncAttributeMaxDynamicSharedMemorySize, ASMEM * 4);
        s_init = true;
    }

    k_reduce1<<<dim3(256, NB, 2), 256>>>(x_u, x_d, p_part);
    k_reduce2<<<dim3(NB, 2), 256>>>(p_part, p_stats);

    k_pconv_tc<<<dim3(128, 3, NB), 256>>>(x_u, Wqkv_u, bqkv_u, nw_u, nb_u, p_stats,          p_qu);
    k_pconv_tc<<<dim3(128, 3, NB), 256>>>(x_d, Wqkv_d, bqkv_d, nw_d, nb_d, p_stats + 2 * NB, p_qd);

    k_tin<<<dim3(16, 32, NB * 4), dim3(32, 8)>>>(p_qu, p_qd, p_tin);

    size_t smemA = (size_t)ASMEM * 4;
    k_attn_h_tc<<<dim3(NWD, NB), 512, smemA>>>(p_tin, scale_h, p_tout);
    k_tout_epi<<<dim3(16, 32, NB), dim3(32, 8)>>>(p_tout, x_u, x_d, p_stats,
                                                  m1w_u, m1b_u, m2w_u, m2b_u,
                                                  m1w_d, m1b_d, m2w_d, m2b_d, out);

    k_attn_w_tc<<<dim3(NH, NB), 512, smemA>>>(p_qu, p_qd, scale_w, x_u, x_d, p_stats,
                                              m1w_u, m1b_u, m2w_u, m2b_u,
                                              m1w_d, m1b_d, m2w_d, m2b_d, out);

    k_cpart<<<dim3(32, NB), 256>>>(p_qu, p_qd, p_sp);
    k_csoft<<<NB, dim3(32, 32)>>>(p_sp, scale_c, p_ac);
    k_capply_epi<<<dim3(HW / 256, NB), 256>>>(p_qu, p_qd, p_ac, x_u, x_d, p_stats,
                                              m1w_u, m1b_u, m2w_u, m2b_u,
                                              m1w_d, m1b_d, m2w_d, m2b_d, out);
}

// round 8
// speedup vs baseline: 2.1138x; 1.0031x over previous
#include <cuda_runtime.h>
#include <math.h>
#include <stdint.h>

// ---------------- problem constants ----------------
static constexpr int NB   = 8;
static constexpr int NC   = 96;
static constexpr int NH   = 128;
static constexpr int NWD  = 128;
static constexpr int HW   = NH * NWD;   // 16384
static constexpr int NCH  = NC * HW;
static constexpr int C2   = 2 * NC;     // 192

// ---------------- scratch ----------------
__device__ float g_qkv_u[(size_t)NB * C2 * HW];
__device__ float g_qkv_d[(size_t)NB * C2 * HW];
__device__ float g_part [2 * NB * 256 * 2];
__device__ float g_stats[2 * NB * 2];
__device__ float g_spart[(size_t)NB * 32 * 32 * 32];
__device__ float g_ac   [NB * 32 * 32];
__device__ float g_tin  [(size_t)4 * NB * 32 * HW];  // h-attn inputs [t][b][c][w][h]
__device__ float g_tout [(size_t)2 * NB * 32 * HW];  // h-attn outputs [t][b][c][w][h]

// ---------------- K1/K2: mean/var ----------------
__global__ void k_reduce1(const float* __restrict__ xu, const float* __restrict__ xd,
                          float* __restrict__ part)
{
    int chunk = blockIdx.x, b = blockIdx.y, z = blockIdx.z;
    const float4* x = (const float4*)((z == 0 ? xu : xd) + (size_t)b * NCH + (size_t)chunk * 6144);
    float s = 0.f, ss = 0.f;
    for (int i = threadIdx.x; i < 1536; i += 256) {
        float4 v = x[i];
        s += v.x + v.y + v.z + v.w;
        ss += v.x * v.x + v.y * v.y + v.z * v.z + v.w * v.w;
    }
    __shared__ float sh[256], sh2[256];
    sh[threadIdx.x] = s; sh2[threadIdx.x] = ss;
    __syncthreads();
    for (int o = 128; o > 0; o >>= 1) {
        if (threadIdx.x < o) { sh[threadIdx.x] += sh[threadIdx.x + o]; sh2[threadIdx.x] += sh2[threadIdx.x + o]; }
        __syncthreads();
    }
    if (threadIdx.x == 0) {
        int o = ((z * NB + b) * 256 + chunk) * 2;
        part[o] = sh[0]; part[o + 1] = sh2[0];
    }
}

__global__ void k_reduce2(const float* __restrict__ part, float* __restrict__ stats)
{
    int b = blockIdx.x, z = blockIdx.y, tid = threadIdx.x;
    __shared__ double sh[256], sh2[256];
    int o = ((z * NB + b) * 256 + tid) * 2;
    sh[tid] = (double)part[o]; sh2[tid] = (double)part[o + 1];
    __syncthreads();
    for (int s = 128; s > 0; s >>= 1) {
        if (tid < s) { sh[tid] += sh[tid + s]; sh2[tid] += sh2[tid + s]; }
        __syncthreads();
    }
    if (tid == 0) {
        double mean = sh[0] / (double)NCH;
        double var  = sh2[0] / (double)NCH - mean * mean;
        stats[(z * NB + b) * 2 + 0] = (float)mean;
        stats[(z * NB + b) * 2 + 1] = sqrtf((float)var + 1e-5f);
    }
}

// ---------------- tf32 helpers ----------------
__device__ __forceinline__ float to_tf32(float v) {
    uint32_t u;
    asm("cvt.rna.tf32.f32 %0, %1;" : "=r"(u) : "f"(v));
    return __uint_as_float(u);
}
__device__ __forceinline__ uint32_t ldu(const float* p) { return __float_as_uint(*p); }
__device__ __forceinline__ uint32_t ntf(float v, float s, float o) {
    uint32_t u;
    float t = fmaf(v, s, o);
    asm("cvt.rna.tf32.f32 %0, %1;" : "=r"(u) : "f"(t));
    return u;
}

__device__ __forceinline__ void mma_tf32(float* c,
                                         uint32_t a0, uint32_t a1, uint32_t a2, uint32_t a3,
                                         uint32_t b0, uint32_t b1)
{
    asm volatile("mma.sync.aligned.m16n8k8.row.col.f32.tf32.tf32.f32 "
                 "{%0,%1,%2,%3}, {%4,%5,%6,%7}, {%8,%9}, {%0,%1,%2,%3};"
                 : "+f"(c[0]), "+f"(c[1]), "+f"(c[2]), "+f"(c[3])
                 : "r"(a0), "r"(a1), "r"(a2), "r"(a3), "r"(b0), "r"(b1));
}

// ---------------- K3: fused normalize + 1x1 conv GEMM (tf32, no B staging) ----------------
static constexpr int PIT = 100;

__global__ __launch_bounds__(256)
void k_pconv_tc(const float* __restrict__ x, const float* __restrict__ Wm,
                const float* __restrict__ bias, const float* __restrict__ nw,
                const float* __restrict__ nb, const float* __restrict__ stats,
                float* __restrict__ out)
{
    __shared__ float sA[64 * PIT];
    __shared__ float sSc[96], sOf[96];
    int b = blockIdx.z, mBase = blockIdx.y * 64, nBase = blockIdx.x * 128;
    int tid = threadIdx.x;
    float mean = stats[b * 2], inv = 1.0f / stats[b * 2 + 1];

    for (int idx = tid; idx < 64 * 96; idx += 256) {
        int m = idx / 96, k = idx - m * 96;
        sA[m * PIT + k] = to_tf32(Wm[(mBase + m) * 96 + k]);
    }
    if (tid < 96) {
        float s = inv * nw[tid];
        sSc[tid] = s;
        sOf[tid] = fmaf(-mean, s, nb[tid]);
    }
    __syncthreads();

    int warp = tid >> 5, lane = tid & 31;
    int warpM = warp & 1, warpN = warp >> 1;
    int g = lane >> 2, tg = lane & 3;

    float acc[2][4][4];
#pragma unroll
    for (int mt = 0; mt < 2; mt++)
#pragma unroll
        for (int nt = 0; nt < 4; nt++)
#pragma unroll
            for (int r = 0; r < 4; r++) acc[mt][nt][r] = 0.f;

    const float* pa = sA + (warpM * 32 + g) * PIT + tg;
    const float* px = x + (size_t)b * NC * HW + nBase + warpN * 32 + g;

#pragma unroll
    for (int ks = 0; ks < 12; ks++) {
        int k0 = ks * 8;
        // A fragments from shared (conflict-free: pitch%32==4)
        uint32_t a[2][4];
#pragma unroll
        for (int mt = 0; mt < 2; mt++) {
            const float* p = pa + mt * 16 * PIT + k0;
            a[mt][0] = ldu(p); a[mt][1] = ldu(p + 8 * PIT);
            a[mt][2] = ldu(p + 4); a[mt][3] = ldu(p + 8 * PIT + 4);
        }
        // B fragments straight from gmem with fused normalization
        float s0 = sSc[k0 + tg], o0 = sOf[k0 + tg];
        float s1 = sSc[k0 + tg + 4], o1 = sOf[k0 + tg + 4];
        const float* q0 = px + (size_t)(k0 + tg) * HW;
        const float* q1 = px + (size_t)(k0 + tg + 4) * HW;
        uint32_t bf[4][2];
#pragma unroll
        for (int nt = 0; nt < 4; nt++) {
            bf[nt][0] = ntf(q0[nt * 8], s0, o0);
            bf[nt][1] = ntf(q1[nt * 8], s1, o1);
        }
#pragma unroll
        for (int mt = 0; mt < 2; mt++)
#pragma unroll
            for (int nt = 0; nt < 4; nt++)
                mma_tf32(acc[mt][nt], a[mt][0], a[mt][1], a[mt][2], a[mt][3], bf[nt][0], bf[nt][1]);
    }

#pragma unroll
    for (int mt = 0; mt < 2; mt++) {
        int o0 = mBase + warpM * 32 + mt * 16 + g;
        float bs0 = bias[o0], bs1 = bias[o0 + 8];
        size_t base0 = ((size_t)b * C2 + o0) * HW + nBase + warpN * 32;
        size_t base1 = base0 + (size_t)8 * HW;
#pragma unroll
        for (int nt = 0; nt < 4; nt++) {
            int nc0 = nt * 8 + tg * 2;
            *(float2*)&out[base0 + nc0] = make_float2(acc[mt][nt][0] + bs0, acc[mt][nt][1] + bs0);
            *(float2*)&out[base1 + nc0] = make_float2(acc[mt][nt][2] + bs1, acc[mt][nt][3] + bs1);
        }
    }
}

// ---------------- transpose in (32x32 tiles) ----------------
__global__ void k_tin(const float* __restrict__ qu, const float* __restrict__ qd,
                      float* __restrict__ tin)
{
    __shared__ float sh[32][33];
    int tile = blockIdx.x;
    int wb = (tile & 3) * 32, hb = (tile >> 2) * 32;
    int c = blockIdx.y;
    int z = blockIdx.z, t = z & 3, b = z >> 2;
    int tx = threadIdx.x, ty = threadIdx.y;
    const float* base = (t == 0 || t == 3) ? qu : qd;
    int coff = (t >= 2) ? 96 + c : c;
    const float* src = base + ((size_t)b * C2 + coff) * HW;
#pragma unroll
    for (int r = 0; r < 4; r++)
        sh[ty + 8 * r][tx] = src[(hb + ty + 8 * r) * 128 + wb + tx];
    __syncthreads();
    float* dst = tin + ((size_t)(t * NB + b) * 32 + c) * HW;
#pragma unroll
    for (int r = 0; r < 4; r++)
        dst[(wb + ty + 8 * r) * 128 + hb + tx] = sh[tx][ty + 8 * r];
}

// ---------------- transpose out + fused epilogue (ch 0-31) ----------------
__global__ void k_tout_epi(const float* __restrict__ tout,
                           const float* __restrict__ xu, const float* __restrict__ xd,
                           const float* __restrict__ stats,
                           const float* __restrict__ m1wu, const float* __restrict__ m1bu,
                           const float* __restrict__ m2wu, const float* __restrict__ m2bu,
                           const float* __restrict__ m1wd, const float* __restrict__ m1bd,
                           const float* __restrict__ m2wd, const float* __restrict__ m2bd,
                           float* __restrict__ out)
{
    __shared__ float sh0[32][33], sh1[32][33];
    int tile = blockIdx.x;
    int hb = (tile & 3) * 32, wb = (tile >> 2) * 32;
    int c = blockIdx.y, b = blockIdx.z;
    int tx = threadIdx.x, ty = threadIdx.y;
    const size_t GRPO = (size_t)NB * 32 * HW;
    const float* src0 = tout + ((size_t)b * 32 + c) * HW;
    const float* src1 = tout + GRPO + ((size_t)b * 32 + c) * HW;
#pragma unroll
    for (int r = 0; r < 4; r++) {
        sh0[ty + 8 * r][tx] = src0[(wb + ty + 8 * r) * 128 + hb + tx];
        sh1[ty + 8 * r][tx] = src1[(wb + ty + 8 * r) * 128 + hb + tx];
    }
    __syncthreads();
    float mu = stats[b * 2], su = stats[b * 2 + 1];
    float md = stats[2 * NB + b * 2], sd = stats[2 * NB + b * 2 + 1];
    float ru = su * m1wu[c] + m1bu[c], bu = mu * m2wu[c] + m2bu[c];
    float rd = sd * m1wd[c] + m1bd[c], bd = md * m2wd[c] + m2bd[c];
    size_t cb = ((size_t)b * NC + c) * HW;
#pragma unroll
    for (int r = 0; r < 4; r++) {
        size_t e = cb + (size_t)(hb + ty + 8 * r) * 128 + wb + tx;
        out[e] = sh0[tx][ty + 8 * r] * ru + bu + xu[e] + sh1[tx][ty + 8 * r] * rd + bd + xd[e];
    }
}

// ---------------- tensor-core attention (512 threads) ----------------
static constexpr int PS = 132;
static constexpr int PT = 132;
static constexpr int ASMEM = (128 * PS + 2 * 32 * PT);

// height-axis attention on transposed data. CTA = (w, b).
__global__ __launch_bounds__(512, 2)
void k_attn_h_tc(const float* __restrict__ tin, const float* __restrict__ sch,
                 float* __restrict__ tout)
{
    extern __shared__ float sm[];
    float* S  = sm;
    float* T0 = sm + 128 * PS;
    float* T1 = T0 + 32 * PT;
    int w = blockIdx.x, b = blockIdx.y, tid = threadIdx.x;
    int wid = tid >> 5, lane = tid & 31, g = lane >> 2, tg = lane & 3;
    const size_t GRP = (size_t)NB * 32 * HW;
    const float* qp  = tin + (size_t)b * 32 * HW + (size_t)w * 128;
    const float* kp  = qp + GRP;
    const float* vdp = qp + 2 * GRP;
    const float* vup = qp + 3 * GRP;

    for (int idx = tid; idx < 32 * 128; idx += 512) {
        int c = idx >> 7, i = idx & 127;
        T0[c * PT + i] = to_tf32(qp[(size_t)c * HW + i]);
        T1[c * PT + i] = to_tf32(kp[(size_t)c * HW + i]);
    }
    __syncthreads();
    float sc = sch[0];

    int ib = (wid >> 1) * 16;
    int jh = (wid & 1) * 64;
    {
        float acc[8][4];
#pragma unroll
        for (int jt = 0; jt < 8; jt++)
#pragma unroll
            for (int r = 0; r < 4; r++) acc[jt][r] = 0.f;
#pragma unroll
        for (int ks = 0; ks < 4; ks++) {
            int k0 = ks * 8;
            uint32_t a0 = ldu(&T0[(k0 + tg) * PT + ib + g]);
            uint32_t a1 = ldu(&T0[(k0 + tg) * PT + ib + g + 8]);
            uint32_t a2 = ldu(&T0[(k0 + tg + 4) * PT + ib + g]);
            uint32_t a3 = ldu(&T0[(k0 + tg + 4) * PT + ib + g + 8]);
#pragma unroll
            for (int jt = 0; jt < 8; jt++) {
                int jb = jh + jt * 8;
                uint32_t b0 = ldu(&T1[(k0 + tg) * PT + jb + g]);
                uint32_t b1 = ldu(&T1[(k0 + tg + 4) * PT + jb + g]);
                mma_tf32(acc[jt], a0, a1, a2, a3, b0, b1);
            }
        }
#pragma unroll
        for (int jt = 0; jt < 8; jt++) {
            int jb = jh + jt * 8;
            S[(ib + g) * PS + jb + 2 * tg]         = acc[jt][0] * sc;
            S[(ib + g) * PS + jb + 2 * tg + 1]     = acc[jt][1] * sc;
            S[(ib + g + 8) * PS + jb + 2 * tg]     = acc[jt][2] * sc;
            S[(ib + g + 8) * PS + jb + 2 * tg + 1] = acc[jt][3] * sc;
        }
    }
    __syncthreads();

#pragma unroll 1
    for (int t = 0; t < 8; t++) {
        int r = wid * 8 + t;
        float* row = S + r * PS;
        float v0 = row[lane], v1 = row[lane + 32], v2 = row[lane + 64], v3 = row[lane + 96];
        float m = fmaxf(fmaxf(v0, v1), fmaxf(v2, v3));
#pragma unroll
        for (int o = 16; o > 0; o >>= 1) m = fmaxf(m, __shfl_xor_sync(0xffffffffu, m, o));
        float e0 = __expf(v0 - m), e1 = __expf(v1 - m), e2 = __expf(v2 - m), e3 = __expf(v3 - m);
        float s = e0 + e1 + e2 + e3;
#pragma unroll
        for (int o = 16; o > 0; o >>= 1) s += __shfl_xor_sync(0xffffffffu, s, o);
        float inv = 1.0f / s;
        row[lane] = e0 * inv; row[lane + 32] = e1 * inv; row[lane + 64] = e2 * inv; row[lane + 96] = e3 * inv;
    }
    __syncthreads();

    for (int idx = tid; idx < 32 * 128; idx += 512) {
        int c = idx >> 7, i = idx & 127;
        T0[c * PT + i] = to_tf32(vdp[(size_t)c * HW + i]);
        T1[c * PT + i] = to_tf32(vup[(size_t)c * HW + i]);
    }
    __syncthreads();

    int ch = (wid & 1) * 16;
    float accD[2][4], accU[2][4];
#pragma unroll
    for (int ct = 0; ct < 2; ct++)
#pragma unroll
        for (int r = 0; r < 4; r++) { accD[ct][r] = 0.f; accU[ct][r] = 0.f; }

#pragma unroll 4
    for (int ks = 0; ks < 16; ks++) {
        int k0 = ks * 8;
        uint32_t a0 = ldu(&S[(ib + g) * PS + k0 + tg]);
        uint32_t a1 = ldu(&S[(ib + g + 8) * PS + k0 + tg]);
        uint32_t a2 = ldu(&S[(ib + g) * PS + k0 + tg + 4]);
        uint32_t a3 = ldu(&S[(ib + g + 8) * PS + k0 + tg + 4]);
#pragma unroll
        for (int ct = 0; ct < 2; ct++) {
            int cb = ch + ct * 8;
            uint32_t b0 = ldu(&T0[(cb + g) * PT + k0 + tg]);
            uint32_t b1 = ldu(&T0[(cb + g) * PT + k0 + tg + 4]);
            mma_tf32(accD[ct], a0, a1, a2, a3, b0, b1);
        }
    }
#pragma unroll 4
    for (int ks = 0; ks < 16; ks++) {
        int k0 = ks * 8;
        uint32_t a0 = ldu(&S[(k0 + tg) * PS + ib + g]);
        uint32_t a1 = ldu(&S[(k0 + tg) * PS + ib + g + 8]);
        uint32_t a2 = ldu(&S[(k0 + tg + 4) * PS + ib + g]);
        uint32_t a3 = ldu(&S[(k0 + tg + 4) * PS + ib + g + 8]);
#pragma unroll
        for (int ct = 0; ct < 2; ct++) {
            int cb = ch + ct * 8;
            uint32_t b0 = ldu(&T1[(cb + g) * PT + k0 + tg]);
            uint32_t b1 = ldu(&T1[(cb + g) * PT + k0 + tg + 4]);
            mma_tf32(accU[ct], a0, a1, a2, a3, b0, b1);
        }
    }
    __syncthreads();

#pragma unroll
    for (int ct = 0; ct < 2; ct++) {
        int cb = ch + ct * 8;
        T0[(cb + 2 * tg) * PT + ib + g]         = accD[ct][0];
        T0[(cb + 2 * tg + 1) * PT + ib + g]     = accD[ct][1];
        T0[(cb + 2 * tg) * PT + ib + g + 8]     = accD[ct][2];
        T0[(cb + 2 * tg + 1) * PT + ib + g + 8] = accD[ct][3];
        T1[(cb + 2 * tg) * PT + ib + g]         = accU[ct][0];
        T1[(cb + 2 * tg + 1) * PT + ib + g]     = accU[ct][1];
        T1[(cb + 2 * tg) * PT + ib + g + 8]     = accU[ct][2];
        T1[(cb + 2 * tg + 1) * PT + ib + g + 8] = accU[ct][3];
    }
    __syncthreads();

    const size_t GRPO = (size_t)NB * 32 * HW;
    float* du = tout + (size_t)b * 32 * HW + (size_t)w * 128;
    float* ud = tout + GRPO + (size_t)b * 32 * HW + (size_t)w * 128;
    for (int idx = tid; idx < 32 * 128; idx += 512) {
        int c = idx >> 7, i = idx & 127;
        du[(size_t)c * HW + i] = T0[c * PT + i];
        ud[(size_t)c * HW + i] = T1[c * PT + i];
    }
}

// width-axis attention + fused epilogue (ch 32-63). CTA = (h, b).
__global__ __launch_bounds__(512, 2)
void k_attn_w_tc(const float* __restrict__ qu, const float* __restrict__ qd,
                 const float* __restrict__ scw,
                 const float* __restrict__ xu, const float* __restrict__ xd,
                 const float* __restrict__ stats,
                 const float* __restrict__ m1wu, const float* __restrict__ m1bu,
                 const float* __restrict__ m2wu, const float* __restrict__ m2bu,
                 const float* __restrict__ m1wd, const float* __restrict__ m1bd,
                 const float* __restrict__ m2wd, const float* __restrict__ m2bd,
                 float* __restrict__ out)
{
    extern __shared__ float sm[];
    float* S  = sm;
    float* T0 = sm + 128 * PS;
    float* T1 = T0 + 32 * PT;
    __shared__ float auxm[4][128], auxs[4][128];
    __shared__ float rf[128], gc[128];
    __shared__ float sru[32], sbu[32], srd[32], sbd[32];
    int h = blockIdx.x, b = blockIdx.y, tid = threadIdx.x;
    int wid = tid >> 5, lane = tid & 31, g = lane >> 2, tg = lane & 3;
    const size_t bb = (size_t)b * C2 * HW;
    const size_t ro = (size_t)h * 128;
    const float* qp  = qu + bb + (size_t)32 * HW + ro;
    const float* kp  = qd + bb + (size_t)32 * HW + ro;
    const float* vdp = qd + bb + (size_t)128 * HW + ro;
    const float* vup = qu + bb + (size_t)128 * HW + ro;

    if (tid < 32) {
        int c = 32 + tid;
        float mu = stats[b * 2], su = stats[b * 2 + 1];
        float md = stats[2 * NB + b * 2], sd = stats[2 * NB + b * 2 + 1];
        sru[tid] = su * m1wu[c] + m1bu[c];
        sbu[tid] = mu * m2wu[c] + m2bu[c];
        srd[tid] = sd * m1wd[c] + m1bd[c];
        sbd[tid] = md * m2wd[c] + m2bd[c];
    }

    for (int idx = tid; idx < 32 * 128; idx += 512) {
        int c = idx >> 7, j = idx & 127;
        T0[c * PT + j] = to_tf32(qp[(size_t)c * HW + j]);
        T1[c * PT + j] = to_tf32(kp[(size_t)c * HW + j]);
    }
    __syncthreads();
    float sc = scw[0];

    int ib = (wid >> 1) * 16;
    int jh = (wid & 1) * 64;
    {
        float acc[8][4];
#pragma unroll
        for (int jt = 0; jt < 8; jt++)
#pragma unroll
            for (int r = 0; r < 4; r++) acc[jt][r] = 0.f;
#pragma unroll
        for (int ks = 0; ks < 4; ks++) {
            int k0 = ks * 8;
            uint32_t a0 = ldu(&T0[(k0 + tg) * PT + ib + g]);
            uint32_t a1 = ldu(&T0[(k0 + tg) * PT + ib + g + 8]);
            uint32_t a2 = ldu(&T0[(k0 + tg + 4) * PT + ib + g]);
            uint32_t a3 = ldu(&T0[(k0 + tg + 4) * PT + ib + g + 8]);
#pragma unroll
            for (int jt = 0; jt < 8; jt++) {
                int jb = jh + jt * 8;
                uint32_t b0 = ldu(&T1[(k0 + tg) * PT + jb + g]);
                uint32_t b1 = ldu(&T1[(k0 + tg + 4) * PT + jb + g]);
                mma_tf32(acc[jt], a0, a1, a2, a3, b0, b1);
            }
        }
#pragma unroll
        for (int jt = 0; jt < 8; jt++) {
            int jb = jh + jt * 8;
            S[(ib + g) * PS + jb + 2 * tg]         = acc[jt][0] * sc;
            S[(ib + g) * PS + jb + 2 * tg + 1]     = acc[jt][1] * sc;
            S[(ib + g + 8) * PS + jb + 2 * tg]     = acc[jt][2] * sc;
            S[(ib + g + 8) * PS + jb + 2 * tg + 1] = acc[jt][3] * sc;
        }
    }
    __syncthreads();

    {
        int cc = tid & 127, q = tid >> 7;
        float m = -1e30f;
        for (int i = q * 32; i < q * 32 + 32; i++) m = fmaxf(m, S[i * PS + cc]);
        auxm[q][cc] = m;
        __syncthreads();
        float M = fmaxf(fmaxf(auxm[0][cc], auxm[1][cc]), fmaxf(auxm[2][cc], auxm[3][cc]));
        float s = 0.f;
        for (int i = q * 32; i < q * 32 + 32; i++) s += __expf(S[i * PS + cc] - M);
        auxs[q][cc] = s;
        __syncthreads();
        if (tid < 128)
            gc[tid] = __expf(-M) / (auxs[0][tid] + auxs[1][tid] + auxs[2][tid] + auxs[3][tid]);
    }
    __syncthreads();

#pragma unroll 1
    for (int t = 0; t < 8; t++) {
        int r = wid * 8 + t;
        float* row = S + r * PS;
        float v0 = row[lane], v1 = row[lane + 32], v2 = row[lane + 64], v3 = row[lane + 96];
        float m = fmaxf(fmaxf(v0, v1), fmaxf(v2, v3));
#pragma unroll
        for (int o = 16; o > 0; o >>= 1) m = fmaxf(m, __shfl_xor_sync(0xffffffffu, m, o));
        float e0 = __expf(v0 - m), e1 = __expf(v1 - m), e2 = __expf(v2 - m), e3 = __expf(v3 - m);
        float s = e0 + e1 + e2 + e3;
#pragma unroll
        for (int o = 16; o > 0; o >>= 1) s += __shfl_xor_sync(0xffffffffu, s, o);
        float inv = 1.0f / s;
        row[lane] = e0 * inv; row[lane + 32] = e1 * inv; row[lane + 64] = e2 * inv; row[lane + 96] = e3 * inv;
        if (lane == 0) rf[r] = s * __expf(m);
    }
    __syncthreads();

    for (int idx = tid; idx < 32 * 128; idx += 512) {
        int c = idx >> 7, j = idx & 127;
        T0[c * PT + j] = to_tf32(vdp[(size_t)c * HW + j]);
        T1[c * PT + j] = to_tf32(vup[(size_t)c * HW + j]);
    }
    __syncthreads();

    int ch = (wid & 1) * 16;
    float accD[2][4];
#pragma unroll
    for (int ct = 0; ct < 2; ct++)
#pragma unroll
        for (int r = 0; r < 4; r++) accD[ct][r] = 0.f;
#pragma unroll 4
    for (int ks = 0; ks < 16; ks++) {
        int k0 = ks * 8;
        uint32_t a0 = ldu(&S[(ib + g) * PS + k0 + tg]);
        uint32_t a1 = ldu(&S[(ib + g + 8) * PS + k0 + tg]);
        uint32_t a2 = ldu(&S[(ib + g) * PS + k0 + tg + 4]);
        uint32_t a3 = ldu(&S[(ib + g + 8) * PS + k0 + tg + 4]);
#pragma unroll
        for (int ct = 0; ct < 2; ct++) {
            int cb = ch + ct * 8;
            uint32_t b0 = ldu(&T0[(cb + g) * PT + k0 + tg]);
            uint32_t b1 = ldu(&T0[(cb + g) * PT + k0 + tg + 4]);
            mma_tf32(accD[ct], a0, a1, a2, a3, b0, b1);
        }
    }
    __syncthreads();

    for (int idx = tid; idx < 128 * 128; idx += 512) {
        int i = idx >> 7, j = idx & 127;
        S[i * PS + j] *= rf[i] * gc[j];
    }
    __syncthreads();

    float accU[2][4];
#pragma unroll
    for (int ct = 0; ct < 2; ct++)
#pragma unroll
        for (int r = 0; r < 4; r++) accU[ct][r] = 0.f;
#pragma unroll 4
    for (int ks = 0; ks < 16; ks++) {
        int k0 = ks * 8;
        uint32_t a0 = ldu(&S[(k0 + tg) * PS + ib + g]);
        uint32_t a1 = ldu(&S[(k0 + tg) * PS + ib + g + 8]);
        uint32_t a2 = ldu(&S[(k0 + tg + 4) * PS + ib + g]);
        uint32_t a3 = ldu(&S[(k0 + tg + 4) * PS + ib + g + 8]);
#pragma unroll
        for (int ct = 0; ct < 2; ct++) {
            int cb = ch + ct * 8;
            uint32_t b0 = ldu(&T1[(cb + g) * PT + k0 + tg]);
            uint32_t b1 = ldu(&T1[(cb + g) * PT + k0 + tg + 4]);
            mma_tf32(accU[ct], a0, a1, a2, a3, b0, b1);
        }
    }
    __syncthreads();

#pragma unroll
    for (int ct = 0; ct < 2; ct++) {
        int cb = ch + ct * 8;
        T0[(cb + 2 * tg) * PT + ib + g]         = accD[ct][0];
        T0[(cb + 2 * tg + 1) * PT + ib + g]     = accD[ct][1];
        T0[(cb + 2 * tg) * PT + ib + g + 8]     = accD[ct][2];
        T0[(cb + 2 * tg + 1) * PT + ib + g + 8] = accD[ct][3];
        T1[(cb + 2 * tg) * PT + ib + g]         = accU[ct][0];
        T1[(cb + 2 * tg + 1) * PT + ib + g]     = accU[ct][1];
        T1[(cb + 2 * tg) * PT + ib + g + 8]     = accU[ct][2];
        T1[(cb + 2 * tg + 1) * PT + ib + g + 8] = accU[ct][3];
    }
    __syncthreads();

    const size_t xb = (size_t)b * NCH + (size_t)32 * HW + ro;
    for (int idx = tid; idx < 32 * 128; idx += 512) {
        int c = idx >> 7, j = idx & 127;
        size_t e = xb + (size_t)c * HW + j;
        out[e] = T0[c * PT + j] * sru[c] + sbu[c] + xu[e]
               + T1[c * PT + j] * srd[c] + sbd[c] + xd[e];
    }
}

// ---------------- channel attention ----------------
__global__ void k_cpart(const float* __restrict__ qu, const float* __restrict__ qd,
                        float* __restrict__ spart)
{
    __shared__ float qs[32 * 129], ks[32 * 129];
    int chunk = blockIdx.x, b = blockIdx.y, tid = threadIdx.x;
    const size_t bb = (size_t)b * C2 * HW;
    int c0 = (tid >> 5) * 4, d = tid & 31;
    float acc[4] = {0.f, 0.f, 0.f, 0.f};
    for (int sub = 0; sub < 4; sub++) {
        int n0 = chunk * 512 + sub * 128;
        for (int idx = tid; idx < 32 * 128; idx += 256) {
            int c = idx >> 7, t = idx & 127;
            qs[c * 129 + t] = qu[bb + (size_t)(64 + c) * HW + n0 + t];
            ks[c * 129 + t] = qd[bb + (size_t)(64 + c) * HW + n0 + t];
        }
        __syncthreads();
        for (int t = 0; t < 128; t++) {
            float kv = ks[d * 129 + t];
#pragma unroll
            for (int cc = 0; cc < 4; cc++) acc[cc] = fmaf(qs[(c0 + cc) * 129 + t], kv, acc[cc]);
        }
        __syncthreads();
    }
#pragma unroll
    for (int cc = 0; cc < 4; cc++)
        spart[(((size_t)b * 32 + chunk) * 32 + c0 + cc) * 32 + d] = acc[cc];
}

__global__ void k_csoft(const float* __restrict__ spart, const float* __restrict__ scc,
                        float* __restrict__ ac)
{
    int b = blockIdx.x, d = threadIdx.x, c = threadIdx.y;
    float s = 0.f;
    for (int ch = 0; ch < 32; ch++)
        s += spart[(((size_t)b * 32 + ch) * 32 + c) * 32 + d];
    s *= scc[0];
    float m = s;
#pragma unroll
    for (int o = 16; o > 0; o >>= 1) m = fmaxf(m, __shfl_xor_sync(0xffffffffu, m, o));
    float e = __expf(s - m);
    float sum = e;
#pragma unroll
    for (int o = 16; o > 0; o >>= 1) sum += __shfl_xor_sync(0xffffffffu, sum, o);
    ac[((size_t)b * 32 + c) * 32 + d] = e / sum;
}

__global__ void k_capply_epi(const float* __restrict__ qu, const float* __restrict__ qd,
                             const float* __restrict__ ac,
                             const float* __restrict__ xu, const float* __restrict__ xd,
                             const float* __restrict__ stats,
                             const float* __restrict__ m1wu, const float* __restrict__ m1bu,
                             const float* __restrict__ m2wu, const float* __restrict__ m2bu,
                             const float* __restrict__ m1wd, const float* __restrict__ m1bd,
                             const float* __restrict__ m2wd, const float* __restrict__ m2bd,
                             float* __restrict__ out)
{
    __shared__ float A[1024];
    __shared__ float sru[32], sbu[32], srd[32], sbd[32];
    int b = blockIdx.y, tid = threadIdx.x;
    int n = blockIdx.x * 256 + tid;
    for (int i = tid; i < 1024; i += 256) A[i] = ac[(size_t)b * 1024 + i];
    if (tid < 32) {
        int c = 64 + tid;
        float mu = stats[b * 2], su = stats[b * 2 + 1];
        float md = stats[2 * NB + b * 2], sd = stats[2 * NB + b * 2 + 1];
        sru[tid] = su * m1wu[c] + m1bu[c];
        sbu[tid] = mu * m2wu[c] + m2bu[c];
        srd[tid] = sd * m1wd[c] + m1bd[c];
        sbd[tid] = md * m2wd[c] + m2bd[c];
    }
    __syncthreads();
    const size_t bb = (size_t)b * C2 * HW;
    const size_t xb = (size_t)b * NCH;
    float vd[32], vu[32];
#pragma unroll
    for (int d = 0; d < 32; d++) {
        vd[d] = qd[bb + (size_t)(160 + d) * HW + n];
        vu[d] = qu[bb + (size_t)(160 + d) * HW + n];
    }
#pragma unroll
    for (int c = 0; c < 32; c++) {
        float ad = 0.f, au = 0.f;
#pragma unroll
        for (int d = 0; d < 32; d++) {
            float a = A[c * 32 + d];
            ad = fmaf(a, vd[d], ad);
            au = fmaf(a, vu[d], au);
        }
        size_t e = xb + (size_t)(64 + c) * HW + n;
        out[e] = ad * sru[c] + sbu[c] + xu[e] + au * srd[c] + sbd[c] + xd[e];
    }
}

// ---------------- launch ----------------
extern "C" void kernel_launch(void* const* d_in, const int* in_sizes, int n_in,
                              void* d_out, int out_size)
{
    const float* x_u  = (const float*)d_in[0];
    const float* x_d  = (const float*)d_in[1];
    const float* nw_u = (const float*)d_in[2];
    const float* nb_u = (const float*)d_in[3];
    const float* m1w_u = (const float*)d_in[4];
    const float* m1b_u = (const float*)d_in[5];
    const float* m2w_u = (const float*)d_in[6];
    const float* m2b_u = (const float*)d_in[7];
    const float* nw_d = (const float*)d_in[8];
    const float* nb_d = (const float*)d_in[9];
    const float* m1w_d = (const float*)d_in[10];
    const float* m1b_d = (const float*)d_in[11];
    const float* m2w_d = (const float*)d_in[12];
    const float* m2b_d = (const float*)d_in[13];
    const float* Wqkv_u = (const float*)d_in[14];
    const float* bqkv_u = (const float*)d_in[15];
    const float* Wqkv_d = (const float*)d_in[16];
    const float* bqkv_d = (const float*)d_in[17];
    const float* scale_h = (const float*)d_in[18];
    const float* scale_w = (const float*)d_in[19];
    const float* scale_c = (const float*)d_in[20];
    float* out = (float*)d_out;

    static bool s_init = false;
    static float *p_qu, *p_qd, *p_part, *p_stats, *p_sp, *p_ac, *p_tin, *p_tout;
    if (!s_init) {
        cudaGetSymbolAddress((void**)&p_qu, g_qkv_u);
        cudaGetSymbolAddress((void**)&p_qd, g_qkv_d);
        cudaGetSymbolAddress((void**)&p_part, g_part);
        cudaGetSymbolAddress((void**)&p_stats, g_stats);
        cudaGetSymbolAddress((void**)&p_sp, g_spart);
        cudaGetSymbolAddress((void**)&p_ac, g_ac);
        cudaGetSymbolAddress((void**)&p_tin, g_tin);
        cudaGetSymbolAddress((void**)&p_tout, g_tout);
        cudaFuncSetAttribute(k_attn_h_tc, cudaFuncAttributeMaxDynamicSharedMemorySize, ASMEM * 4);
        cudaFuncSetAttribute(k_attn_w_tc, cudaFuncAttributeMaxDynamicSharedMemorySize, ASMEM * 4);
        s_init = true;
    }

    k_reduce1<<<dim3(256, NB, 2), 256>>>(x_u, x_d, p_part);
    k_reduce2<<<dim3(NB, 2), 256>>>(p_part, p_stats);

    k_pconv_tc<<<dim3(128, 3, NB), 256>>>(x_u, Wqkv_u, bqkv_u, nw_u, nb_u, p_stats,          p_qu);
    k_pconv_tc<<<dim3(128, 3, NB), 256>>>(x_d, Wqkv_d, bqkv_d, nw_d, nb_d, p_stats + 2 * NB, p_qd);

    k_tin<<<dim3(16, 32, NB * 4), dim3(32, 8)>>>(p_qu, p_qd, p_tin);

    size_t smemA = (size_t)ASMEM * 4;
    k_attn_h_tc<<<dim3(NWD, NB), 512, smemA>>>(p_tin, scale_h, p_tout);
    k_tout_epi<<<dim3(16, 32, NB), dim3(32, 8)>>>(p_tout, x_u, x_d, p_stats,
                                                  m1w_u, m1b_u, m2w_u, m2b_u,
                                                  m1w_d, m1b_d, m2w_d, m2b_d, out);

    k_attn_w_tc<<<dim3(NH, NB), 512, smemA>>>(p_qu, p_qd, scale_w, x_u, x_d, p_stats,
                                              m1w_u, m1b_u, m2w_u, m2b_u,
                                              m1w_d, m1b_d, m2w_d, m2b_d, out);

    k_cpart<<<dim3(32, NB), 256>>>(p_qu, p_qd, p_sp);
    k_csoft<<<NB, dim3(32, 32)>>>(p_sp, scale_c, p_ac);
    k_capply_epi<<<dim3(HW / 256, NB), 256>>>(p_qu, p_qd, p_ac, x_u, x_d, p_stats,
                                              m1w_u, m1b_u, m2w_u, m2b_u,
                                              m1w_d, m1b_d, m2w_d, m2b_d, out);
}